// round 1
// baseline (speedup 1.0000x reference)
#include <cuda_runtime.h>
#include <math.h>

#define NN 100000
#define NE 1600000
#define NP 500000
#define NF 128

// ---------------- static device scratch (no allocations allowed) ----------------
__device__ float g_h[(size_t)NN * NF];        // current hidden state
__device__ float g_selfb[(size_t)NN * NF];    // h @ W_self + b
__device__ float g_support[(size_t)NN * NF];  // h @ W_neighbor
__device__ int   g_rowptr[NN + 1];
__device__ int   g_cursor[NN];                // reused as degree counter, then scatter cursor
__device__ int   g_pcol[NE];                  // permuted (CSR-ordered) col indices
__device__ float g_pw[NE];                    // permuted edge weights

// ---------------- CSR build ----------------
__global__ void k_zero_deg() {
    int i = blockIdx.x * blockDim.x + threadIdx.x;
    if (i < NN) g_cursor[i] = 0;
}

__global__ void k_count_deg(const int* __restrict__ row) {
    int e = blockIdx.x * blockDim.x + threadIdx.x;
    if (e < NE) atomicAdd(&g_cursor[row[e]], 1);
}

// Single-block scan over NN degrees -> rowptr (inclusive at i+1) and cursor (exclusive start)
__global__ void k_scan_deg() {
    __shared__ int sh[1024];
    __shared__ int s_carry;
    int t = threadIdx.x;
    if (t == 0) { s_carry = 0; g_rowptr[0] = 0; }
    __syncthreads();
    for (int base = 0; base < NN; base += 1024) {
        int idx = base + t;
        int v = (idx < NN) ? g_cursor[idx] : 0;
        sh[t] = v;
        __syncthreads();
        for (int off = 1; off < 1024; off <<= 1) {
            int y = (t >= off) ? sh[t - off] : 0;
            __syncthreads();
            sh[t] += y;
            __syncthreads();
        }
        int incl = sh[t] + s_carry;
        if (idx < NN) {
            g_rowptr[idx + 1] = incl;
            g_cursor[idx] = incl - v;  // exclusive prefix = scatter start
        }
        __syncthreads();
        if (t == 1023) s_carry = incl;
        __syncthreads();
    }
}

__global__ void k_scatter_edges(const int* __restrict__ row, const int* __restrict__ col,
                                const float* __restrict__ w) {
    int e = blockIdx.x * blockDim.x + threadIdx.x;
    if (e < NE) {
        int pos = atomicAdd(&g_cursor[row[e]], 1);
        g_pcol[pos] = col[e];
        g_pw[pos]   = w[e];
    }
}

// ---------------- SGEMM: C[M x 128] = A[M x 128] @ B[128 x 128] (+ bias) ----------------
// 128x128 block tile, BK=16, 256 threads, 8x8 register tile per thread.
__global__ __launch_bounds__(256) void k_gemm128(
    const float* __restrict__ A, const float* __restrict__ B,
    const float* __restrict__ bias, float* __restrict__ C, int M)
{
    __shared__ float As[16][128];
    __shared__ float Bs[16][128];
    int tid = threadIdx.x;
    int tx = tid & 15;     // output col group
    int ty = tid >> 4;     // output row group
    int rowBase = blockIdx.x * 128;

    float acc[8][8];
#pragma unroll
    for (int i = 0; i < 8; i++)
#pragma unroll
        for (int j = 0; j < 8; j++) acc[i][j] = 0.f;

    for (int kt = 0; kt < 128; kt += 16) {
        // A tile: 128 rows x 16 cols = 512 float4
#pragma unroll
        for (int j = 0; j < 2; j++) {
            int f4 = tid * 2 + j;          // 0..511
            int r  = f4 >> 2;              // 0..127
            int k4 = (f4 & 3) << 2;        // 0,4,8,12
            float4 v = make_float4(0.f, 0.f, 0.f, 0.f);
            int gr = rowBase + r;
            if (gr < M) v = *(const float4*)(A + (size_t)gr * 128 + kt + k4);
            As[k4 + 0][r] = v.x; As[k4 + 1][r] = v.y;
            As[k4 + 2][r] = v.z; As[k4 + 3][r] = v.w;
        }
        // B tile: 16 rows x 128 cols
#pragma unroll
        for (int j = 0; j < 2; j++) {
            int f4 = tid * 2 + j;
            int kr = f4 >> 5;              // 0..15
            int n4 = (f4 & 31) << 2;       // 0..124
            *(float4*)(&Bs[kr][n4]) = *(const float4*)(B + (size_t)(kt + kr) * 128 + n4);
        }
        __syncthreads();
#pragma unroll
        for (int kk = 0; kk < 16; kk++) {
            float ra[8], rb[8];
#pragma unroll
            for (int i = 0; i < 8; i++) ra[i] = As[kk][ty * 8 + i];
#pragma unroll
            for (int j = 0; j < 8; j++) rb[j] = Bs[kk][tx * 8 + j];
#pragma unroll
            for (int i = 0; i < 8; i++)
#pragma unroll
                for (int j = 0; j < 8; j++) acc[i][j] += ra[i] * rb[j];
        }
        __syncthreads();
    }
#pragma unroll
    for (int i = 0; i < 8; i++) {
        int r = rowBase + ty * 8 + i;
        if (r >= M) continue;
#pragma unroll
        for (int j = 0; j < 8; j += 4) {
            int c = tx * 8 + j;
            float4 v;
            float b0 = bias ? bias[c + 0] : 0.f;
            float b1 = bias ? bias[c + 1] : 0.f;
            float b2 = bias ? bias[c + 2] : 0.f;
            float b3 = bias ? bias[c + 3] : 0.f;
            v.x = acc[i][j + 0] + b0;
            v.y = acc[i][j + 1] + b1;
            v.z = acc[i][j + 2] + b2;
            v.w = acc[i][j + 3] + b3;
            *(float4*)(C + (size_t)r * 128 + c) = v;
        }
    }
}

// ---------------- neighbor aggregation: out[n] = maybe_relu(selfb[n] + sum_e w*support[col]) ----
__global__ __launch_bounds__(128) void k_aggregate(float* __restrict__ out, int relu) {
    int node = blockIdx.x;
    int f = threadIdx.x;  // 0..127
    float acc = g_selfb[(size_t)node * 128 + f];
    int s = g_rowptr[node];
    int e = g_rowptr[node + 1];
    int i = s;
#pragma unroll 4
    for (; i < e; i++) {
        int c   = g_pcol[i];
        float w = g_pw[i];
        acc += w * g_support[(size_t)c * 128 + f];
    }
    if (relu) acc = fmaxf(acc, 0.f);
    out[(size_t)node * 128 + f] = acc;
}

// ---------------- fused decoder: p = sigmoid(relu(concat(z[x],z[y]) @ W1 + b1) @ W2 + b2) ----
__global__ __launch_bounds__(256) void k_decoder(
    const float* __restrict__ z, const int* __restrict__ xidx, const int* __restrict__ yidx,
    const float* __restrict__ w1, const float* __restrict__ b1,
    const float* __restrict__ w2, const float* __restrict__ b2,
    float* __restrict__ p)
{
    __shared__ float As[16][128];
    __shared__ float Bs[16][128];
    __shared__ int   sxi[128], syi[128];
    __shared__ float sw2[128], sb1[128];
    __shared__ float red[128][17];

    int tid = threadIdx.x;
    int tx = tid & 15, ty = tid >> 4;
    int pairBase = blockIdx.x * 128;

    if (tid < 128) {
        int pp = pairBase + tid;
        sxi[tid] = (pp < NP) ? xidx[pp] : 0;
        syi[tid] = (pp < NP) ? yidx[pp] : 0;
        sw2[tid] = w2[tid];
        sb1[tid] = b1[tid];
    }
    __syncthreads();

    float acc[8][8];
#pragma unroll
    for (int i = 0; i < 8; i++)
#pragma unroll
        for (int j = 0; j < 8; j++) acc[i][j] = 0.f;

    for (int kt = 0; kt < 256; kt += 16) {
#pragma unroll
        for (int j = 0; j < 2; j++) {
            int f4 = tid * 2 + j;
            int r  = f4 >> 2;
            int k4 = (f4 & 3) << 2;
            int kg = kt + k4;
            int node, koff;
            if (kg < 128) { node = sxi[r]; koff = kg; }
            else          { node = syi[r]; koff = kg - 128; }
            float4 v = *(const float4*)(z + (size_t)node * 128 + koff);
            As[k4 + 0][r] = v.x; As[k4 + 1][r] = v.y;
            As[k4 + 2][r] = v.z; As[k4 + 3][r] = v.w;
        }
#pragma unroll
        for (int j = 0; j < 2; j++) {
            int f4 = tid * 2 + j;
            int kr = f4 >> 5;
            int n4 = (f4 & 31) << 2;
            *(float4*)(&Bs[kr][n4]) = *(const float4*)(w1 + (size_t)(kt + kr) * 128 + n4);
        }
        __syncthreads();
#pragma unroll
        for (int kk = 0; kk < 16; kk++) {
            float ra[8], rb[8];
#pragma unroll
            for (int i = 0; i < 8; i++) ra[i] = As[kk][ty * 8 + i];
#pragma unroll
            for (int j = 0; j < 8; j++) rb[j] = Bs[kk][tx * 8 + j];
#pragma unroll
            for (int i = 0; i < 8; i++)
#pragma unroll
                for (int j = 0; j < 8; j++) acc[i][j] += ra[i] * rb[j];
        }
        __syncthreads();
    }

    // fc2 + sigmoid epilogue (hdec never hits memory)
    float part[8];
#pragma unroll
    for (int i = 0; i < 8; i++) part[i] = 0.f;
#pragma unroll
    for (int i = 0; i < 8; i++)
#pragma unroll
        for (int j = 0; j < 8; j++) {
            int c = tx * 8 + j;
            float hv = fmaxf(acc[i][j] + sb1[c], 0.f);
            part[i] += hv * sw2[c];
        }
#pragma unroll
    for (int i = 0; i < 8; i++) red[ty * 8 + i][tx] = part[i];
    __syncthreads();
    if (tid < 128) {
        float s = 0.f;
#pragma unroll
        for (int c = 0; c < 16; c++) s += red[tid][c];
        s += b2[0];
        float pv = 1.f / (1.f + expf(-s));
        int pp = pairBase + tid;
        if (pp < NP) p[pp] = pv;
    }
}

// ---------------- launch ----------------
extern "C" void kernel_launch(void* const* d_in, const int* in_sizes, int n_in,
                              void* d_out, int out_size) {
    const float* x     = (const float*)d_in[0];
    const int*   erow  = (const int*)  d_in[1];
    const int*   ecol  = (const int*)  d_in[2];
    const float* ew    = (const float*)d_in[3];
    const int*   xidx  = (const int*)  d_in[4];
    const int*   yidx  = (const int*)  d_in[5];
    const float* ws[3] = { (const float*)d_in[6],  (const float*)d_in[9],  (const float*)d_in[12] };
    const float* wn[3] = { (const float*)d_in[7],  (const float*)d_in[10], (const float*)d_in[13] };
    const float* bb[3] = { (const float*)d_in[8],  (const float*)d_in[11], (const float*)d_in[14] };
    const float* dw1 = (const float*)d_in[15];
    const float* db1 = (const float*)d_in[16];
    const float* dw2 = (const float*)d_in[17];
    const float* db2 = (const float*)d_in[18];

    float* out = (float*)d_out;
    float* p_out = out;            // [NP]
    float* z_out = out + NP;       // [NN*128]

    void* ptr;
    cudaGetSymbolAddress(&ptr, g_h);       float* h_buf     = (float*)ptr;
    cudaGetSymbolAddress(&ptr, g_selfb);   float* selfb_buf = (float*)ptr;
    cudaGetSymbolAddress(&ptr, g_support); float* sup_buf   = (float*)ptr;

    // CSR build (each call; graph-capturable, deterministic up to fp-atomic-free structure)
    k_zero_deg<<<(NN + 255) / 256, 256>>>();
    k_count_deg<<<(NE + 255) / 256, 256>>>(erow);
    k_scan_deg<<<1, 1024>>>();
    k_scatter_edges<<<(NE + 255) / 256, 256>>>(erow, ecol, ew);

    const int gemmGrid = (NN + 127) / 128;

    // layer 1
    k_gemm128<<<gemmGrid, 256>>>(x, ws[0], bb[0], selfb_buf, NN);
    k_gemm128<<<gemmGrid, 256>>>(x, wn[0], nullptr, sup_buf, NN);
    k_aggregate<<<NN, 128>>>(h_buf, 1);
    // layer 2
    k_gemm128<<<gemmGrid, 256>>>(h_buf, ws[1], bb[1], selfb_buf, NN);
    k_gemm128<<<gemmGrid, 256>>>(h_buf, wn[1], nullptr, sup_buf, NN);
    k_aggregate<<<NN, 128>>>(h_buf, 1);
    // layer 3 -> z (no relu), written straight into d_out
    k_gemm128<<<gemmGrid, 256>>>(h_buf, ws[2], bb[2], selfb_buf, NN);
    k_gemm128<<<gemmGrid, 256>>>(h_buf, wn[2], nullptr, sup_buf, NN);
    k_aggregate<<<NN, 128>>>(z_out, 0);

    // decoder -> p
    k_decoder<<<(NP + 127) / 128, 256>>>(z_out, xidx, yidx, dw1, db1, dw2, db2, p_out);
}

// round 2
// speedup vs baseline: 1.0955x; 1.0955x over previous
#include <cuda_runtime.h>
#include <math.h>

#define NN 100000
#define NE 1600000
#define NP 500000
#define NF 128
#define SCAN_B 1024
#define NBLK ((NN + SCAN_B - 1) / SCAN_B)   // 98

// ---------------- static device scratch (no allocations allowed) ----------------
__device__ float g_h[(size_t)NN * NF];        // current hidden state
__device__ float g_selfb[(size_t)NN * NF];    // h @ W_self + b
__device__ float g_support[(size_t)NN * NF];  // h @ W_neighbor
__device__ int   g_rowptr[NN + 1];
__device__ int   g_cursor[NN];                // degree counter -> scatter cursor
__device__ int   g_partial[NBLK];
__device__ int   g_blockoff[NBLK];
__device__ int   g_pcol[NE];                  // CSR-ordered col indices
__device__ float g_pw[NE];                    // CSR-ordered edge weights

// ---------------- packed fp32x2 helpers (Blackwell double-rate fp32) ----------------
__device__ __forceinline__ unsigned long long fma_f32x2(unsigned long long a,
                                                        unsigned long long b,
                                                        unsigned long long c) {
    unsigned long long d;
    asm("fma.rn.f32x2 %0, %1, %2, %3;" : "=l"(d) : "l"(a), "l"(b), "l"(c));
    return d;
}
__device__ __forceinline__ unsigned long long pack2(float x) {
    unsigned long long d;
    asm("mov.b64 %0, {%1, %1};" : "=l"(d) : "f"(x));
    return d;
}
__device__ __forceinline__ float2 unpack2(unsigned long long u) {
    float lo, hi;
    asm("mov.b64 {%0, %1}, %2;" : "=f"(lo), "=f"(hi) : "l"(u));
    return make_float2(lo, hi);
}

// ---------------- CSR build ----------------
__global__ void k_zero_deg() {
    int i = blockIdx.x * blockDim.x + threadIdx.x;
    if (i < NN) g_cursor[i] = 0;
}

__global__ void k_count_deg(const int* __restrict__ row) {
    int e = blockIdx.x * blockDim.x + threadIdx.x;
    if (e < NE) atomicAdd(&g_cursor[row[e]], 1);
}

// phase 1: per-block sums of degrees
__global__ __launch_bounds__(SCAN_B) void k_scan_part() {
    __shared__ int sh[SCAN_B / 32];
    int t = threadIdx.x;
    int idx = blockIdx.x * SCAN_B + t;
    int v = (idx < NN) ? g_cursor[idx] : 0;
#pragma unroll
    for (int off = 16; off > 0; off >>= 1) v += __shfl_down_sync(0xffffffffu, v, off);
    if ((t & 31) == 0) sh[t >> 5] = v;
    __syncthreads();
    if (t < 32) {
        int s = (t < SCAN_B / 32) ? sh[t] : 0;
#pragma unroll
        for (int off = 16; off > 0; off >>= 1) s += __shfl_down_sync(0xffffffffu, s, off);
        if (t == 0) g_partial[blockIdx.x] = s;
    }
}

// phase 2: exclusive scan of NBLK partials (1 block)
__global__ __launch_bounds__(128) void k_scan_mid() {
    __shared__ int sh[128];
    int t = threadIdx.x;
    int v = (t < NBLK) ? g_partial[t] : 0;
    sh[t] = v;
    __syncthreads();
#pragma unroll
    for (int off = 1; off < 128; off <<= 1) {
        int y = (t >= off) ? sh[t - off] : 0;
        __syncthreads();
        sh[t] += y;
        __syncthreads();
    }
    if (t < NBLK) g_blockoff[t] = sh[t] - v;  // exclusive
}

// phase 3: block-local inclusive scan + block offset -> rowptr / cursor
__global__ __launch_bounds__(SCAN_B) void k_scan_final() {
    __shared__ int sh[SCAN_B];
    int t = threadIdx.x;
    int idx = blockIdx.x * SCAN_B + t;
    int v = (idx < NN) ? g_cursor[idx] : 0;
    sh[t] = v;
    __syncthreads();
#pragma unroll
    for (int off = 1; off < SCAN_B; off <<= 1) {
        int y = (t >= off) ? sh[t - off] : 0;
        __syncthreads();
        sh[t] += y;
        __syncthreads();
    }
    if (idx < NN) {
        int incl = sh[t] + g_blockoff[blockIdx.x];
        g_rowptr[idx + 1] = incl;
        g_cursor[idx] = incl - v;
    }
    if (idx == 0) g_rowptr[0] = 0;
}

__global__ void k_scatter_edges(const int* __restrict__ row, const int* __restrict__ col,
                                const float* __restrict__ w) {
    int e = blockIdx.x * blockDim.x + threadIdx.x;
    if (e < NE) {
        int pos = atomicAdd(&g_cursor[row[e]], 1);
        g_pcol[pos] = col[e];
        g_pw[pos]   = w[e];
    }
}

// ---------------- SGEMM: C[M x 128] = A[M x 128] @ B[128 x 128] (+ bias) ----------------
// 128x128 tile, BK=16, 256 threads, 8x8 per thread, packed f32x2 FFMA.
__global__ __launch_bounds__(256) void k_gemm128(
    const float* __restrict__ A, const float* __restrict__ B,
    const float* __restrict__ bias, float* __restrict__ C, int M)
{
    __shared__ float As[16][128];
    __shared__ float Bs[16][128];
    int tid = threadIdx.x;
    int tx = tid & 15;
    int ty = tid >> 4;
    int rowBase = blockIdx.x * 128;

    unsigned long long accp[8][4];
#pragma unroll
    for (int i = 0; i < 8; i++)
#pragma unroll
        for (int j = 0; j < 4; j++) accp[i][j] = 0ull;

    for (int kt = 0; kt < 128; kt += 16) {
#pragma unroll
        for (int j = 0; j < 2; j++) {
            int f4 = tid * 2 + j;
            int r  = f4 >> 2;
            int k4 = (f4 & 3) << 2;
            float4 v = make_float4(0.f, 0.f, 0.f, 0.f);
            int gr = rowBase + r;
            if (gr < M) v = *(const float4*)(A + (size_t)gr * 128 + kt + k4);
            As[k4 + 0][r] = v.x; As[k4 + 1][r] = v.y;
            As[k4 + 2][r] = v.z; As[k4 + 3][r] = v.w;
        }
#pragma unroll
        for (int j = 0; j < 2; j++) {
            int f4 = tid * 2 + j;
            int kr = f4 >> 5;
            int n4 = (f4 & 31) << 2;
            *(float4*)(&Bs[kr][n4]) = *(const float4*)(B + (size_t)(kt + kr) * 128 + n4);
        }
        __syncthreads();
#pragma unroll
        for (int kk = 0; kk < 16; kk++) {
            float ra[8];
            unsigned long long rb2[4];
#pragma unroll
            for (int i = 0; i < 8; i++) ra[i] = As[kk][ty * 8 + i];
            const unsigned long long* bp = (const unsigned long long*)&Bs[kk][tx * 8];
#pragma unroll
            for (int j = 0; j < 4; j++) rb2[j] = bp[j];
#pragma unroll
            for (int i = 0; i < 8; i++) {
                unsigned long long ra2 = pack2(ra[i]);
#pragma unroll
                for (int j = 0; j < 4; j++) accp[i][j] = fma_f32x2(ra2, rb2[j], accp[i][j]);
            }
        }
        __syncthreads();
    }
#pragma unroll
    for (int i = 0; i < 8; i++) {
        int r = rowBase + ty * 8 + i;
        if (r >= M) continue;
#pragma unroll
        for (int j = 0; j < 2; j++) {
            int c = tx * 8 + j * 4;
            float2 p0 = unpack2(accp[i][j * 2 + 0]);
            float2 p1 = unpack2(accp[i][j * 2 + 1]);
            float4 v;
            v.x = p0.x; v.y = p0.y; v.z = p1.x; v.w = p1.y;
            if (bias) { v.x += bias[c]; v.y += bias[c+1]; v.z += bias[c+2]; v.w += bias[c+3]; }
            *(float4*)(C + (size_t)r * 128 + c) = v;
        }
    }
}

// ---------------- neighbor aggregation ----------------
__global__ __launch_bounds__(128) void k_aggregate(float* __restrict__ out, int relu) {
    int node = blockIdx.x;
    int f = threadIdx.x;
    float acc0 = g_selfb[(size_t)node * 128 + f];
    float acc1 = 0.f;
    int s = g_rowptr[node];
    int e = g_rowptr[node + 1];
    int i = s;
    for (; i + 1 < e; i += 2) {
        int c0 = g_pcol[i], c1 = g_pcol[i + 1];
        float w0 = g_pw[i], w1 = g_pw[i + 1];
        acc0 += w0 * g_support[(size_t)c0 * 128 + f];
        acc1 += w1 * g_support[(size_t)c1 * 128 + f];
    }
    if (i < e) {
        acc0 += g_pw[i] * g_support[(size_t)g_pcol[i] * 128 + f];
    }
    float acc = acc0 + acc1;
    if (relu) acc = fmaxf(acc, 0.f);
    out[(size_t)node * 128 + f] = acc;
}

// ---------------- fused decoder ----------------
__global__ __launch_bounds__(256) void k_decoder(
    const float* __restrict__ z, const int* __restrict__ xidx, const int* __restrict__ yidx,
    const float* __restrict__ w1, const float* __restrict__ b1,
    const float* __restrict__ w2, const float* __restrict__ b2,
    float* __restrict__ p)
{
    __shared__ float As[16][128];
    __shared__ float Bs[16][128];
    __shared__ int   sxi[128], syi[128];
    __shared__ float sw2[128], sb1[128];
    __shared__ float red[128][17];

    int tid = threadIdx.x;
    int tx = tid & 15, ty = tid >> 4;
    int pairBase = blockIdx.x * 128;

    if (tid < 128) {
        int pp = pairBase + tid;
        sxi[tid] = (pp < NP) ? xidx[pp] : 0;
        syi[tid] = (pp < NP) ? yidx[pp] : 0;
        sw2[tid] = w2[tid];
        sb1[tid] = b1[tid];
    }
    __syncthreads();

    unsigned long long accp[8][4];
#pragma unroll
    for (int i = 0; i < 8; i++)
#pragma unroll
        for (int j = 0; j < 4; j++) accp[i][j] = 0ull;

    for (int kt = 0; kt < 256; kt += 16) {
#pragma unroll
        for (int j = 0; j < 2; j++) {
            int f4 = tid * 2 + j;
            int r  = f4 >> 2;
            int k4 = (f4 & 3) << 2;
            int kg = kt + k4;
            int node, koff;
            if (kg < 128) { node = sxi[r]; koff = kg; }
            else          { node = syi[r]; koff = kg - 128; }
            float4 v = *(const float4*)(z + (size_t)node * 128 + koff);
            As[k4 + 0][r] = v.x; As[k4 + 1][r] = v.y;
            As[k4 + 2][r] = v.z; As[k4 + 3][r] = v.w;
        }
#pragma unroll
        for (int j = 0; j < 2; j++) {
            int f4 = tid * 2 + j;
            int kr = f4 >> 5;
            int n4 = (f4 & 31) << 2;
            *(float4*)(&Bs[kr][n4]) = *(const float4*)(w1 + (size_t)(kt + kr) * 128 + n4);
        }
        __syncthreads();
#pragma unroll
        for (int kk = 0; kk < 16; kk++) {
            float ra[8];
            unsigned long long rb2[4];
#pragma unroll
            for (int i = 0; i < 8; i++) ra[i] = As[kk][ty * 8 + i];
            const unsigned long long* bp = (const unsigned long long*)&Bs[kk][tx * 8];
#pragma unroll
            for (int j = 0; j < 4; j++) rb2[j] = bp[j];
#pragma unroll
            for (int i = 0; i < 8; i++) {
                unsigned long long ra2 = pack2(ra[i]);
#pragma unroll
                for (int j = 0; j < 4; j++) accp[i][j] = fma_f32x2(ra2, rb2[j], accp[i][j]);
            }
        }
        __syncthreads();
    }

    // fc2 + sigmoid epilogue (hdec never materialized)
    float part[8];
#pragma unroll
    for (int i = 0; i < 8; i++) part[i] = 0.f;
#pragma unroll
    for (int i = 0; i < 8; i++) {
#pragma unroll
        for (int j = 0; j < 4; j++) {
            int c = tx * 8 + j * 2;
            float2 pv = unpack2(accp[i][j]);
            float h0 = fmaxf(pv.x + sb1[c + 0], 0.f);
            float h1 = fmaxf(pv.y + sb1[c + 1], 0.f);
            part[i] += h0 * sw2[c + 0] + h1 * sw2[c + 1];
        }
    }
#pragma unroll
    for (int i = 0; i < 8; i++) red[ty * 8 + i][tx] = part[i];
    __syncthreads();
    if (tid < 128) {
        float s = 0.f;
#pragma unroll
        for (int c = 0; c < 16; c++) s += red[tid][c];
        s += b2[0];
        float pv = 1.f / (1.f + expf(-s));
        int pp = pairBase + tid;
        if (pp < NP) p[pp] = pv;
    }
}

// ---------------- launch ----------------
extern "C" void kernel_launch(void* const* d_in, const int* in_sizes, int n_in,
                              void* d_out, int out_size) {
    const float* x     = (const float*)d_in[0];
    const int*   erow  = (const int*)  d_in[1];
    const int*   ecol  = (const int*)  d_in[2];
    const float* ew    = (const float*)d_in[3];
    const int*   xidx  = (const int*)  d_in[4];
    const int*   yidx  = (const int*)  d_in[5];
    const float* ws[3] = { (const float*)d_in[6],  (const float*)d_in[9],  (const float*)d_in[12] };
    const float* wn[3] = { (const float*)d_in[7],  (const float*)d_in[10], (const float*)d_in[13] };
    const float* bb[3] = { (const float*)d_in[8],  (const float*)d_in[11], (const float*)d_in[14] };
    const float* dw1 = (const float*)d_in[15];
    const float* db1 = (const float*)d_in[16];
    const float* dw2 = (const float*)d_in[17];
    const float* db2 = (const float*)d_in[18];

    float* out = (float*)d_out;
    float* p_out = out;            // [NP]
    float* z_out = out + NP;       // [NN*128]

    void* ptr;
    cudaGetSymbolAddress(&ptr, g_h);       float* h_buf     = (float*)ptr;
    cudaGetSymbolAddress(&ptr, g_selfb);   float* selfb_buf = (float*)ptr;
    cudaGetSymbolAddress(&ptr, g_support); float* sup_buf   = (float*)ptr;

    // CSR build
    k_zero_deg<<<(NN + 255) / 256, 256>>>();
    k_count_deg<<<(NE + 255) / 256, 256>>>(erow);
    k_scan_part<<<NBLK, SCAN_B>>>();
    k_scan_mid<<<1, 128>>>();
    k_scan_final<<<NBLK, SCAN_B>>>();
    k_scatter_edges<<<(NE + 255) / 256, 256>>>(erow, ecol, ew);

    const int gemmGrid = (NN + 127) / 128;

    // layer 1
    k_gemm128<<<gemmGrid, 256>>>(x, ws[0], bb[0], selfb_buf, NN);
    k_gemm128<<<gemmGrid, 256>>>(x, wn[0], nullptr, sup_buf, NN);
    k_aggregate<<<NN, 128>>>(h_buf, 1);
    // layer 2
    k_gemm128<<<gemmGrid, 256>>>(h_buf, ws[1], bb[1], selfb_buf, NN);
    k_gemm128<<<gemmGrid, 256>>>(h_buf, wn[1], nullptr, sup_buf, NN);
    k_aggregate<<<NN, 128>>>(h_buf, 1);
    // layer 3 -> z (no relu) straight into d_out
    k_gemm128<<<gemmGrid, 256>>>(h_buf, ws[2], bb[2], selfb_buf, NN);
    k_gemm128<<<gemmGrid, 256>>>(h_buf, wn[2], nullptr, sup_buf, NN);
    k_aggregate<<<NN, 128>>>(z_out, 0);

    // decoder -> p
    k_decoder<<<(NP + 127) / 128, 256>>>(z_out, xidx, yidx, dw1, db1, dw2, db2, p_out);
}

// round 4
// speedup vs baseline: 1.4165x; 1.2931x over previous
#include <cuda_runtime.h>
#include <cuda_fp16.h>
#include <math.h>
#include <stdint.h>

#define NN 100000
#define NE 1600000
#define NP 500000
#define SCAN_B 1024
#define NBLK ((NN + SCAN_B - 1) / SCAN_B)   // 98

// ---------------- static device scratch ----------------
__device__ float g_h[(size_t)NN * 128];
__device__ float g_selfb[(size_t)NN * 128];
__device__ float g_support[(size_t)NN * 128];
__device__ int   g_rowptr[NN + 1];
__device__ int   g_cursor[NN];
__device__ int   g_partial[NBLK];
__device__ int   g_blockoff[NBLK];
__device__ int   g_pcol[NE];
__device__ float g_pw[NE];
// converted weights: 6 node mats [n][k] 128x128 + W1 [n][k] 128x256, fp16 hi/lo
#define W_NODE_ELEMS (6 * 16384)
#define W_TOTAL (W_NODE_ELEMS + 32768)
__device__ __half g_whi[W_TOTAL];
__device__ __half g_wlo[W_TOTAL];

// ---------------- helpers ----------------
__device__ __forceinline__ uint32_t smem_u32(const void* p) {
    uint32_t a;
    asm("{ .reg .u64 t; cvta.to.shared.u64 t, %1; cvt.u32.u64 %0, t; }" : "=r"(a) : "l"(p));
    return a;
}
__device__ __forceinline__ void ldsm_x4(uint32_t& r0, uint32_t& r1, uint32_t& r2, uint32_t& r3,
                                        uint32_t addr) {
    asm volatile("ldmatrix.sync.aligned.m8n8.x4.shared.b16 {%0,%1,%2,%3}, [%4];"
                 : "=r"(r0), "=r"(r1), "=r"(r2), "=r"(r3) : "r"(addr));
}
__device__ __forceinline__ void ldsm_x2(uint32_t& r0, uint32_t& r1, uint32_t addr) {
    asm volatile("ldmatrix.sync.aligned.m8n8.x2.shared.b16 {%0,%1}, [%2];"
                 : "=r"(r0), "=r"(r1) : "r"(addr));
}
__device__ __forceinline__ void mma16816(float* c, const uint32_t* a, const uint32_t* b) {
    asm volatile("mma.sync.aligned.m16n8k16.row.col.f32.f16.f16.f32 "
                 "{%0,%1,%2,%3}, {%4,%5,%6,%7}, {%8,%9}, {%0,%1,%2,%3};"
                 : "+f"(c[0]), "+f"(c[1]), "+f"(c[2]), "+f"(c[3])
                 : "r"(a[0]), "r"(a[1]), "r"(a[2]), "r"(a[3]), "r"(b[0]), "r"(b[1]));
}

// split fp32 -> (hi, lo) fp16
__device__ __forceinline__ void split1(float v, __half& h, __half& l) {
    h = __float2half_rn(v);
    l = __float2half_rn(v - __half2float(h));
}
// split float4 and store 4 halfs (8B) to each of hi/lo
__device__ __forceinline__ void split_store4(char* hiP, char* loP, uint32_t off, float4 v) {
    __half hx, hy, hz, hw, lx, ly, lz, lw;
    split1(v.x, hx, lx); split1(v.y, hy, ly);
    split1(v.z, hz, lz); split1(v.w, hw, lw);
    __half2 h01 = __halves2half2(hx, hy), h23 = __halves2half2(hz, hw);
    __half2 l01 = __halves2half2(lx, ly), l23 = __halves2half2(lz, lw);
    uint2 uh, ul;
    uh.x = *reinterpret_cast<unsigned*>(&h01); uh.y = *reinterpret_cast<unsigned*>(&h23);
    ul.x = *reinterpret_cast<unsigned*>(&l01); ul.y = *reinterpret_cast<unsigned*>(&l23);
    *(uint2*)(hiP + off) = uh;
    *(uint2*)(loP + off) = ul;
}

// padded row strides (halfs): K=128 tiles -> 136, K=256 tiles -> 264
#define PK128 136
#define PK256 264

// ---------------- CSR build ----------------
__global__ void k_zero_deg() {
    int i = blockIdx.x * blockDim.x + threadIdx.x;
    if (i < NN) g_cursor[i] = 0;
}
__global__ void k_count_deg(const int* __restrict__ row) {
    int e = blockIdx.x * blockDim.x + threadIdx.x;
    if (e < NE) atomicAdd(&g_cursor[row[e]], 1);
}
__global__ __launch_bounds__(SCAN_B) void k_scan_part() {
    __shared__ int sh[SCAN_B / 32];
    int t = threadIdx.x;
    int idx = blockIdx.x * SCAN_B + t;
    int v = (idx < NN) ? g_cursor[idx] : 0;
#pragma unroll
    for (int off = 16; off > 0; off >>= 1) v += __shfl_down_sync(0xffffffffu, v, off);
    if ((t & 31) == 0) sh[t >> 5] = v;
    __syncthreads();
    if (t < 32) {
        int s = (t < SCAN_B / 32) ? sh[t] : 0;
#pragma unroll
        for (int off = 16; off > 0; off >>= 1) s += __shfl_down_sync(0xffffffffu, s, off);
        if (t == 0) g_partial[blockIdx.x] = s;
    }
}
__global__ __launch_bounds__(128) void k_scan_mid() {
    __shared__ int sh[128];
    int t = threadIdx.x;
    int v = (t < NBLK) ? g_partial[t] : 0;
    sh[t] = v;
    __syncthreads();
#pragma unroll
    for (int off = 1; off < 128; off <<= 1) {
        int y = (t >= off) ? sh[t - off] : 0;
        __syncthreads();
        sh[t] += y;
        __syncthreads();
    }
    if (t < NBLK) g_blockoff[t] = sh[t] - v;
}
__global__ __launch_bounds__(SCAN_B) void k_scan_final() {
    __shared__ int sh[SCAN_B];
    int t = threadIdx.x;
    int idx = blockIdx.x * SCAN_B + t;
    int v = (idx < NN) ? g_cursor[idx] : 0;
    sh[t] = v;
    __syncthreads();
#pragma unroll
    for (int off = 1; off < SCAN_B; off <<= 1) {
        int y = (t >= off) ? sh[t - off] : 0;
        __syncthreads();
        sh[t] += y;
        __syncthreads();
    }
    if (idx < NN) {
        int incl = sh[t] + g_blockoff[blockIdx.x];
        g_rowptr[idx + 1] = incl;
        g_cursor[idx] = incl - v;
    }
    if (idx == 0) g_rowptr[0] = 0;
}
__global__ void k_scatter_edges(const int* __restrict__ row, const int* __restrict__ col,
                                const float* __restrict__ w) {
    int e = blockIdx.x * blockDim.x + threadIdx.x;
    if (e < NE) {
        int pos = atomicAdd(&g_cursor[row[e]], 1);
        g_pcol[pos] = col[e];
        g_pw[pos]   = w[e];
    }
}

// ---------------- neighbor aggregation ----------------
__global__ __launch_bounds__(128) void k_aggregate(float* __restrict__ out, int relu) {
    int node = blockIdx.x;
    int f = threadIdx.x;
    float acc0 = g_selfb[(size_t)node * 128 + f];
    float acc1 = 0.f;
    int s = g_rowptr[node];
    int e = g_rowptr[node + 1];
    int i = s;
    for (; i + 1 < e; i += 2) {
        int c0 = g_pcol[i], c1 = g_pcol[i + 1];
        float w0 = g_pw[i], w1 = g_pw[i + 1];
        acc0 += w0 * g_support[(size_t)c0 * 128 + f];
        acc1 += w1 * g_support[(size_t)c1 * 128 + f];
    }
    if (i < e) acc0 += g_pw[i] * g_support[(size_t)g_pcol[i] * 128 + f];
    float acc = acc0 + acc1;
    if (relu) acc = fmaxf(acc, 0.f);
    out[(size_t)node * 128 + f] = acc;
}

// ---------------- weight conversion (once per launch) ----------------
// node mats m=0..5: dst[m*16384 + n*128 + k] = split(W[k*128+n])
// w1: dst[98304 + n*256 + k] = split(w1[k*128+n])
__global__ void k_convert_weights(const float* w0, const float* w1_, const float* w2_,
                                  const float* w3, const float* w4, const float* w5,
                                  const float* wdec) {
    int idx = blockIdx.x * blockDim.x + threadIdx.x;
    if (idx >= W_TOTAL) return;
    float v;
    if (idx < W_NODE_ELEMS) {
        int m = idx >> 14;
        int e = idx & 16383;
        int n = e >> 7, k = e & 127;
        const float* W = (m == 0) ? w0 : (m == 1) ? w1_ : (m == 2) ? w2_
                       : (m == 3) ? w3 : (m == 4) ? w4 : w5;
        v = W[k * 128 + n];
    } else {
        int e = idx - W_NODE_ELEMS;
        int n = e >> 8, k = e & 255;
        v = wdec[k * 128 + n];
    }
    __half h, l;
    split1(v, h, l);
    g_whi[idx] = h;
    g_wlo[idx] = l;
}

// ---------------- warp GEMM core: 32x64 per warp, K=128 chunk ----------------
// As[m][k] padded PK128, Bs[n][k] padded PK128. acc[2][8][4] (f32).
__device__ __forceinline__ void warp_mm_k128(uint32_t asH, uint32_t asL,
                                             uint32_t bsH, uint32_t bsL,
                                             int warpM, int warpN, int lane,
                                             float acc[2][8][4]) {
    // lane-invariant address bases
    uint32_t aRow = warpM * 32 + (lane & 15);
    uint32_t aColSel = (lane >> 4) * 8;
    uint32_t aOff0 = (aRow * PK128 + aColSel) * 2;          // mt=0
    uint32_t aOff1 = ((aRow + 16) * PK128 + aColSel) * 2;   // mt=1
    uint32_t bRow = warpN * 64 + (lane & 7);
    uint32_t bColSel = ((lane >> 3) & 1) * 8;
    uint32_t bOffBase = (bRow * PK128 + bColSel) * 2;

    for (int ks = 0; ks < 8; ks++) {
        uint32_t kadd = ks * 32;  // 16 halfs
        uint32_t aH[2][4], aL[2][4];
        ldsm_x4(aH[0][0], aH[0][1], aH[0][2], aH[0][3], asH + aOff0 + kadd);
        ldsm_x4(aH[1][0], aH[1][1], aH[1][2], aH[1][3], asH + aOff1 + kadd);
        ldsm_x4(aL[0][0], aL[0][1], aL[0][2], aL[0][3], asL + aOff0 + kadd);
        ldsm_x4(aL[1][0], aL[1][1], aL[1][2], aL[1][3], asL + aOff1 + kadd);
#pragma unroll
        for (int nt = 0; nt < 8; nt++) {
            uint32_t bo = bOffBase + nt * 8 * PK128 * 2 + kadd;
            uint32_t bH[2], bL[2];
            ldsm_x2(bH[0], bH[1], bsH + bo);
            ldsm_x2(bL[0], bL[1], bsL + bo);
#pragma unroll
            for (int mt = 0; mt < 2; mt++) {
                mma16816(acc[mt][nt], aH[mt], bH);
                mma16816(acc[mt][nt], aH[mt], bL);
                mma16816(acc[mt][nt], aL[mt], bH);
            }
        }
    }
}

// ---------------- fused node layer GEMM ----------------
// smem offsets (bytes)
#define NO_BIAS  0                       // 512
#define NO_AHI   1024
#define NO_ALO   (NO_AHI + 128 * PK128 * 2)   // +34816
#define NO_WSHI  (NO_ALO + 128 * PK128 * 2)
#define NO_WSLO  (NO_WSHI + 128 * PK128 * 2)
#define NO_WNHI  (NO_WSLO + 128 * PK128 * 2)
#define NO_WNLO  (NO_WNHI + 128 * PK128 * 2)
#define NO_SMEM  (NO_WNLO + 128 * PK128 * 2)  // 209920

__global__ __launch_bounds__(256, 1) void k_mm_node(
    const float* __restrict__ A, int wsel,       // weight pair index (layer): ws=g_whi+wsel*2*16384...
    const float* __restrict__ bias,
    float* __restrict__ Cself, float* __restrict__ Csup)
{
    extern __shared__ char sm[];
    uint32_t sb = smem_u32(sm);
    int tid = threadIdx.x;
    int lane = tid & 31, wid = tid >> 5;
    int warpM = wid & 3, warpN = wid >> 2;
    int base = blockIdx.x * 128;

    if (tid < 128) ((float*)(sm + NO_BIAS))[tid] = bias[tid];

    // copy weights (fp16, [n][k] contiguous) into padded smem
    const uint4* whS = (const uint4*)(g_whi + (size_t)(2 * wsel) * 16384);
    const uint4* wlS = (const uint4*)(g_wlo + (size_t)(2 * wsel) * 16384);
    const uint4* whN = (const uint4*)(g_whi + (size_t)(2 * wsel + 1) * 16384);
    const uint4* wlN = (const uint4*)(g_wlo + (size_t)(2 * wsel + 1) * 16384);
    for (int idx = tid; idx < 2048; idx += 256) {
        int r = idx >> 4, u = idx & 15;
        uint32_t off = r * (PK128 * 2) + u * 16;
        *(uint4*)(sm + NO_WSHI + off) = whS[idx];
        *(uint4*)(sm + NO_WSLO + off) = wlS[idx];
        *(uint4*)(sm + NO_WNHI + off) = whN[idx];
        *(uint4*)(sm + NO_WNLO + off) = wlN[idx];
    }
    // load + split A tile
    for (int idx = tid; idx < 4096; idx += 256) {
        int r = idx >> 5, c4 = idx & 31;
        int gr = base + r;
        float4 v = (gr < NN) ? *(const float4*)(A + (size_t)gr * 128 + c4 * 4)
                             : make_float4(0.f, 0.f, 0.f, 0.f);
        split_store4(sm + NO_AHI, sm + NO_ALO, r * (PK128 * 2) + c4 * 8, v);
    }
    __syncthreads();

    const float* sbias = (const float*)(sm + NO_BIAS);

    // pass 1: Ws (+bias) -> Cself
    {
        float acc[2][8][4];
#pragma unroll
        for (int mt = 0; mt < 2; mt++)
#pragma unroll
            for (int nt = 0; nt < 8; nt++)
#pragma unroll
                for (int q = 0; q < 4; q++) acc[mt][nt][q] = 0.f;
        warp_mm_k128(sb + NO_AHI, sb + NO_ALO, sb + NO_WSHI, sb + NO_WSLO,
                     warpM, warpN, lane, acc);
#pragma unroll
        for (int mt = 0; mt < 2; mt++) {
            int r0 = base + warpM * 32 + mt * 16 + (lane >> 2);
#pragma unroll
            for (int nt = 0; nt < 8; nt++) {
                int c = warpN * 64 + nt * 8 + (lane & 3) * 2;
                if (r0 < NN) {
                    float2 v0 = make_float2(acc[mt][nt][0] + sbias[c],
                                            acc[mt][nt][1] + sbias[c + 1]);
                    *(float2*)(Cself + (size_t)r0 * 128 + c) = v0;
                }
                if (r0 + 8 < NN) {
                    float2 v1 = make_float2(acc[mt][nt][2] + sbias[c],
                                            acc[mt][nt][3] + sbias[c + 1]);
                    *(float2*)(Cself + (size_t)(r0 + 8) * 128 + c) = v1;
                }
            }
        }
    }
    // pass 2: Wn -> Csup
    {
        float acc[2][8][4];
#pragma unroll
        for (int mt = 0; mt < 2; mt++)
#pragma unroll
            for (int nt = 0; nt < 8; nt++)
#pragma unroll
                for (int q = 0; q < 4; q++) acc[mt][nt][q] = 0.f;
        warp_mm_k128(sb + NO_AHI, sb + NO_ALO, sb + NO_WNHI, sb + NO_WNLO,
                     warpM, warpN, lane, acc);
#pragma unroll
        for (int mt = 0; mt < 2; mt++) {
            int r0 = base + warpM * 32 + mt * 16 + (lane >> 2);
#pragma unroll
            for (int nt = 0; nt < 8; nt++) {
                int c = warpN * 64 + nt * 8 + (lane & 3) * 2;
                if (r0 < NN)
                    *(float2*)(Csup + (size_t)r0 * 128 + c) =
                        make_float2(acc[mt][nt][0], acc[mt][nt][1]);
                if (r0 + 8 < NN)
                    *(float2*)(Csup + (size_t)(r0 + 8) * 128 + c) =
                        make_float2(acc[mt][nt][2], acc[mt][nt][3]);
            }
        }
    }
}

// ---------------- fused decoder ----------------
#define DO_B1   0      // 512
#define DO_W2   512    // 512
#define DO_XI   1024   // 512
#define DO_YI   1536   // 512
#define DO_AHI  2048
#define DO_ALO  (DO_AHI + 128 * PK128 * 2)
#define DO_W1HI (DO_ALO + 128 * PK128 * 2)       // 128 rows x PK256
#define DO_W1LO (DO_W1HI + 128 * PK256 * 2)
#define DO_SMEM (DO_W1LO + 128 * PK256 * 2)      // 206848
#define DO_RED  DO_AHI                            // reuse after compute: float[128][8]

__global__ __launch_bounds__(256, 1) void k_mm_decoder(
    const float* __restrict__ z, const int* __restrict__ xidx, const int* __restrict__ yidx,
    const float* __restrict__ b1, const float* __restrict__ w2, const float* __restrict__ b2,
    float* __restrict__ p)
{
    extern __shared__ char sm[];
    uint32_t sb = smem_u32(sm);
    int tid = threadIdx.x;
    int lane = tid & 31, wid = tid >> 5;
    int warpM = wid & 3, warpN = wid >> 2;
    int pairBase = blockIdx.x * 128;

    if (tid < 128) {
        ((float*)(sm + DO_B1))[tid] = b1[tid];
        ((float*)(sm + DO_W2))[tid] = w2[tid];
        int pp = pairBase + tid;
        ((int*)(sm + DO_XI))[tid] = (pp < NP) ? xidx[pp] : 0;
        ((int*)(sm + DO_YI))[tid] = (pp < NP) ? yidx[pp] : 0;
    }
    // copy W1 fp16 [n][k256] into padded smem
    {
        const uint4* wh = (const uint4*)(g_whi + W_NODE_ELEMS);
        const uint4* wl = (const uint4*)(g_wlo + W_NODE_ELEMS);
        for (int idx = tid; idx < 4096; idx += 256) {
            int r = idx >> 5, u = idx & 31;
            uint32_t off = r * (PK256 * 2) + u * 16;
            *(uint4*)(sm + DO_W1HI + off) = wh[idx];
            *(uint4*)(sm + DO_W1LO + off) = wl[idx];
        }
    }
    __syncthreads();

    const int* sxi = (const int*)(sm + DO_XI);
    const int* syi = (const int*)(sm + DO_YI);

    float acc[2][8][4];
#pragma unroll
    for (int mt = 0; mt < 2; mt++)
#pragma unroll
        for (int nt = 0; nt < 8; nt++)
#pragma unroll
            for (int q = 0; q < 4; q++) acc[mt][nt][q] = 0.f;

    // address bases
    uint32_t aRow = warpM * 32 + (lane & 15);
    uint32_t aColSel = (lane >> 4) * 8;
    uint32_t aOff0 = (aRow * PK128 + aColSel) * 2;
    uint32_t aOff1 = ((aRow + 16) * PK128 + aColSel) * 2;
    uint32_t bRow = warpN * 64 + (lane & 7);
    uint32_t bColSel = ((lane >> 3) & 1) * 8;
    uint32_t bOffBase = (bRow * PK256 + bColSel) * 2;

    for (int chunk = 0; chunk < 2; chunk++) {
        // gather A chunk: z[xidx] (chunk 0) or z[yidx] (chunk 1)
        const int* nidx = chunk ? syi : sxi;
        for (int idx = tid; idx < 4096; idx += 256) {
            int r = idx >> 5, c4 = idx & 31;
            int node = nidx[r];
            float4 v = *(const float4*)(z + (size_t)node * 128 + c4 * 4);
            split_store4(sm + DO_AHI, sm + DO_ALO, r * (PK128 * 2) + c4 * 8, v);
        }
        __syncthreads();

        uint32_t kChunk = chunk * 128 * 2;  // byte offset into W1 K dim
        for (int ks = 0; ks < 8; ks++) {
            uint32_t kadd = ks * 32;
            uint32_t aH[2][4], aL[2][4];
            ldsm_x4(aH[0][0], aH[0][1], aH[0][2], aH[0][3], sb + DO_AHI + aOff0 + kadd);
            ldsm_x4(aH[1][0], aH[1][1], aH[1][2], aH[1][3], sb + DO_AHI + aOff1 + kadd);
            ldsm_x4(aL[0][0], aL[0][1], aL[0][2], aL[0][3], sb + DO_ALO + aOff0 + kadd);
            ldsm_x4(aL[1][0], aL[1][1], aL[1][2], aL[1][3], sb + DO_ALO + aOff1 + kadd);
#pragma unroll
            for (int nt = 0; nt < 8; nt++) {
                uint32_t bo = bOffBase + nt * 8 * PK256 * 2 + kChunk + kadd;
                uint32_t bH[2], bL[2];
                ldsm_x2(bH[0], bH[1], sb + DO_W1HI + bo);
                ldsm_x2(bL[0], bL[1], sb + DO_W1LO + bo);
#pragma unroll
                for (int mt = 0; mt < 2; mt++) {
                    mma16816(acc[mt][nt], aH[mt], bH);
                    mma16816(acc[mt][nt], aH[mt], bL);
                    mma16816(acc[mt][nt], aL[mt], bH);
                }
            }
        }
        __syncthreads();  // A smem reused next chunk / as red
    }

    // epilogue: hdec = relu(acc + b1); partial = hdec . w2 per row
    const float* sb1 = (const float*)(sm + DO_B1);
    const float* sw2 = (const float*)(sm + DO_W2);
    float* red = (float*)(sm + DO_RED);   // [128][8]
#pragma unroll
    for (int mt = 0; mt < 2; mt++) {
        int rl = warpM * 32 + mt * 16 + (lane >> 2);
        float p0 = 0.f, p1 = 0.f;
#pragma unroll
        for (int nt = 0; nt < 8; nt++) {
            int c = warpN * 64 + nt * 8 + (lane & 3) * 2;
            float h00 = fmaxf(acc[mt][nt][0] + sb1[c], 0.f);
            float h01 = fmaxf(acc[mt][nt][1] + sb1[c + 1], 0.f);
            float h10 = fmaxf(acc[mt][nt][2] + sb1[c], 0.f);
            float h11 = fmaxf(acc[mt][nt][3] + sb1[c + 1], 0.f);
            p0 += h00 * sw2[c] + h01 * sw2[c + 1];
            p1 += h10 * sw2[c] + h11 * sw2[c + 1];
        }
        red[rl * 8 + warpN * 4 + (lane & 3)] = p0;
        red[(rl + 8) * 8 + warpN * 4 + (lane & 3)] = p1;
    }
    __syncthreads();
    if (tid < 128) {
        float s = 0.f;
#pragma unroll
        for (int j = 0; j < 8; j++) s += red[tid * 8 + j];
        s += b2[0];
        float pv = 1.f / (1.f + expf(-s));
        int pp = pairBase + tid;
        if (pp < NP) p[pp] = pv;
    }
}

// ---------------- launch ----------------
extern "C" void kernel_launch(void* const* d_in, const int* in_sizes, int n_in,
                              void* d_out, int out_size) {
    const float* x     = (const float*)d_in[0];
    const int*   erow  = (const int*)  d_in[1];
    const int*   ecol  = (const int*)  d_in[2];
    const float* ew    = (const float*)d_in[3];
    const int*   xidx  = (const int*)  d_in[4];
    const int*   yidx  = (const int*)  d_in[5];
    const float* ws[3] = { (const float*)d_in[6],  (const float*)d_in[9],  (const float*)d_in[12] };
    const float* wn[3] = { (const float*)d_in[7],  (const float*)d_in[10], (const float*)d_in[13] };
    const float* bb[3] = { (const float*)d_in[8],  (const float*)d_in[11], (const float*)d_in[14] };
    const float* dw1 = (const float*)d_in[15];
    const float* db1 = (const float*)d_in[16];
    const float* dw2 = (const float*)d_in[17];
    const float* db2 = (const float*)d_in[18];

    float* out = (float*)d_out;
    float* p_out = out;            // [NP]
    float* z_out = out + NP;       // [NN*128]

    void* ptr;
    cudaGetSymbolAddress(&ptr, g_h);       float* h_buf     = (float*)ptr;
    cudaGetSymbolAddress(&ptr, g_selfb);   float* selfb_buf = (float*)ptr;
    cudaGetSymbolAddress(&ptr, g_support); float* sup_buf   = (float*)ptr;

    cudaFuncSetAttribute(k_mm_node, cudaFuncAttributeMaxDynamicSharedMemorySize, NO_SMEM);
    cudaFuncSetAttribute(k_mm_decoder, cudaFuncAttributeMaxDynamicSharedMemorySize, DO_SMEM);

    // CSR build + weight conversion
    k_zero_deg<<<(NN + 255) / 256, 256>>>();
    k_count_deg<<<(NE + 255) / 256, 256>>>(erow);
    k_scan_part<<<NBLK, SCAN_B>>>();
    k_scan_mid<<<1, 128>>>();
    k_scan_final<<<NBLK, SCAN_B>>>();
    k_scatter_edges<<<(NE + 255) / 256, 256>>>(erow, ecol, ew);
    k_convert_weights<<<(W_TOTAL + 255) / 256, 256>>>(ws[0], wn[0], ws[1], wn[1], ws[2], wn[2], dw1);

    const int nodeGrid = (NN + 127) / 128;   // 782

    // layer 1 (weights pair 0: idx 0=ws1, 1=wn1)
    k_mm_node<<<nodeGrid, 256, NO_SMEM>>>(x, 0, bb[0], selfb_buf, sup_buf);
    k_aggregate<<<NN, 128>>>(h_buf, 1);
    // layer 2
    k_mm_node<<<nodeGrid, 256, NO_SMEM>>>(h_buf, 1, bb[1], selfb_buf, sup_buf);
    k_aggregate<<<NN, 128>>>(h_buf, 1);
    // layer 3 -> z
    k_mm_node<<<nodeGrid, 256, NO_SMEM>>>(h_buf, 2, bb[2], selfb_buf, sup_buf);
    k_aggregate<<<NN, 128>>>(z_out, 0);

    // decoder
    k_mm_decoder<<<(NP + 127) / 128, 256, DO_SMEM>>>(z_out, xidx, yidx, db1, dw2, db2, p_out);
}

// round 5
// speedup vs baseline: 1.8249x; 1.2883x over previous
#include <cuda_runtime.h>
#include <cuda_fp16.h>
#include <math.h>
#include <stdint.h>

#define NN 100000
#define NE 1600000
#define NP 500000
#define SCAN_B 1024
#define NBLK ((NN + SCAN_B - 1) / SCAN_B)   // 98

// ---------------- static device scratch ----------------
__device__ float g_selfb[(size_t)NN * 128];
__device__ float g_support[(size_t)NN * 128];
__device__ __half g_ahi[(size_t)NN * 128];   // activation hi (GEMM A input)
__device__ __half g_alo[(size_t)NN * 128];   // activation lo
__device__ int   g_rowptr[NN + 1];
__device__ int   g_cursor[NN];
__device__ int   g_partial[NBLK];
__device__ int   g_blockoff[NBLK];
__device__ int   g_pcol[NE];
__device__ float g_pw[NE];
// converted weights: 6 node mats [n][k] 128x128 + W1 [n][k] 128x256, fp16 hi/lo
#define W_NODE_ELEMS (6 * 16384)
#define W_TOTAL (W_NODE_ELEMS + 32768)
__device__ __half g_whi[W_TOTAL];
__device__ __half g_wlo[W_TOTAL];

// padded row strides in halfs
#define PK128 136
#define PK256 264

// ---------------- helpers ----------------
__device__ __forceinline__ uint32_t smem_u32(const void* p) {
    uint32_t a;
    asm("{ .reg .u64 t; cvta.to.shared.u64 t, %1; cvt.u32.u64 %0, t; }" : "=r"(a) : "l"(p));
    return a;
}
__device__ __forceinline__ void ldsm_x4(uint32_t& r0, uint32_t& r1, uint32_t& r2, uint32_t& r3,
                                        uint32_t addr) {
    asm volatile("ldmatrix.sync.aligned.m8n8.x4.shared.b16 {%0,%1,%2,%3}, [%4];"
                 : "=r"(r0), "=r"(r1), "=r"(r2), "=r"(r3) : "r"(addr));
}
__device__ __forceinline__ void ldsm_x2(uint32_t& r0, uint32_t& r1, uint32_t addr) {
    asm volatile("ldmatrix.sync.aligned.m8n8.x2.shared.b16 {%0,%1}, [%2];"
                 : "=r"(r0), "=r"(r1) : "r"(addr));
}
__device__ __forceinline__ void mma16816(float* c, const uint32_t* a, const uint32_t* b) {
    asm volatile("mma.sync.aligned.m16n8k16.row.col.f32.f16.f16.f32 "
                 "{%0,%1,%2,%3}, {%4,%5,%6,%7}, {%8,%9}, {%0,%1,%2,%3};"
                 : "+f"(c[0]), "+f"(c[1]), "+f"(c[2]), "+f"(c[3])
                 : "r"(a[0]), "r"(a[1]), "r"(a[2]), "r"(a[3]), "r"(b[0]), "r"(b[1]));
}
__device__ __forceinline__ void cp16(uint32_t dst, const void* src, unsigned sz) {
    asm volatile("cp.async.cg.shared.global [%0], [%1], 16, %2;"
                 :: "r"(dst), "l"(src), "r"(sz) : "memory");
}
#define CP_COMMIT() asm volatile("cp.async.commit_group;" ::: "memory")
#define CP_WAIT1()  asm volatile("cp.async.wait_group 1;" ::: "memory")
#define CP_WAIT0()  asm volatile("cp.async.wait_group 0;" ::: "memory")

__device__ __forceinline__ void split1(float v, __half& h, __half& l) {
    h = __float2half_rn(v);
    l = __float2half_rn(v - __half2float(h));
}

// ---------------- CSR build ----------------
__global__ void k_zero_deg() {
    int i = blockIdx.x * blockDim.x + threadIdx.x;
    if (i < NN) g_cursor[i] = 0;
}
__global__ void k_count_deg(const int* __restrict__ row) {
    int e = blockIdx.x * blockDim.x + threadIdx.x;
    if (e < NE) atomicAdd(&g_cursor[row[e]], 1);
}
__global__ __launch_bounds__(SCAN_B) void k_scan_part() {
    __shared__ int sh[SCAN_B / 32];
    int t = threadIdx.x;
    int idx = blockIdx.x * SCAN_B + t;
    int v = (idx < NN) ? g_cursor[idx] : 0;
#pragma unroll
    for (int off = 16; off > 0; off >>= 1) v += __shfl_down_sync(0xffffffffu, v, off);
    if ((t & 31) == 0) sh[t >> 5] = v;
    __syncthreads();
    if (t < 32) {
        int s = (t < SCAN_B / 32) ? sh[t] : 0;
#pragma unroll
        for (int off = 16; off > 0; off >>= 1) s += __shfl_down_sync(0xffffffffu, s, off);
        if (t == 0) g_partial[blockIdx.x] = s;
    }
}
__global__ __launch_bounds__(128) void k_scan_mid() {
    __shared__ int sh[128];
    int t = threadIdx.x;
    int v = (t < NBLK) ? g_partial[t] : 0;
    sh[t] = v;
    __syncthreads();
#pragma unroll
    for (int off = 1; off < 128; off <<= 1) {
        int y = (t >= off) ? sh[t - off] : 0;
        __syncthreads();
        sh[t] += y;
        __syncthreads();
    }
    if (t < NBLK) g_blockoff[t] = sh[t] - v;
}
__global__ __launch_bounds__(SCAN_B) void k_scan_final() {
    __shared__ int sh[SCAN_B];
    int t = threadIdx.x;
    int idx = blockIdx.x * SCAN_B + t;
    int v = (idx < NN) ? g_cursor[idx] : 0;
    sh[t] = v;
    __syncthreads();
#pragma unroll
    for (int off = 1; off < SCAN_B; off <<= 1) {
        int y = (t >= off) ? sh[t - off] : 0;
        __syncthreads();
        sh[t] += y;
        __syncthreads();
    }
    if (idx < NN) {
        int incl = sh[t] + g_blockoff[blockIdx.x];
        g_rowptr[idx + 1] = incl;
        g_cursor[idx] = incl - v;
    }
    if (idx == 0) g_rowptr[0] = 0;
}
__global__ void k_scatter_edges(const int* __restrict__ row, const int* __restrict__ col,
                                const float* __restrict__ w) {
    int e = blockIdx.x * blockDim.x + threadIdx.x;
    if (e < NE) {
        int pos = atomicAdd(&g_cursor[row[e]], 1);
        g_pcol[pos] = col[e];
        g_pw[pos]   = w[e];
    }
}

// ---------------- converters ----------------
__global__ void k_convert_x(const float* __restrict__ x) {
    int i = blockIdx.x * blockDim.x + threadIdx.x;
    if (i < NN * 128) {
        __half h, l;
        split1(x[i], h, l);
        g_ahi[i] = h;
        g_alo[i] = l;
    }
}
__global__ void k_convert_weights(const float* w0, const float* w1_, const float* w2_,
                                  const float* w3, const float* w4, const float* w5,
                                  const float* wdec) {
    int idx = blockIdx.x * blockDim.x + threadIdx.x;
    if (idx >= W_TOTAL) return;
    float v;
    if (idx < W_NODE_ELEMS) {
        int m = idx >> 14;
        int e = idx & 16383;
        int n = e >> 7, k = e & 127;
        const float* W = (m == 0) ? w0 : (m == 1) ? w1_ : (m == 2) ? w2_
                       : (m == 3) ? w3 : (m == 4) ? w4 : w5;
        v = W[k * 128 + n];
    } else {
        int e = idx - W_NODE_ELEMS;
        int n = e >> 8, k = e & 255;
        v = wdec[k * 128 + n];
    }
    __half h, l;
    split1(v, h, l);
    g_whi[idx] = h;
    g_wlo[idx] = l;
}

// ---------------- neighbor aggregation: out = maybe_relu(selfb + sum w*support) ----------------
// writes fp16 hi/lo (next GEMM / decoder input); optionally fp32 (z output)
__global__ __launch_bounds__(128) void k_aggregate(float* __restrict__ outf, int relu, int writef) {
    int node = blockIdx.x;
    int f = threadIdx.x;
    size_t idx = (size_t)node * 128 + f;
    float acc0 = g_selfb[idx];
    float acc1 = 0.f;
    int s = g_rowptr[node];
    int e = g_rowptr[node + 1];
    int i = s;
    for (; i + 1 < e; i += 2) {
        int c0 = g_pcol[i], c1 = g_pcol[i + 1];
        float w0 = g_pw[i], w1 = g_pw[i + 1];
        acc0 += w0 * g_support[(size_t)c0 * 128 + f];
        acc1 += w1 * g_support[(size_t)c1 * 128 + f];
    }
    if (i < e) acc0 += g_pw[i] * g_support[(size_t)g_pcol[i] * 128 + f];
    float acc = acc0 + acc1;
    if (relu) acc = fmaxf(acc, 0.f);
    if (writef) outf[idx] = acc;
    __half h, l;
    split1(acc, h, l);
    g_ahi[idx] = h;
    g_alo[idx] = l;
}

// ---------------- persistent node GEMM: M=64 tiles, double-buffered A ----------------
// smem layout (bytes):
#define NO_BIAS  0                               // 512
#define NO_WSHI  1024
#define NO_WSLO  (NO_WSHI + 128 * PK128 * 2)     // +34816
#define NO_WNHI  (NO_WSLO + 128 * PK128 * 2)
#define NO_WNLO  (NO_WNHI + 128 * PK128 * 2)
#define NO_A0    (NO_WNLO + 128 * PK128 * 2)     // stage0: hi then lo
#define NO_ASTG  (64 * PK128 * 2)                // 17408 per hi or lo
#define NO_A1    (NO_A0 + 2 * NO_ASTG)
#define NO_SMEM  (NO_A1 + 2 * NO_ASTG)           // 209920

#define NODE_TILES ((NN + 63) / 64)              // 1563

__device__ __forceinline__ void issue_node_tile(int rowBase, uint32_t smHi, uint32_t smLo, int tid) {
    int r = tid >> 2;               // 0..63
    int u0 = (tid & 3) * 4;         // units 0..15
    int gr = rowBase + r;
    unsigned sz = (gr < NN) ? 16u : 0u;
    int grc = gr < NN ? gr : NN - 1;
    const char* srcH = (const char*)g_ahi + (size_t)grc * 256;
    const char* srcL = (const char*)g_alo + (size_t)grc * 256;
    uint32_t drow = (uint32_t)r * (PK128 * 2);
#pragma unroll
    for (int q = 0; q < 4; q++) {
        uint32_t o = (u0 + q) * 16;
        cp16(smHi + drow + o, srcH + o, sz);
        cp16(smLo + drow + o, srcL + o, sz);
    }
}

__global__ __launch_bounds__(256, 1) void k_mm_node(
    int wsel, const float* __restrict__ bias,
    float* __restrict__ Cself, float* __restrict__ Csup)
{
    extern __shared__ char sm[];
    uint32_t sb = smem_u32(sm);
    int tid = threadIdx.x;
    int lane = tid & 31, wid = tid >> 5;
    int warpM = wid & 1, warpN = wid >> 1;       // 2 x 4 warps, warp tile 32x32

    if (tid < 128) ((float*)(sm + NO_BIAS))[tid] = bias[tid];
    // weights once
    {
        const uint4* whS = (const uint4*)(g_whi + (size_t)(2 * wsel) * 16384);
        const uint4* wlS = (const uint4*)(g_wlo + (size_t)(2 * wsel) * 16384);
        const uint4* whN = (const uint4*)(g_whi + (size_t)(2 * wsel + 1) * 16384);
        const uint4* wlN = (const uint4*)(g_wlo + (size_t)(2 * wsel + 1) * 16384);
        for (int idx = tid; idx < 2048; idx += 256) {
            int r = idx >> 4, u = idx & 15;
            uint32_t off = r * (PK128 * 2) + u * 16;
            *(uint4*)(sm + NO_WSHI + off) = whS[idx];
            *(uint4*)(sm + NO_WSLO + off) = wlS[idx];
            *(uint4*)(sm + NO_WNHI + off) = whN[idx];
            *(uint4*)(sm + NO_WNLO + off) = wlN[idx];
        }
    }

    uint32_t aStage[2] = { sb + NO_A0, sb + NO_A1 };
    const float* sbias = (const float*)(sm + NO_BIAS);

    // lane-invariant fragment address pieces
    uint32_t aRow = warpM * 32 + (lane & 15);
    uint32_t aColSel = (lane >> 4) * 8;
    uint32_t aOff0 = (aRow * PK128 + aColSel) * 2;
    uint32_t aOff1 = ((aRow + 16) * PK128 + aColSel) * 2;
    uint32_t bRow = warpN * 32 + (lane & 7);
    uint32_t bColSel = ((lane >> 3) & 1) * 8;
    uint32_t bOffBase = (bRow * PK128 + bColSel) * 2;

    int t = blockIdx.x;
    int buf = 0;
    if (t < NODE_TILES) { issue_node_tile(t * 64, aStage[0], aStage[0] + NO_ASTG, tid); CP_COMMIT(); }
    __syncthreads();   // weights visible

    while (t < NODE_TILES) {
        int tn = t + gridDim.x;
        if (tn < NODE_TILES) {
            issue_node_tile(tn * 64, aStage[buf ^ 1], aStage[buf ^ 1] + NO_ASTG, tid);
            CP_COMMIT();
            CP_WAIT1();
        } else {
            CP_WAIT0();
        }
        __syncthreads();

        float accS[2][4][4], accN[2][4][4];
#pragma unroll
        for (int mt = 0; mt < 2; mt++)
#pragma unroll
            for (int nt = 0; nt < 4; nt++)
#pragma unroll
                for (int q = 0; q < 4; q++) { accS[mt][nt][q] = 0.f; accN[mt][nt][q] = 0.f; }

        uint32_t asH = aStage[buf], asL = aStage[buf] + NO_ASTG;
#pragma unroll
        for (int ks = 0; ks < 8; ks++) {
            uint32_t kadd = ks * 32;
            uint32_t aH[2][4], aL[2][4];
            ldsm_x4(aH[0][0], aH[0][1], aH[0][2], aH[0][3], asH + aOff0 + kadd);
            ldsm_x4(aH[1][0], aH[1][1], aH[1][2], aH[1][3], asH + aOff1 + kadd);
            ldsm_x4(aL[0][0], aL[0][1], aL[0][2], aL[0][3], asL + aOff0 + kadd);
            ldsm_x4(aL[1][0], aL[1][1], aL[1][2], aL[1][3], asL + aOff1 + kadd);
#pragma unroll
            for (int nt = 0; nt < 4; nt++) {
                uint32_t bo = bOffBase + nt * 8 * PK128 * 2 + kadd;
                uint32_t bHs[2], bLs[2], bHn[2], bLn[2];
                ldsm_x2(bHs[0], bHs[1], sb + NO_WSHI + bo);
                ldsm_x2(bLs[0], bLs[1], sb + NO_WSLO + bo);
                ldsm_x2(bHn[0], bHn[1], sb + NO_WNHI + bo);
                ldsm_x2(bLn[0], bLn[1], sb + NO_WNLO + bo);
#pragma unroll
                for (int mt = 0; mt < 2; mt++) {
                    mma16816(accS[mt][nt], aH[mt], bHs);
                    mma16816(accS[mt][nt], aH[mt], bLs);
                    mma16816(accS[mt][nt], aL[mt], bHs);
                    mma16816(accN[mt][nt], aH[mt], bHn);
                    mma16816(accN[mt][nt], aH[mt], bLn);
                    mma16816(accN[mt][nt], aL[mt], bHn);
                }
            }
        }

        int base = t * 64;
#pragma unroll
        for (int mt = 0; mt < 2; mt++) {
            int r0 = base + warpM * 32 + mt * 16 + (lane >> 2);
#pragma unroll
            for (int nt = 0; nt < 4; nt++) {
                int c = warpN * 32 + nt * 8 + (lane & 3) * 2;
                if (r0 < NN) {
                    *(float2*)(Cself + (size_t)r0 * 128 + c) =
                        make_float2(accS[mt][nt][0] + sbias[c], accS[mt][nt][1] + sbias[c + 1]);
                    *(float2*)(Csup + (size_t)r0 * 128 + c) =
                        make_float2(accN[mt][nt][0], accN[mt][nt][1]);
                }
                if (r0 + 8 < NN) {
                    *(float2*)(Cself + (size_t)(r0 + 8) * 128 + c) =
                        make_float2(accS[mt][nt][2] + sbias[c], accS[mt][nt][3] + sbias[c + 1]);
                    *(float2*)(Csup + (size_t)(r0 + 8) * 128 + c) =
                        make_float2(accN[mt][nt][2], accN[mt][nt][3]);
                }
            }
        }
        __syncthreads();
        buf ^= 1;
        t = tn;
    }
}

// ---------------- persistent fused decoder: 64-pair tiles, (tile,chunk) pipeline ----------------
#define DO_B1   0       // 512
#define DO_W2   512     // 512
#define DO_RED  1024    // 64*16*4 = 4096
#define DO_W1HI 5120
#define DO_W1LO (DO_W1HI + 128 * PK256 * 2)      // +67584
#define DO_A0   (DO_W1LO + 128 * PK256 * 2)
#define DO_ASTG (64 * PK128 * 2)                 // 17408
#define DO_A1   (DO_A0 + 2 * DO_ASTG)
#define DO_SMEM (DO_A1 + 2 * DO_ASTG)            // 209920

#define DEC_TILES ((NP + 63) / 64)               // 7813

__device__ __forceinline__ void issue_dec_stage(int tile, int chunk,
                                                const int* __restrict__ xidx,
                                                const int* __restrict__ yidx,
                                                uint32_t smHi, uint32_t smLo, int tid) {
    int r = tid >> 2;
    int u0 = (tid & 3) * 4;
    int pp = tile * 64 + r;
    const int* idx = chunk ? yidx : xidx;
    int node = (pp < NP) ? idx[pp] : 0;
    const char* srcH = (const char*)g_ahi + (size_t)node * 256;
    const char* srcL = (const char*)g_alo + (size_t)node * 256;
    uint32_t drow = (uint32_t)r * (PK128 * 2);
#pragma unroll
    for (int q = 0; q < 4; q++) {
        uint32_t o = (u0 + q) * 16;
        cp16(smHi + drow + o, srcH + o, 16u);
        cp16(smLo + drow + o, srcL + o, 16u);
    }
}

__global__ __launch_bounds__(256, 1) void k_mm_decoder(
    const int* __restrict__ xidx, const int* __restrict__ yidx,
    const float* __restrict__ b1, const float* __restrict__ w2, const float* __restrict__ b2,
    float* __restrict__ p)
{
    extern __shared__ char sm[];
    uint32_t sb = smem_u32(sm);
    int tid = threadIdx.x;
    int lane = tid & 31, wid = tid >> 5;
    int warpM = wid & 1, warpN = wid >> 1;

    if (tid < 128) {
        ((float*)(sm + DO_B1))[tid] = b1[tid];
        ((float*)(sm + DO_W2))[tid] = w2[tid];
    }
    {
        const uint4* wh = (const uint4*)(g_whi + W_NODE_ELEMS);
        const uint4* wl = (const uint4*)(g_wlo + W_NODE_ELEMS);
        for (int idx = tid; idx < 4096; idx += 256) {
            int r = idx >> 5, u = idx & 31;
            uint32_t off = r * (PK256 * 2) + u * 16;
            *(uint4*)(sm + DO_W1HI + off) = wh[idx];
            *(uint4*)(sm + DO_W1LO + off) = wl[idx];
        }
    }

    uint32_t aStage[2] = { sb + DO_A0, sb + DO_A1 };
    const float* sb1 = (const float*)(sm + DO_B1);
    const float* sw2 = (const float*)(sm + DO_W2);
    float* red = (float*)(sm + DO_RED);
    float b2v = __ldg(b2);

    uint32_t aRow = warpM * 32 + (lane & 15);
    uint32_t aColSel = (lane >> 4) * 8;
    uint32_t aOff0 = (aRow * PK128 + aColSel) * 2;
    uint32_t aOff1 = ((aRow + 16) * PK128 + aColSel) * 2;
    uint32_t bRow = warpN * 32 + (lane & 7);
    uint32_t bColSel = ((lane >> 3) & 1) * 8;
    uint32_t bOffBase = (bRow * PK256 + bColSel) * 2;

    float acc[2][4][4];
#pragma unroll
    for (int mt = 0; mt < 2; mt++)
#pragma unroll
        for (int nt = 0; nt < 4; nt++)
#pragma unroll
            for (int q = 0; q < 4; q++) acc[mt][nt][q] = 0.f;

    int t = blockIdx.x;
    int c = 0;
    int buf = 0;
    if (t < DEC_TILES) {
        issue_dec_stage(t, 0, xidx, yidx, aStage[0], aStage[0] + DO_ASTG, tid);
        CP_COMMIT();
    }
    __syncthreads();   // W1 visible

    while (t < DEC_TILES) {
        int nt_ = t, nc = c + 1;
        if (nc == 2) { nc = 0; nt_ = t + gridDim.x; }
        if (nt_ < DEC_TILES) {
            issue_dec_stage(nt_, nc, xidx, yidx, aStage[buf ^ 1], aStage[buf ^ 1] + DO_ASTG, tid);
            CP_COMMIT();
            CP_WAIT1();
        } else {
            CP_WAIT0();
        }
        __syncthreads();

        uint32_t asH = aStage[buf], asL = aStage[buf] + DO_ASTG;
        uint32_t kChunk = c * 256;   // byte offset into W1 K dim
#pragma unroll
        for (int ks = 0; ks < 8; ks++) {
            uint32_t kadd = ks * 32;
            uint32_t aH[2][4], aL[2][4];
            ldsm_x4(aH[0][0], aH[0][1], aH[0][2], aH[0][3], asH + aOff0 + kadd);
            ldsm_x4(aH[1][0], aH[1][1], aH[1][2], aH[1][3], asH + aOff1 + kadd);
            ldsm_x4(aL[0][0], aL[0][1], aL[0][2], aL[0][3], asL + aOff0 + kadd);
            ldsm_x4(aL[1][0], aL[1][1], aL[1][2], aL[1][3], asL + aOff1 + kadd);
#pragma unroll
            for (int nt2 = 0; nt2 < 4; nt2++) {
                uint32_t bo = bOffBase + nt2 * 8 * PK256 * 2 + kChunk + kadd;
                uint32_t bH[2], bL[2];
                ldsm_x2(bH[0], bH[1], sb + DO_W1HI + bo);
                ldsm_x2(bL[0], bL[1], sb + DO_W1LO + bo);
#pragma unroll
                for (int mt = 0; mt < 2; mt++) {
                    mma16816(acc[mt][nt2], aH[mt], bH);
                    mma16816(acc[mt][nt2], aH[mt], bL);
                    mma16816(acc[mt][nt2], aL[mt], bH);
                }
            }
        }

        if (c == 1) {
            // epilogue: relu + fc2 reduction + sigmoid
#pragma unroll
            for (int mt = 0; mt < 2; mt++) {
                int rl = warpM * 32 + mt * 16 + (lane >> 2);
                float p0 = 0.f, p1 = 0.f;
#pragma unroll
                for (int nt2 = 0; nt2 < 4; nt2++) {
                    int cc = warpN * 32 + nt2 * 8 + (lane & 3) * 2;
                    float h00 = fmaxf(acc[mt][nt2][0] + sb1[cc], 0.f);
                    float h01 = fmaxf(acc[mt][nt2][1] + sb1[cc + 1], 0.f);
                    float h10 = fmaxf(acc[mt][nt2][2] + sb1[cc], 0.f);
                    float h11 = fmaxf(acc[mt][nt2][3] + sb1[cc + 1], 0.f);
                    p0 += h00 * sw2[cc] + h01 * sw2[cc + 1];
                    p1 += h10 * sw2[cc] + h11 * sw2[cc + 1];
                }
                red[rl * 16 + warpN * 4 + (lane & 3)] = p0;
                red[(rl + 8) * 16 + warpN * 4 + (lane & 3)] = p1;
            }
            __syncthreads();
            if (tid < 64) {
                float s = 0.f;
#pragma unroll
                for (int j = 0; j < 16; j++) s += red[tid * 16 + j];
                s += b2v;
                float pv = 1.f / (1.f + expf(-s));
                int pp = t * 64 + tid;
                if (pp < NP) p[pp] = pv;
            }
            // reset acc
#pragma unroll
            for (int mt = 0; mt < 2; mt++)
#pragma unroll
                for (int nt2 = 0; nt2 < 4; nt2++)
#pragma unroll
                    for (int q = 0; q < 4; q++) acc[mt][nt2][q] = 0.f;
        }
        __syncthreads();
        buf ^= 1;
        c = nc;
        t = nt_;
    }
}

// ---------------- launch ----------------
extern "C" void kernel_launch(void* const* d_in, const int* in_sizes, int n_in,
                              void* d_out, int out_size) {
    const float* x     = (const float*)d_in[0];
    const int*   erow  = (const int*)  d_in[1];
    const int*   ecol  = (const int*)  d_in[2];
    const float* ew    = (const float*)d_in[3];
    const int*   xidx  = (const int*)  d_in[4];
    const int*   yidx  = (const int*)  d_in[5];
    const float* ws[3] = { (const float*)d_in[6],  (const float*)d_in[9],  (const float*)d_in[12] };
    const float* wn[3] = { (const float*)d_in[7],  (const float*)d_in[10], (const float*)d_in[13] };
    const float* bb[3] = { (const float*)d_in[8],  (const float*)d_in[11], (const float*)d_in[14] };
    const float* dw1 = (const float*)d_in[15];
    const float* db1 = (const float*)d_in[16];
    const float* dw2 = (const float*)d_in[17];
    const float* db2 = (const float*)d_in[18];

    float* out = (float*)d_out;
    float* p_out = out;            // [NP]
    float* z_out = out + NP;       // [NN*128]

    void* ptr;
    cudaGetSymbolAddress(&ptr, g_selfb);   float* selfb_buf = (float*)ptr;
    cudaGetSymbolAddress(&ptr, g_support); float* sup_buf   = (float*)ptr;

    int nsm = 148;
    cudaDeviceGetAttribute(&nsm, cudaDevAttrMultiProcessorCount, 0);

    cudaFuncSetAttribute(k_mm_node, cudaFuncAttributeMaxDynamicSharedMemorySize, NO_SMEM);
    cudaFuncSetAttribute(k_mm_decoder, cudaFuncAttributeMaxDynamicSharedMemorySize, DO_SMEM);

    // CSR build + conversions
    k_zero_deg<<<(NN + 255) / 256, 256>>>();
    k_count_deg<<<(NE + 255) / 256, 256>>>(erow);
    k_scan_part<<<NBLK, SCAN_B>>>();
    k_scan_mid<<<1, 128>>>();
    k_scan_final<<<NBLK, SCAN_B>>>();
    k_scatter_edges<<<(NE + 255) / 256, 256>>>(erow, ecol, ew);
    k_convert_weights<<<(W_TOTAL + 255) / 256, 256>>>(ws[0], wn[0], ws[1], wn[1], ws[2], wn[2], dw1);
    k_convert_x<<<(NN * 128 + 255) / 256, 256>>>(x);

    // layer 1
    k_mm_node<<<nsm, 256, NO_SMEM>>>(0, bb[0], selfb_buf, sup_buf);
    k_aggregate<<<NN, 128>>>(nullptr, 1, 0);
    // layer 2
    k_mm_node<<<nsm, 256, NO_SMEM>>>(1, bb[1], selfb_buf, sup_buf);
    k_aggregate<<<NN, 128>>>(nullptr, 1, 0);
    // layer 3 -> z (fp32) + hi/lo for decoder
    k_mm_node<<<nsm, 256, NO_SMEM>>>(2, bb[2], selfb_buf, sup_buf);
    k_aggregate<<<NN, 128>>>(z_out, 0, 1);

    // decoder
    k_mm_decoder<<<nsm, 256, DO_SMEM>>>(xidx, yidx, db1, dw2, db2, p_out);
}

// round 6
// speedup vs baseline: 2.0678x; 1.1331x over previous
#include <cuda_runtime.h>
#include <cuda_fp16.h>
#include <math.h>
#include <stdint.h>

#define NN 100000
#define NE 1600000
#define NP 500000
#define SCAN_B 1024
#define NBLK ((NN + SCAN_B - 1) / SCAN_B)   // 98

// ---------------- static device scratch ----------------
__device__ float  g_selfb[(size_t)NN * 128];
__device__ __half g_suph[(size_t)NN * 128];   // h @ Wn in fp16 (gathered operand)
__device__ __half g_ahi[(size_t)NN * 128];    // activation hi (GEMM A input)
__device__ __half g_alo[(size_t)NN * 128];    // activation lo
__device__ int   g_rowptr[NN + 1];
__device__ int   g_cursor[NN];
__device__ int   g_partial[NBLK];
__device__ int   g_blockoff[NBLK];
__device__ int   g_pcol[NE];
__device__ float g_pw[NE];
// converted weights: 6 node mats [n][k] 128x128 + W1 [n][k] 128x256, fp16 hi/lo
#define W_NODE_ELEMS (6 * 16384)
#define W_TOTAL (W_NODE_ELEMS + 32768)
__device__ __half g_whi[W_TOTAL];
__device__ __half g_wlo[W_TOTAL];

// padded row strides in halfs
#define PK128 136
#define PK256 264

// ---------------- helpers ----------------
__device__ __forceinline__ uint32_t smem_u32(const void* p) {
    uint32_t a;
    asm("{ .reg .u64 t; cvta.to.shared.u64 t, %1; cvt.u32.u64 %0, t; }" : "=r"(a) : "l"(p));
    return a;
}
__device__ __forceinline__ void ldsm_x4(uint32_t& r0, uint32_t& r1, uint32_t& r2, uint32_t& r3,
                                        uint32_t addr) {
    asm volatile("ldmatrix.sync.aligned.m8n8.x4.shared.b16 {%0,%1,%2,%3}, [%4];"
                 : "=r"(r0), "=r"(r1), "=r"(r2), "=r"(r3) : "r"(addr));
}
__device__ __forceinline__ void ldsm_x2(uint32_t& r0, uint32_t& r1, uint32_t addr) {
    asm volatile("ldmatrix.sync.aligned.m8n8.x2.shared.b16 {%0,%1}, [%2];"
                 : "=r"(r0), "=r"(r1) : "r"(addr));
}
__device__ __forceinline__ void mma16816(float* c, const uint32_t* a, const uint32_t* b) {
    asm volatile("mma.sync.aligned.m16n8k16.row.col.f32.f16.f16.f32 "
                 "{%0,%1,%2,%3}, {%4,%5,%6,%7}, {%8,%9}, {%0,%1,%2,%3};"
                 : "+f"(c[0]), "+f"(c[1]), "+f"(c[2]), "+f"(c[3])
                 : "r"(a[0]), "r"(a[1]), "r"(a[2]), "r"(a[3]), "r"(b[0]), "r"(b[1]));
}
__device__ __forceinline__ void cp16(uint32_t dst, const void* src, unsigned sz) {
    asm volatile("cp.async.cg.shared.global [%0], [%1], 16, %2;"
                 :: "r"(dst), "l"(src), "r"(sz) : "memory");
}
#define CP_COMMIT() asm volatile("cp.async.commit_group;" ::: "memory")
#define CP_WAIT1()  asm volatile("cp.async.wait_group 1;" ::: "memory")
#define CP_WAIT0()  asm volatile("cp.async.wait_group 0;" ::: "memory")

__device__ __forceinline__ void split1(float v, __half& h, __half& l) {
    h = __float2half_rn(v);
    l = __float2half_rn(v - __half2float(h));
}

// ---------------- CSR build ----------------
__global__ void k_zero_deg() {
    int i = blockIdx.x * blockDim.x + threadIdx.x;
    if (i < NN) g_cursor[i] = 0;
}
__global__ void k_count_deg(const int* __restrict__ row) {
    int e = blockIdx.x * blockDim.x + threadIdx.x;
    if (e < NE) atomicAdd(&g_cursor[row[e]], 1);
}
__global__ __launch_bounds__(SCAN_B) void k_scan_part() {
    __shared__ int sh[SCAN_B / 32];
    int t = threadIdx.x;
    int idx = blockIdx.x * SCAN_B + t;
    int v = (idx < NN) ? g_cursor[idx] : 0;
#pragma unroll
    for (int off = 16; off > 0; off >>= 1) v += __shfl_down_sync(0xffffffffu, v, off);
    if ((t & 31) == 0) sh[t >> 5] = v;
    __syncthreads();
    if (t < 32) {
        int s = (t < SCAN_B / 32) ? sh[t] : 0;
#pragma unroll
        for (int off = 16; off > 0; off >>= 1) s += __shfl_down_sync(0xffffffffu, s, off);
        if (t == 0) g_partial[blockIdx.x] = s;
    }
}
__global__ __launch_bounds__(128) void k_scan_mid() {
    __shared__ int sh[128];
    int t = threadIdx.x;
    int v = (t < NBLK) ? g_partial[t] : 0;
    sh[t] = v;
    __syncthreads();
#pragma unroll
    for (int off = 1; off < 128; off <<= 1) {
        int y = (t >= off) ? sh[t - off] : 0;
        __syncthreads();
        sh[t] += y;
        __syncthreads();
    }
    if (t < NBLK) g_blockoff[t] = sh[t] - v;
}
__global__ __launch_bounds__(SCAN_B) void k_scan_final() {
    __shared__ int sh[SCAN_B];
    int t = threadIdx.x;
    int idx = blockIdx.x * SCAN_B + t;
    int v = (idx < NN) ? g_cursor[idx] : 0;
    sh[t] = v;
    __syncthreads();
#pragma unroll
    for (int off = 1; off < SCAN_B; off <<= 1) {
        int y = (t >= off) ? sh[t - off] : 0;
        __syncthreads();
        sh[t] += y;
        __syncthreads();
    }
    if (idx < NN) {
        int incl = sh[t] + g_blockoff[blockIdx.x];
        g_rowptr[idx + 1] = incl;
        g_cursor[idx] = incl - v;
    }
    if (idx == 0) g_rowptr[0] = 0;
}
__global__ void k_scatter_edges(const int* __restrict__ row, const int* __restrict__ col,
                                const float* __restrict__ w) {
    int e = blockIdx.x * blockDim.x + threadIdx.x;
    if (e < NE) {
        int pos = atomicAdd(&g_cursor[row[e]], 1);
        g_pcol[pos] = col[e];
        g_pw[pos]   = w[e];
    }
}

// ---------------- converters ----------------
__global__ void k_convert_x(const float* __restrict__ x) {
    int i = blockIdx.x * blockDim.x + threadIdx.x;
    if (i < NN * 128) {
        __half h, l;
        split1(x[i], h, l);
        g_ahi[i] = h;
        g_alo[i] = l;
    }
}
__global__ void k_convert_weights(const float* w0, const float* w1_, const float* w2_,
                                  const float* w3, const float* w4, const float* w5,
                                  const float* wdec) {
    int idx = blockIdx.x * blockDim.x + threadIdx.x;
    if (idx >= W_TOTAL) return;
    float v;
    if (idx < W_NODE_ELEMS) {
        int m = idx >> 14;
        int e = idx & 16383;
        int n = e >> 7, k = e & 127;
        const float* W = (m == 0) ? w0 : (m == 1) ? w1_ : (m == 2) ? w2_
                       : (m == 3) ? w3 : (m == 4) ? w4 : w5;
        v = W[k * 128 + n];
    } else {
        int e = idx - W_NODE_ELEMS;
        int n = e >> 8, k = e & 255;
        v = wdec[k * 128 + n];
    }
    __half h, l;
    split1(v, h, l);
    g_whi[idx] = h;
    g_wlo[idx] = l;
}

// ---------------- neighbor aggregation: out = maybe_relu(selfb + sum w*support_fp16) ----------------
__global__ __launch_bounds__(128) void k_aggregate(float* __restrict__ outf, int relu, int writef) {
    int node = blockIdx.x;
    int f = threadIdx.x;
    size_t idx = (size_t)node * 128 + f;
    float acc0 = g_selfb[idx];
    float acc1 = 0.f;
    int s = g_rowptr[node];
    int e = g_rowptr[node + 1];
    int i = s;
    for (; i + 1 < e; i += 2) {
        int c0 = g_pcol[i], c1 = g_pcol[i + 1];
        float w0 = g_pw[i], w1 = g_pw[i + 1];
        acc0 += w0 * __half2float(g_suph[(size_t)c0 * 128 + f]);
        acc1 += w1 * __half2float(g_suph[(size_t)c1 * 128 + f]);
    }
    if (i < e) acc0 += g_pw[i] * __half2float(g_suph[(size_t)g_pcol[i] * 128 + f]);
    float acc = acc0 + acc1;
    if (relu) acc = fmaxf(acc, 0.f);
    if (writef) outf[idx] = acc;
    __half h, l;
    split1(acc, h, l);
    g_ahi[idx] = h;
    g_alo[idx] = l;
}

// ---------------- persistent node GEMM: M=64 tiles, double-buffered A ----------------
#define NO_BIAS  0                               // 512
#define NO_WSHI  1024
#define NO_WSLO  (NO_WSHI + 128 * PK128 * 2)     // +34816
#define NO_WNHI  (NO_WSLO + 128 * PK128 * 2)
#define NO_WNLO  (NO_WNHI + 128 * PK128 * 2)
#define NO_A0    (NO_WNLO + 128 * PK128 * 2)     // stage0: hi then lo
#define NO_ASTG  (64 * PK128 * 2)                // 17408 per hi or lo
#define NO_A1    (NO_A0 + 2 * NO_ASTG)
#define NO_SMEM  (NO_A1 + 2 * NO_ASTG)           // 209920

#define NODE_TILES ((NN + 63) / 64)              // 1563

__device__ __forceinline__ void issue_node_tile(int rowBase, uint32_t smHi, uint32_t smLo, int tid) {
    int r = tid >> 2;               // 0..63
    int u0 = (tid & 3) * 4;         // units 0..15
    int gr = rowBase + r;
    unsigned sz = (gr < NN) ? 16u : 0u;
    int grc = gr < NN ? gr : NN - 1;
    const char* srcH = (const char*)g_ahi + (size_t)grc * 256;
    const char* srcL = (const char*)g_alo + (size_t)grc * 256;
    uint32_t drow = (uint32_t)r * (PK128 * 2);
#pragma unroll
    for (int q = 0; q < 4; q++) {
        uint32_t o = (u0 + q) * 16;
        cp16(smHi + drow + o, srcH + o, sz);
        cp16(smLo + drow + o, srcL + o, sz);
    }
}

__global__ __launch_bounds__(256, 1) void k_mm_node(
    int wsel, const float* __restrict__ bias, float* __restrict__ Cself)
{
    extern __shared__ char sm[];
    uint32_t sb = smem_u32(sm);
    int tid = threadIdx.x;
    int lane = tid & 31, wid = tid >> 5;
    int warpM = wid & 1, warpN = wid >> 1;       // 2 x 4 warps, warp tile 32x32

    if (tid < 128) ((float*)(sm + NO_BIAS))[tid] = bias[tid];
    // weights once
    {
        const uint4* whS = (const uint4*)(g_whi + (size_t)(2 * wsel) * 16384);
        const uint4* wlS = (const uint4*)(g_wlo + (size_t)(2 * wsel) * 16384);
        const uint4* whN = (const uint4*)(g_whi + (size_t)(2 * wsel + 1) * 16384);
        const uint4* wlN = (const uint4*)(g_wlo + (size_t)(2 * wsel + 1) * 16384);
        for (int idx = tid; idx < 2048; idx += 256) {
            int r = idx >> 4, u = idx & 15;
            uint32_t off = r * (PK128 * 2) + u * 16;
            *(uint4*)(sm + NO_WSHI + off) = whS[idx];
            *(uint4*)(sm + NO_WSLO + off) = wlS[idx];
            *(uint4*)(sm + NO_WNHI + off) = whN[idx];
            *(uint4*)(sm + NO_WNLO + off) = wlN[idx];
        }
    }

    uint32_t aStage[2] = { sb + NO_A0, sb + NO_A1 };
    const float* sbias = (const float*)(sm + NO_BIAS);

    uint32_t aRow = warpM * 32 + (lane & 15);
    uint32_t aColSel = (lane >> 4) * 8;
    uint32_t aOff0 = (aRow * PK128 + aColSel) * 2;
    uint32_t aOff1 = ((aRow + 16) * PK128 + aColSel) * 2;
    uint32_t bRow = warpN * 32 + (lane & 7);
    uint32_t bColSel = ((lane >> 3) & 1) * 8;
    uint32_t bOffBase = (bRow * PK128 + bColSel) * 2;

    int t = blockIdx.x;
    int buf = 0;
    if (t < NODE_TILES) { issue_node_tile(t * 64, aStage[0], aStage[0] + NO_ASTG, tid); CP_COMMIT(); }
    __syncthreads();   // weights visible

    while (t < NODE_TILES) {
        int tn = t + gridDim.x;
        if (tn < NODE_TILES) {
            issue_node_tile(tn * 64, aStage[buf ^ 1], aStage[buf ^ 1] + NO_ASTG, tid);
            CP_COMMIT();
            CP_WAIT1();
        } else {
            CP_WAIT0();
        }
        __syncthreads();

        float accS[2][4][4], accN[2][4][4];
#pragma unroll
        for (int mt = 0; mt < 2; mt++)
#pragma unroll
            for (int nt = 0; nt < 4; nt++)
#pragma unroll
                for (int q = 0; q < 4; q++) { accS[mt][nt][q] = 0.f; accN[mt][nt][q] = 0.f; }

        uint32_t asH = aStage[buf], asL = aStage[buf] + NO_ASTG;
#pragma unroll
        for (int ks = 0; ks < 8; ks++) {
            uint32_t kadd = ks * 32;
            uint32_t aH[2][4], aL[2][4];
            ldsm_x4(aH[0][0], aH[0][1], aH[0][2], aH[0][3], asH + aOff0 + kadd);
            ldsm_x4(aH[1][0], aH[1][1], aH[1][2], aH[1][3], asH + aOff1 + kadd);
            ldsm_x4(aL[0][0], aL[0][1], aL[0][2], aL[0][3], asL + aOff0 + kadd);
            ldsm_x4(aL[1][0], aL[1][1], aL[1][2], aL[1][3], asL + aOff1 + kadd);
#pragma unroll
            for (int nt = 0; nt < 4; nt++) {
                uint32_t bo = bOffBase + nt * 8 * PK128 * 2 + kadd;
                uint32_t bHs[2], bLs[2], bHn[2], bLn[2];
                ldsm_x2(bHs[0], bHs[1], sb + NO_WSHI + bo);
                ldsm_x2(bLs[0], bLs[1], sb + NO_WSLO + bo);
                ldsm_x2(bHn[0], bHn[1], sb + NO_WNHI + bo);
                ldsm_x2(bLn[0], bLn[1], sb + NO_WNLO + bo);
#pragma unroll
                for (int mt = 0; mt < 2; mt++) {
                    mma16816(accS[mt][nt], aH[mt], bHs);
                    mma16816(accS[mt][nt], aH[mt], bLs);
                    mma16816(accS[mt][nt], aL[mt], bHs);
                    mma16816(accN[mt][nt], aH[mt], bHn);
                    mma16816(accN[mt][nt], aH[mt], bLn);
                    mma16816(accN[mt][nt], aL[mt], bHn);
                }
            }
        }

        int base = t * 64;
#pragma unroll
        for (int mt = 0; mt < 2; mt++) {
            int r0 = base + warpM * 32 + mt * 16 + (lane >> 2);
#pragma unroll
            for (int nt = 0; nt < 4; nt++) {
                int c = warpN * 32 + nt * 8 + (lane & 3) * 2;
                if (r0 < NN) {
                    *(float2*)(Cself + (size_t)r0 * 128 + c) =
                        make_float2(accS[mt][nt][0] + sbias[c], accS[mt][nt][1] + sbias[c + 1]);
                    *(__half2*)(&g_suph[(size_t)r0 * 128 + c]) =
                        __halves2half2(__float2half_rn(accN[mt][nt][0]),
                                       __float2half_rn(accN[mt][nt][1]));
                }
                if (r0 + 8 < NN) {
                    *(float2*)(Cself + (size_t)(r0 + 8) * 128 + c) =
                        make_float2(accS[mt][nt][2] + sbias[c], accS[mt][nt][3] + sbias[c + 1]);
                    *(__half2*)(&g_suph[(size_t)(r0 + 8) * 128 + c]) =
                        __halves2half2(__float2half_rn(accN[mt][nt][2]),
                                       __float2half_rn(accN[mt][nt][3]));
                }
            }
        }
        __syncthreads();
        buf ^= 1;
        t = tn;
    }
}

// ---------------- persistent fused decoder: 64-pair tiles, A hi-only, 2-term MMA ----------------
#define DO_B1   0       // 512
#define DO_W2   512     // 512
#define DO_RED  1024    // 64*16*4 = 4096
#define DO_W1HI 5120
#define DO_W1LO (DO_W1HI + 128 * PK256 * 2)      // +67584
#define DO_A0   (DO_W1LO + 128 * PK256 * 2)
#define DO_ASTG (64 * PK128 * 2)                 // 17408 (hi only)
#define DO_A1   (DO_A0 + DO_ASTG)
#define DO_SMEM (DO_A1 + DO_ASTG)                // 175104

#define DEC_TILES ((NP + 63) / 64)               // 7813

__device__ __forceinline__ void issue_dec_stage(int tile, int chunk,
                                                const int* __restrict__ xidx,
                                                const int* __restrict__ yidx,
                                                uint32_t smHi, int tid) {
    int r = tid >> 2;
    int u0 = (tid & 3) * 4;
    int pp = tile * 64 + r;
    const int* idx = chunk ? yidx : xidx;
    int node = (pp < NP) ? idx[pp] : 0;
    const char* srcH = (const char*)g_ahi + (size_t)node * 256;
    uint32_t drow = (uint32_t)r * (PK128 * 2);
#pragma unroll
    for (int q = 0; q < 4; q++) {
        uint32_t o = (u0 + q) * 16;
        cp16(smHi + drow + o, srcH + o, 16u);
    }
}

__global__ __launch_bounds__(256, 1) void k_mm_decoder(
    const int* __restrict__ xidx, const int* __restrict__ yidx,
    const float* __restrict__ b1, const float* __restrict__ w2, const float* __restrict__ b2,
    float* __restrict__ p)
{
    extern __shared__ char sm[];
    uint32_t sb = smem_u32(sm);
    int tid = threadIdx.x;
    int lane = tid & 31, wid = tid >> 5;
    int warpM = wid & 1, warpN = wid >> 1;

    if (tid < 128) {
        ((float*)(sm + DO_B1))[tid] = b1[tid];
        ((float*)(sm + DO_W2))[tid] = w2[tid];
    }
    {
        const uint4* wh = (const uint4*)(g_whi + W_NODE_ELEMS);
        const uint4* wl = (const uint4*)(g_wlo + W_NODE_ELEMS);
        for (int idx = tid; idx < 4096; idx += 256) {
            int r = idx >> 5, u = idx & 31;
            uint32_t off = r * (PK256 * 2) + u * 16;
            *(uint4*)(sm + DO_W1HI + off) = wh[idx];
            *(uint4*)(sm + DO_W1LO + off) = wl[idx];
        }
    }

    uint32_t aStage[2] = { sb + DO_A0, sb + DO_A1 };
    const float* sb1 = (const float*)(sm + DO_B1);
    const float* sw2 = (const float*)(sm + DO_W2);
    float* red = (float*)(sm + DO_RED);
    float b2v = __ldg(b2);

    uint32_t aRow = warpM * 32 + (lane & 15);
    uint32_t aColSel = (lane >> 4) * 8;
    uint32_t aOff0 = (aRow * PK128 + aColSel) * 2;
    uint32_t aOff1 = ((aRow + 16) * PK128 + aColSel) * 2;
    uint32_t bRow = warpN * 32 + (lane & 7);
    uint32_t bColSel = ((lane >> 3) & 1) * 8;
    uint32_t bOffBase = (bRow * PK256 + bColSel) * 2;

    float acc[2][4][4];
#pragma unroll
    for (int mt = 0; mt < 2; mt++)
#pragma unroll
        for (int nt = 0; nt < 4; nt++)
#pragma unroll
            for (int q = 0; q < 4; q++) acc[mt][nt][q] = 0.f;

    int t = blockIdx.x;
    int c = 0;
    int buf = 0;
    if (t < DEC_TILES) {
        issue_dec_stage(t, 0, xidx, yidx, aStage[0], tid);
        CP_COMMIT();
    }
    __syncthreads();   // W1 visible

    while (t < DEC_TILES) {
        int nt_ = t, nc = c + 1;
        if (nc == 2) { nc = 0; nt_ = t + gridDim.x; }
        if (nt_ < DEC_TILES) {
            issue_dec_stage(nt_, nc, xidx, yidx, aStage[buf ^ 1], tid);
            CP_COMMIT();
            CP_WAIT1();
        } else {
            CP_WAIT0();
        }
        __syncthreads();

        uint32_t asH = aStage[buf];
        uint32_t kChunk = c * 256;   // byte offset into W1 K dim
#pragma unroll
        for (int ks = 0; ks < 8; ks++) {
            uint32_t kadd = ks * 32;
            uint32_t aH[2][4];
            ldsm_x4(aH[0][0], aH[0][1], aH[0][2], aH[0][3], asH + aOff0 + kadd);
            ldsm_x4(aH[1][0], aH[1][1], aH[1][2], aH[1][3], asH + aOff1 + kadd);
#pragma unroll
            for (int nt2 = 0; nt2 < 4; nt2++) {
                uint32_t bo = bOffBase + nt2 * 8 * PK256 * 2 + kChunk + kadd;
                uint32_t bH[2], bL[2];
                ldsm_x2(bH[0], bH[1], sb + DO_W1HI + bo);
                ldsm_x2(bL[0], bL[1], sb + DO_W1LO + bo);
#pragma unroll
                for (int mt = 0; mt < 2; mt++) {
                    mma16816(acc[mt][nt2], aH[mt], bH);
                    mma16816(acc[mt][nt2], aH[mt], bL);
                }
            }
        }

        if (c == 1) {
            // epilogue: relu + fc2 reduction + sigmoid
#pragma unroll
            for (int mt = 0; mt < 2; mt++) {
                int rl = warpM * 32 + mt * 16 + (lane >> 2);
                float p0 = 0.f, p1 = 0.f;
#pragma unroll
                for (int nt2 = 0; nt2 < 4; nt2++) {
                    int cc = warpN * 32 + nt2 * 8 + (lane & 3) * 2;
                    float h00 = fmaxf(acc[mt][nt2][0] + sb1[cc], 0.f);
                    float h01 = fmaxf(acc[mt][nt2][1] + sb1[cc + 1], 0.f);
                    float h10 = fmaxf(acc[mt][nt2][2] + sb1[cc], 0.f);
                    float h11 = fmaxf(acc[mt][nt2][3] + sb1[cc + 1], 0.f);
                    p0 += h00 * sw2[cc] + h01 * sw2[cc + 1];
                    p1 += h10 * sw2[cc] + h11 * sw2[cc + 1];
                }
                red[rl * 16 + warpN * 4 + (lane & 3)] = p0;
                red[(rl + 8) * 16 + warpN * 4 + (lane & 3)] = p1;
            }
            __syncthreads();
            if (tid < 64) {
                float s = 0.f;
#pragma unroll
                for (int j = 0; j < 16; j++) s += red[tid * 16 + j];
                s += b2v;
                float pv = 1.f / (1.f + expf(-s));
                int pp = t * 64 + tid;
                if (pp < NP) p[pp] = pv;
            }
#pragma unroll
            for (int mt = 0; mt < 2; mt++)
#pragma unroll
                for (int nt2 = 0; nt2 < 4; nt2++)
#pragma unroll
                    for (int q = 0; q < 4; q++) acc[mt][nt2][q] = 0.f;
        }
        __syncthreads();
        buf ^= 1;
        c = nc;
        t = nt_;
    }
}

// ---------------- launch ----------------
extern "C" void kernel_launch(void* const* d_in, const int* in_sizes, int n_in,
                              void* d_out, int out_size) {
    const float* x     = (const float*)d_in[0];
    const int*   erow  = (const int*)  d_in[1];
    const int*   ecol  = (const int*)  d_in[2];
    const float* ew    = (const float*)d_in[3];
    const int*   xidx  = (const int*)  d_in[4];
    const int*   yidx  = (const int*)  d_in[5];
    const float* ws[3] = { (const float*)d_in[6],  (const float*)d_in[9],  (const float*)d_in[12] };
    const float* wn[3] = { (const float*)d_in[7],  (const float*)d_in[10], (const float*)d_in[13] };
    const float* bb[3] = { (const float*)d_in[8],  (const float*)d_in[11], (const float*)d_in[14] };
    const float* dw1 = (const float*)d_in[15];
    const float* db1 = (const float*)d_in[16];
    const float* dw2 = (const float*)d_in[17];
    const float* db2 = (const float*)d_in[18];

    float* out = (float*)d_out;
    float* p_out = out;            // [NP]
    float* z_out = out + NP;       // [NN*128]

    void* ptr;
    cudaGetSymbolAddress(&ptr, g_selfb);   float* selfb_buf = (float*)ptr;

    int nsm = 148;
    cudaDeviceGetAttribute(&nsm, cudaDevAttrMultiProcessorCount, 0);

    cudaFuncSetAttribute(k_mm_node, cudaFuncAttributeMaxDynamicSharedMemorySize, NO_SMEM);
    cudaFuncSetAttribute(k_mm_decoder, cudaFuncAttributeMaxDynamicSharedMemorySize, DO_SMEM);

    // ordered so the 4th launch (ncu's sample) is the node GEMM
    k_convert_x<<<(NN * 128 + 255) / 256, 256>>>(x);                                        // 1
    k_convert_weights<<<(W_TOTAL + 255) / 256, 256>>>(ws[0], wn[0], ws[1], wn[1], ws[2], wn[2], dw1); // 2
    k_zero_deg<<<(NN + 255) / 256, 256>>>();                                                // 3
    k_mm_node<<<nsm, 256, NO_SMEM>>>(0, bb[0], selfb_buf);                                  // 4 <- profiled
    k_count_deg<<<(NE + 255) / 256, 256>>>(erow);                                           // 5
    k_scan_part<<<NBLK, SCAN_B>>>();                                                        // 6
    k_scan_mid<<<1, 128>>>();                                                               // 7
    k_scan_final<<<NBLK, SCAN_B>>>();                                                       // 8
    k_scatter_edges<<<(NE + 255) / 256, 256>>>(erow, ecol, ew);                             // 9
    k_aggregate<<<NN, 128>>>(nullptr, 1, 0);                                                // 10
    k_mm_node<<<nsm, 256, NO_SMEM>>>(1, bb[1], selfb_buf);                                  // 11
    k_aggregate<<<NN, 128>>>(nullptr, 1, 0);                                                // 12
    k_mm_node<<<nsm, 256, NO_SMEM>>>(2, bb[2], selfb_buf);                                  // 13
    k_aggregate<<<NN, 128>>>(z_out, 0, 1);                                                  // 14
    k_mm_decoder<<<nsm, 256, DO_SMEM>>>(xidx, yidx, db1, dw2, db2, p_out);                  // 15
}

// round 7
// speedup vs baseline: 2.0783x; 1.0051x over previous
#include <cuda_runtime.h>
#include <cuda_fp16.h>
#include <math.h>
#include <stdint.h>

#define NN 100000
#define NE 1600000
#define NP 500000
#define SCAN_B 1024
#define NBLK ((NN + SCAN_B - 1) / SCAN_B)   // 98

// ---------------- static device scratch ----------------
__device__ float  g_selfb[(size_t)NN * 128];
__device__ __half g_suph[(size_t)NN * 128];   // h @ Wn in fp16 (gathered operand)
__device__ __half g_ahi[(size_t)NN * 128];    // activation hi
__device__ __half g_alo[(size_t)NN * 128];    // activation lo
__device__ int   g_rowptr[NN + 1];
__device__ int   g_cursor[NN];
__device__ int   g_partial[NBLK];
__device__ int   g_blockoff[NBLK];
__device__ int   g_pcol[NE];
__device__ float g_pw[NE];
#define W_NODE_ELEMS (6 * 16384)
#define W_TOTAL (W_NODE_ELEMS + 32768)
__device__ __half g_whi[W_TOTAL];
__device__ __half g_wlo[W_TOTAL];

#define PK128 136
#define PK256 264

// ---------------- helpers ----------------
__device__ __forceinline__ uint32_t smem_u32(const void* p) {
    uint32_t a;
    asm("{ .reg .u64 t; cvta.to.shared.u64 t, %1; cvt.u32.u64 %0, t; }" : "=r"(a) : "l"(p));
    return a;
}
__device__ __forceinline__ void ldsm_x4(uint32_t& r0, uint32_t& r1, uint32_t& r2, uint32_t& r3,
                                        uint32_t addr) {
    asm volatile("ldmatrix.sync.aligned.m8n8.x4.shared.b16 {%0,%1,%2,%3}, [%4];"
                 : "=r"(r0), "=r"(r1), "=r"(r2), "=r"(r3) : "r"(addr));
}
__device__ __forceinline__ void ldsm_x2(uint32_t& r0, uint32_t& r1, uint32_t addr) {
    asm volatile("ldmatrix.sync.aligned.m8n8.x2.shared.b16 {%0,%1}, [%2];"
                 : "=r"(r0), "=r"(r1) : "r"(addr));
}
__device__ __forceinline__ void mma16816(float* c, const uint32_t* a, const uint32_t* b) {
    asm volatile("mma.sync.aligned.m16n8k16.row.col.f32.f16.f16.f32 "
                 "{%0,%1,%2,%3}, {%4,%5,%6,%7}, {%8,%9}, {%0,%1,%2,%3};"
                 : "+f"(c[0]), "+f"(c[1]), "+f"(c[2]), "+f"(c[3])
                 : "r"(a[0]), "r"(a[1]), "r"(a[2]), "r"(a[3]), "r"(b[0]), "r"(b[1]));
}
__device__ __forceinline__ void cp16(uint32_t dst, const void* src, unsigned sz) {
    asm volatile("cp.async.cg.shared.global [%0], [%1], 16, %2;"
                 :: "r"(dst), "l"(src), "r"(sz) : "memory");
}
#define CP_COMMIT() asm volatile("cp.async.commit_group;" ::: "memory")
#define CP_WAIT1()  asm volatile("cp.async.wait_group 1;" ::: "memory")
#define CP_WAIT0()  asm volatile("cp.async.wait_group 0;" ::: "memory")

__device__ __forceinline__ void split1(float v, __half& h, __half& l) {
    h = __float2half_rn(v);
    l = __float2half_rn(v - __half2float(h));
}

// ---------------- CSR build ----------------
__global__ void k_zero_deg() {
    int i = blockIdx.x * blockDim.x + threadIdx.x;
    if (i < NN) g_cursor[i] = 0;
}
__global__ void k_count_deg(const int* __restrict__ row) {
    int e = blockIdx.x * blockDim.x + threadIdx.x;
    if (e < NE) atomicAdd(&g_cursor[row[e]], 1);
}
__global__ __launch_bounds__(SCAN_B) void k_scan_part() {
    __shared__ int sh[SCAN_B / 32];
    int t = threadIdx.x;
    int idx = blockIdx.x * SCAN_B + t;
    int v = (idx < NN) ? g_cursor[idx] : 0;
#pragma unroll
    for (int off = 16; off > 0; off >>= 1) v += __shfl_down_sync(0xffffffffu, v, off);
    if ((t & 31) == 0) sh[t >> 5] = v;
    __syncthreads();
    if (t < 32) {
        int s = (t < SCAN_B / 32) ? sh[t] : 0;
#pragma unroll
        for (int off = 16; off > 0; off >>= 1) s += __shfl_down_sync(0xffffffffu, s, off);
        if (t == 0) g_partial[blockIdx.x] = s;
    }
}
__global__ __launch_bounds__(128) void k_scan_mid() {
    __shared__ int sh[128];
    int t = threadIdx.x;
    int v = (t < NBLK) ? g_partial[t] : 0;
    sh[t] = v;
    __syncthreads();
#pragma unroll
    for (int off = 1; off < 128; off <<= 1) {
        int y = (t >= off) ? sh[t - off] : 0;
        __syncthreads();
        sh[t] += y;
        __syncthreads();
    }
    if (t < NBLK) g_blockoff[t] = sh[t] - v;
}
__global__ __launch_bounds__(SCAN_B) void k_scan_final() {
    __shared__ int sh[SCAN_B];
    int t = threadIdx.x;
    int idx = blockIdx.x * SCAN_B + t;
    int v = (idx < NN) ? g_cursor[idx] : 0;
    sh[t] = v;
    __syncthreads();
#pragma unroll
    for (int off = 1; off < SCAN_B; off <<= 1) {
        int y = (t >= off) ? sh[t - off] : 0;
        __syncthreads();
        sh[t] += y;
        __syncthreads();
    }
    if (idx < NN) {
        int incl = sh[t] + g_blockoff[blockIdx.x];
        g_rowptr[idx + 1] = incl;
        g_cursor[idx] = incl - v;
    }
    if (idx == 0) g_rowptr[0] = 0;
}
__global__ void k_scatter_edges(const int* __restrict__ row, const int* __restrict__ col,
                                const float* __restrict__ w) {
    int e = blockIdx.x * blockDim.x + threadIdx.x;
    if (e < NE) {
        int pos = atomicAdd(&g_cursor[row[e]], 1);
        g_pcol[pos] = col[e];
        g_pw[pos]   = w[e];
    }
}

// ---------------- converters ----------------
__global__ void k_convert_x(const float* __restrict__ x) {
    int i = blockIdx.x * blockDim.x + threadIdx.x;
    if (i < NN * 128) {
        __half h, l;
        split1(x[i], h, l);
        g_ahi[i] = h;
        g_alo[i] = l;
    }
}
__global__ void k_convert_weights(const float* w0, const float* w1_, const float* w2_,
                                  const float* w3, const float* w4, const float* w5,
                                  const float* wdec) {
    int idx = blockIdx.x * blockDim.x + threadIdx.x;
    if (idx >= W_TOTAL) return;
    float v;
    if (idx < W_NODE_ELEMS) {
        int m = idx >> 14;
        int e = idx & 16383;
        int n = e >> 7, k = e & 127;
        const float* W = (m == 0) ? w0 : (m == 1) ? w1_ : (m == 2) ? w2_
                       : (m == 3) ? w3 : (m == 4) ? w4 : w5;
        v = W[k * 128 + n];
    } else {
        int e = idx - W_NODE_ELEMS;
        int n = e >> 8, k = e & 255;
        v = wdec[k * 128 + n];
    }
    __half h, l;
    split1(v, h, l);
    g_whi[idx] = h;
    g_wlo[idx] = l;
}

// ---------------- neighbor aggregation ----------------
__global__ __launch_bounds__(128) void k_aggregate(float* __restrict__ outf, int relu, int writef) {
    int node = blockIdx.x;
    int f = threadIdx.x;
    size_t idx = (size_t)node * 128 + f;
    float a0 = g_selfb[idx];
    float a1 = 0.f, a2 = 0.f, a3 = 0.f;
    int s = g_rowptr[node];
    int e = g_rowptr[node + 1];
    int i = s;
    for (; i + 3 < e; i += 4) {
        int c0 = g_pcol[i], c1 = g_pcol[i + 1], c2 = g_pcol[i + 2], c3 = g_pcol[i + 3];
        float w0 = g_pw[i], w1 = g_pw[i + 1], w2 = g_pw[i + 2], w3 = g_pw[i + 3];
        a0 += w0 * __half2float(g_suph[(size_t)c0 * 128 + f]);
        a1 += w1 * __half2float(g_suph[(size_t)c1 * 128 + f]);
        a2 += w2 * __half2float(g_suph[(size_t)c2 * 128 + f]);
        a3 += w3 * __half2float(g_suph[(size_t)c3 * 128 + f]);
    }
    for (; i < e; i++)
        a0 += g_pw[i] * __half2float(g_suph[(size_t)g_pcol[i] * 128 + f]);
    float acc = (a0 + a1) + (a2 + a3);
    if (relu) acc = fmaxf(acc, 0.f);
    if (writef) outf[idx] = acc;
    __half h, l;
    split1(acc, h, l);
    g_ahi[idx] = h;
    g_alo[idx] = l;
}

// ---------------- persistent node GEMM: 512 thr, mat-split warps ----------------
#define NO_BIAS  0                               // 512
#define NO_WSHI  1024
#define NO_WSLO  (NO_WSHI + 128 * PK128 * 2)     // +34816
#define NO_WNHI  (NO_WSLO + 128 * PK128 * 2)
#define NO_A0    (NO_WNHI + 128 * PK128 * 2)
#define NO_ASTG  (64 * PK128 * 2)                // 17408 per hi or lo
#define NO_A1    (NO_A0 + 2 * NO_ASTG)
#define NO_SMEM  (NO_A1 + 2 * NO_ASTG)           // 175104

#define NODE_TILES ((NN + 63) / 64)              // 1563

__device__ __forceinline__ void issue_node_tile(int rowBase, uint32_t smHi, uint32_t smLo, int tid) {
    int r = tid >> 3;               // 0..63
    int u0 = (tid & 7) * 2;         // units 0..15
    int gr = rowBase + r;
    unsigned sz = (gr < NN) ? 16u : 0u;
    int grc = gr < NN ? gr : NN - 1;
    const char* srcH = (const char*)g_ahi + (size_t)grc * 256;
    const char* srcL = (const char*)g_alo + (size_t)grc * 256;
    uint32_t drow = (uint32_t)r * (PK128 * 2);
#pragma unroll
    for (int q = 0; q < 2; q++) {
        uint32_t o = (u0 + q) * 16;
        cp16(smHi + drow + o, srcH + o, sz);
        cp16(smLo + drow + o, srcL + o, sz);
    }
}

__global__ __launch_bounds__(512, 1) void k_mm_node(
    int wsel, const float* __restrict__ bias, float* __restrict__ Cself)
{
    extern __shared__ char sm[];
    uint32_t sb = smem_u32(sm);
    int tid = threadIdx.x;
    int lane = tid & 31, w = tid >> 5;
    int mat   = w & 1;            // 0 = self (3-term), 1 = support (2-term)
    int warpN = (w >> 1) & 3;     // 32-col group
    int warpM = (w >> 3) & 1;     // 32-row group

    if (tid < 128) ((float*)(sm + NO_BIAS))[tid] = bias[tid];
    {
        const uint4* whS = (const uint4*)(g_whi + (size_t)(2 * wsel) * 16384);
        const uint4* wlS = (const uint4*)(g_wlo + (size_t)(2 * wsel) * 16384);
        const uint4* whN = (const uint4*)(g_whi + (size_t)(2 * wsel + 1) * 16384);
        for (int idx = tid; idx < 2048; idx += 512) {
            int r = idx >> 4, u = idx & 15;
            uint32_t off = r * (PK128 * 2) + u * 16;
            *(uint4*)(sm + NO_WSHI + off) = whS[idx];
            *(uint4*)(sm + NO_WSLO + off) = wlS[idx];
            *(uint4*)(sm + NO_WNHI + off) = whN[idx];
        }
    }

    uint32_t aStage[2] = { sb + NO_A0, sb + NO_A1 };
    const float* sbias = (const float*)(sm + NO_BIAS);

    uint32_t aRow = warpM * 32 + (lane & 15);
    uint32_t aColSel = (lane >> 4) * 8;
    uint32_t aOff0 = (aRow * PK128 + aColSel) * 2;
    uint32_t aOff1 = ((aRow + 16) * PK128 + aColSel) * 2;
    uint32_t bRow = warpN * 32 + (lane & 7);
    uint32_t bColSel = ((lane >> 3) & 1) * 8;
    uint32_t bOffBase = (bRow * PK128 + bColSel) * 2;
    uint32_t bHiBase = (mat ? (sb + NO_WNHI) : (sb + NO_WSHI)) + bOffBase;
    uint32_t bLoBase = (sb + NO_WSLO) + bOffBase;

    int t = blockIdx.x;
    int buf = 0;
    if (t < NODE_TILES) { issue_node_tile(t * 64, aStage[0], aStage[0] + NO_ASTG, tid); CP_COMMIT(); }
    __syncthreads();   // weights visible

    while (t < NODE_TILES) {
        int tn = t + gridDim.x;
        if (tn < NODE_TILES) {
            issue_node_tile(tn * 64, aStage[buf ^ 1], aStage[buf ^ 1] + NO_ASTG, tid);
            CP_COMMIT();
            CP_WAIT1();
        } else {
            CP_WAIT0();
        }
        __syncthreads();

        float acc[2][4][4];
#pragma unroll
        for (int mt = 0; mt < 2; mt++)
#pragma unroll
            for (int nt = 0; nt < 4; nt++)
#pragma unroll
                for (int q = 0; q < 4; q++) acc[mt][nt][q] = 0.f;

        uint32_t asH = aStage[buf], asL = aStage[buf] + NO_ASTG;
#pragma unroll
        for (int ks = 0; ks < 8; ks++) {
            uint32_t kadd = ks * 32;
            uint32_t aH[2][4], aL[2][4];
            ldsm_x4(aH[0][0], aH[0][1], aH[0][2], aH[0][3], asH + aOff0 + kadd);
            ldsm_x4(aH[1][0], aH[1][1], aH[1][2], aH[1][3], asH + aOff1 + kadd);
            ldsm_x4(aL[0][0], aL[0][1], aL[0][2], aL[0][3], asL + aOff0 + kadd);
            ldsm_x4(aL[1][0], aL[1][1], aL[1][2], aL[1][3], asL + aOff1 + kadd);
#pragma unroll
            for (int nt = 0; nt < 4; nt++) {
                uint32_t bo = nt * 8 * PK128 * 2 + kadd;
                uint32_t bH[2];
                ldsm_x2(bH[0], bH[1], bHiBase + bo);
                // common: Ahi*Bhi + Alo*Bhi
                mma16816(acc[0][nt], aH[0], bH);
                mma16816(acc[1][nt], aH[1], bH);
                mma16816(acc[0][nt], aL[0], bH);
                mma16816(acc[1][nt], aL[1], bH);
                if (!mat) {  // self adds Ahi*Blo
                    uint32_t bL[2];
                    ldsm_x2(bL[0], bL[1], bLoBase + bo);
                    mma16816(acc[0][nt], aH[0], bL);
                    mma16816(acc[1][nt], aH[1], bL);
                }
            }
        }

        int base = t * 64;
        if (!mat) {
#pragma unroll
            for (int mt = 0; mt < 2; mt++) {
                int r0 = base + warpM * 32 + mt * 16 + (lane >> 2);
#pragma unroll
                for (int nt = 0; nt < 4; nt++) {
                    int c = warpN * 32 + nt * 8 + (lane & 3) * 2;
                    if (r0 < NN)
                        *(float2*)(Cself + (size_t)r0 * 128 + c) =
                            make_float2(acc[mt][nt][0] + sbias[c], acc[mt][nt][1] + sbias[c + 1]);
                    if (r0 + 8 < NN)
                        *(float2*)(Cself + (size_t)(r0 + 8) * 128 + c) =
                            make_float2(acc[mt][nt][2] + sbias[c], acc[mt][nt][3] + sbias[c + 1]);
                }
            }
        } else {
#pragma unroll
            for (int mt = 0; mt < 2; mt++) {
                int r0 = base + warpM * 32 + mt * 16 + (lane >> 2);
#pragma unroll
                for (int nt = 0; nt < 4; nt++) {
                    int c = warpN * 32 + nt * 8 + (lane & 3) * 2;
                    if (r0 < NN)
                        *(__half2*)(&g_suph[(size_t)r0 * 128 + c]) =
                            __halves2half2(__float2half_rn(acc[mt][nt][0]),
                                           __float2half_rn(acc[mt][nt][1]));
                    if (r0 + 8 < NN)
                        *(__half2*)(&g_suph[(size_t)(r0 + 8) * 128 + c]) =
                            __halves2half2(__float2half_rn(acc[mt][nt][2]),
                                           __float2half_rn(acc[mt][nt][3]));
                }
            }
        }
        __syncthreads();
        buf ^= 1;
        t = tn;
    }
}

// ---------------- persistent fused decoder: 512 thr, 64-pair tiles, A hi-only ----------------
#define DO_B1   0       // 512
#define DO_W2   512     // 512
#define DO_RED  1024    // 64*16*4 = 4096
#define DO_W1HI 5120
#define DO_W1LO (DO_W1HI + 128 * PK256 * 2)      // +67584
#define DO_A0   (DO_W1LO + 128 * PK256 * 2)
#define DO_ASTG (64 * PK128 * 2)                 // 17408 (hi only)
#define DO_A1   (DO_A0 + DO_ASTG)
#define DO_SMEM (DO_A1 + DO_ASTG)                // 175104

#define DEC_TILES ((NP + 63) / 64)               // 7813

__device__ __forceinline__ void issue_dec_stage(int tile, int chunk,
                                                const int* __restrict__ xidx,
                                                const int* __restrict__ yidx,
                                                uint32_t smHi, int tid) {
    int r = tid >> 3;
    int u0 = (tid & 7) * 2;
    int pp = tile * 64 + r;
    const int* idx = chunk ? yidx : xidx;
    int node = (pp < NP) ? idx[pp] : 0;
    const char* srcH = (const char*)g_ahi + (size_t)node * 256;
    uint32_t drow = (uint32_t)r * (PK128 * 2);
#pragma unroll
    for (int q = 0; q < 2; q++) {
        uint32_t o = (u0 + q) * 16;
        cp16(smHi + drow + o, srcH + o, 16u);
    }
}

__global__ __launch_bounds__(512, 1) void k_mm_decoder(
    const int* __restrict__ xidx, const int* __restrict__ yidx,
    const float* __restrict__ b1, const float* __restrict__ w2, const float* __restrict__ b2,
    float* __restrict__ p)
{
    extern __shared__ char sm[];
    uint32_t sb = smem_u32(sm);
    int tid = threadIdx.x;
    int lane = tid & 31, w = tid >> 5;
    int warpM = w & 3;        // 16-row group (4 x 16 = 64)
    int warpN = w >> 2;       // 32-col group (4 x 32 = 128)

    if (tid < 128) {
        ((float*)(sm + DO_B1))[tid] = b1[tid];
        ((float*)(sm + DO_W2))[tid] = w2[tid];
    }
    {
        const uint4* wh = (const uint4*)(g_whi + W_NODE_ELEMS);
        const uint4* wl = (const uint4*)(g_wlo + W_NODE_ELEMS);
        for (int idx = tid; idx < 4096; idx += 512) {
            int r = idx >> 5, u = idx & 31;
            uint32_t off = r * (PK256 * 2) + u * 16;
            *(uint4*)(sm + DO_W1HI + off) = wh[idx];
            *(uint4*)(sm + DO_W1LO + off) = wl[idx];
        }
    }

    uint32_t aStage[2] = { sb + DO_A0, sb + DO_A1 };
    const float* sb1 = (const float*)(sm + DO_B1);
    const float* sw2 = (const float*)(sm + DO_W2);
    float* red = (float*)(sm + DO_RED);
    float b2v = __ldg(b2);

    uint32_t aRow = warpM * 16 + (lane & 15);
    uint32_t aColSel = (lane >> 4) * 8;
    uint32_t aOff = (aRow * PK128 + aColSel) * 2;
    uint32_t bRow = warpN * 32 + (lane & 7);
    uint32_t bColSel = ((lane >> 3) & 1) * 8;
    uint32_t bOffBase = (bRow * PK256 + bColSel) * 2;

    float acc[4][4];
#pragma unroll
    for (int nt = 0; nt < 4; nt++)
#pragma unroll
        for (int q = 0; q < 4; q++) acc[nt][q] = 0.f;

    int t = blockIdx.x;
    int c = 0;
    int buf = 0;
    if (t < DEC_TILES) {
        issue_dec_stage(t, 0, xidx, yidx, aStage[0], tid);
        CP_COMMIT();
    }
    __syncthreads();   // W1 visible

    while (t < DEC_TILES) {
        int nt_ = t, nc = c + 1;
        if (nc == 2) { nc = 0; nt_ = t + gridDim.x; }
        if (nt_ < DEC_TILES) {
            issue_dec_stage(nt_, nc, xidx, yidx, aStage[buf ^ 1], tid);
            CP_COMMIT();
            CP_WAIT1();
        } else {
            CP_WAIT0();
        }
        __syncthreads();

        uint32_t asH = aStage[buf];
        uint32_t kChunk = c * 256;   // byte offset into W1 K dim
#pragma unroll
        for (int ks = 0; ks < 8; ks++) {
            uint32_t kadd = ks * 32;
            uint32_t aH[4];
            ldsm_x4(aH[0], aH[1], aH[2], aH[3], asH + aOff + kadd);
#pragma unroll
            for (int nt2 = 0; nt2 < 4; nt2++) {
                uint32_t bo = bOffBase + nt2 * 8 * PK256 * 2 + kChunk + kadd;
                uint32_t bH[2], bL[2];
                ldsm_x2(bH[0], bH[1], sb + DO_W1HI + bo);
                ldsm_x2(bL[0], bL[1], sb + DO_W1LO + bo);
                mma16816(acc[nt2], aH, bH);
                mma16816(acc[nt2], aH, bL);
            }
        }

        if (c == 1) {
            int rl = warpM * 16 + (lane >> 2);
            float p0 = 0.f, p1 = 0.f;
#pragma unroll
            for (int nt2 = 0; nt2 < 4; nt2++) {
                int cc = warpN * 32 + nt2 * 8 + (lane & 3) * 2;
                float h00 = fmaxf(acc[nt2][0] + sb1[cc], 0.f);
                float h01 = fmaxf(acc[nt2][1] + sb1[cc + 1], 0.f);
                float h10 = fmaxf(acc[nt2][2] + sb1[cc], 0.f);
                float h11 = fmaxf(acc[nt2][3] + sb1[cc + 1], 0.f);
                p0 += h00 * sw2[cc] + h01 * sw2[cc + 1];
                p1 += h10 * sw2[cc] + h11 * sw2[cc + 1];
            }
            red[rl * 16 + warpN * 4 + (lane & 3)] = p0;
            red[(rl + 8) * 16 + warpN * 4 + (lane & 3)] = p1;
            __syncthreads();
            if (tid < 64) {
                float s = 0.f;
#pragma unroll
                for (int j = 0; j < 16; j++) s += red[tid * 16 + j];
                s += b2v;
                float pv = 1.f / (1.f + expf(-s));
                int pp = t * 64 + tid;
                if (pp < NP) p[pp] = pv;
            }
#pragma unroll
            for (int nt2 = 0; nt2 < 4; nt2++)
#pragma unroll
                for (int q = 0; q < 4; q++) acc[nt2][q] = 0.f;
        }
        __syncthreads();
        buf ^= 1;
        c = nc;
        t = nt_;
    }
}

// ---------------- launch ----------------
extern "C" void kernel_launch(void* const* d_in, const int* in_sizes, int n_in,
                              void* d_out, int out_size) {
    const float* x     = (const float*)d_in[0];
    const int*   erow  = (const int*)  d_in[1];
    const int*   ecol  = (const int*)  d_in[2];
    const float* ew    = (const float*)d_in[3];
    const int*   xidx  = (const int*)  d_in[4];
    const int*   yidx  = (const int*)  d_in[5];
    const float* ws[3] = { (const float*)d_in[6],  (const float*)d_in[9],  (const float*)d_in[12] };
    const float* wn[3] = { (const float*)d_in[7],  (const float*)d_in[10], (const float*)d_in[13] };
    const float* bb[3] = { (const float*)d_in[8],  (const float*)d_in[11], (const float*)d_in[14] };
    const float* dw1 = (const float*)d_in[15];
    const float* db1 = (const float*)d_in[16];
    const float* dw2 = (const float*)d_in[17];
    const float* db2 = (const float*)d_in[18];

    float* out = (float*)d_out;
    float* p_out = out;            // [NP]
    float* z_out = out + NP;       // [NN*128]

    void* ptr;
    cudaGetSymbolAddress(&ptr, g_selfb);   float* selfb_buf = (float*)ptr;

    int nsm = 148;
    cudaDeviceGetAttribute(&nsm, cudaDevAttrMultiProcessorCount, 0);

    cudaFuncSetAttribute(k_mm_node, cudaFuncAttributeMaxDynamicSharedMemorySize, NO_SMEM);
    cudaFuncSetAttribute(k_mm_decoder, cudaFuncAttributeMaxDynamicSharedMemorySize, DO_SMEM);

    // ordered so the 4th launch (ncu's sample) is the node GEMM
    k_convert_x<<<(NN * 128 + 255) / 256, 256>>>(x);                                        // 1
    k_convert_weights<<<(W_TOTAL + 255) / 256, 256>>>(ws[0], wn[0], ws[1], wn[1], ws[2], wn[2], dw1); // 2
    k_zero_deg<<<(NN + 255) / 256, 256>>>();                                                // 3
    k_mm_node<<<nsm, 512, NO_SMEM>>>(0, bb[0], selfb_buf);                                  // 4 <- profiled
    k_count_deg<<<(NE + 255) / 256, 256>>>(erow);                                           // 5
    k_scan_part<<<NBLK, SCAN_B>>>();                                                        // 6
    k_scan_mid<<<1, 128>>>();                                                               // 7
    k_scan_final<<<NBLK, SCAN_B>>>();                                                       // 8
    k_scatter_edges<<<(NE + 255) / 256, 256>>>(erow, ecol, ew);                             // 9
    k_aggregate<<<NN, 128>>>(nullptr, 1, 0);                                                // 10
    k_mm_node<<<nsm, 512, NO_SMEM>>>(1, bb[1], selfb_buf);                                  // 11
    k_aggregate<<<NN, 128>>>(nullptr, 1, 0);                                                // 12
    k_mm_node<<<nsm, 512, NO_SMEM>>>(2, bb[2], selfb_buf);                                  // 13
    k_aggregate<<<NN, 128>>>(z_out, 0, 1);                                                  // 14
    k_mm_decoder<<<nsm, 512, DO_SMEM>>>(xidx, yidx, db1, dw2, db2, p_out);                  // 15
}

// round 9
// speedup vs baseline: 2.1381x; 1.0288x over previous
#include <cuda_runtime.h>
#include <cuda_fp16.h>
#include <math.h>
#include <stdint.h>

#define NN 100000
#define NE 1600000
#define NP 500000
#define SCAN_B 1024
#define NBLK ((NN + SCAN_B - 1) / SCAN_B)   // 98

// ---------------- static device scratch ----------------
__device__ float  g_selfb[(size_t)NN * 128];
__device__ __half g_suph[(size_t)NN * 128];   // h @ Wn in fp16 (gathered operand)
__device__ __half g_ahi[(size_t)NN * 128];    // activation hi
__device__ __half g_alo[(size_t)NN * 128];    // activation lo
__device__ int   g_rowptr[NN + 1];
__device__ int   g_cursor[NN];
__device__ int   g_partial[NBLK];
__device__ int   g_blockoff[NBLK];
__device__ int   g_pcol[NE];
__device__ float g_pw[NE];
#define W_NODE_ELEMS (6 * 16384)
#define W_TOTAL (W_NODE_ELEMS + 32768)
__device__ __half g_whi[W_TOTAL];
__device__ __half g_wlo[W_TOTAL];

#define PK128 136
#define PK256 264

// ---------------- helpers ----------------
__device__ __forceinline__ uint32_t smem_u32(const void* p) {
    uint32_t a;
    asm("{ .reg .u64 t; cvta.to.shared.u64 t, %1; cvt.u32.u64 %0, t; }" : "=r"(a) : "l"(p));
    return a;
}
__device__ __forceinline__ void ldsm_x4(uint32_t& r0, uint32_t& r1, uint32_t& r2, uint32_t& r3,
                                        uint32_t addr) {
    asm volatile("ldmatrix.sync.aligned.m8n8.x4.shared.b16 {%0,%1,%2,%3}, [%4];"
                 : "=r"(r0), "=r"(r1), "=r"(r2), "=r"(r3) : "r"(addr));
}
__device__ __forceinline__ void ldsm_x2(uint32_t& r0, uint32_t& r1, uint32_t addr) {
    asm volatile("ldmatrix.sync.aligned.m8n8.x2.shared.b16 {%0,%1}, [%2];"
                 : "=r"(r0), "=r"(r1) : "r"(addr));
}
__device__ __forceinline__ void mma16816(float* c, const uint32_t* a, const uint32_t* b) {
    asm volatile("mma.sync.aligned.m16n8k16.row.col.f32.f16.f16.f32 "
                 "{%0,%1,%2,%3}, {%4,%5,%6,%7}, {%8,%9}, {%0,%1,%2,%3};"
                 : "+f"(c[0]), "+f"(c[1]), "+f"(c[2]), "+f"(c[3])
                 : "r"(a[0]), "r"(a[1]), "r"(a[2]), "r"(a[3]), "r"(b[0]), "r"(b[1]));
}
__device__ __forceinline__ void cp16(uint32_t dst, const void* src, unsigned sz) {
    asm volatile("cp.async.cg.shared.global [%0], [%1], 16, %2;"
                 :: "r"(dst), "l"(src), "r"(sz) : "memory");
}
#define CP_COMMIT() asm volatile("cp.async.commit_group;" ::: "memory")
#define CP_WAIT1()  asm volatile("cp.async.wait_group 1;" ::: "memory")

__device__ __forceinline__ void split1(float v, __half& h, __half& l) {
    h = __float2half_rn(v);
    l = __float2half_rn(v - __half2float(h));
}

// ---------------- CSR build ----------------
__global__ void k_zero_deg() {
    int i = blockIdx.x * blockDim.x + threadIdx.x;
    if (i < NN) g_cursor[i] = 0;
}
__global__ void k_count_deg(const int* __restrict__ row) {
    int e = blockIdx.x * blockDim.x + threadIdx.x;
    if (e < NE) atomicAdd(&g_cursor[row[e]], 1);
}
__global__ __launch_bounds__(SCAN_B) void k_scan_part() {
    __shared__ int sh[SCAN_B / 32];
    int t = threadIdx.x;
    int idx = blockIdx.x * SCAN_B + t;
    int v = (idx < NN) ? g_cursor[idx] : 0;
#pragma unroll
    for (int off = 16; off > 0; off >>= 1) v += __shfl_down_sync(0xffffffffu, v, off);
    if ((t & 31) == 0) sh[t >> 5] = v;
    __syncthreads();
    if (t < 32) {
        int s = (t < SCAN_B / 32) ? sh[t] : 0;
#pragma unroll
        for (int off = 16; off > 0; off >>= 1) s += __shfl_down_sync(0xffffffffu, s, off);
        if (t == 0) g_partial[blockIdx.x] = s;
    }
}
__global__ __launch_bounds__(128) void k_scan_mid() {
    __shared__ int sh[128];
    int t = threadIdx.x;
    int v = (t < NBLK) ? g_partial[t] : 0;
    sh[t] = v;
    __syncthreads();
#pragma unroll
    for (int off = 1; off < 128; off <<= 1) {
        int y = (t >= off) ? sh[t - off] : 0;
        __syncthreads();
        sh[t] += y;
        __syncthreads();
    }
    if (t < NBLK) g_blockoff[t] = sh[t] - v;
}
__global__ __launch_bounds__(SCAN_B) void k_scan_final() {
    __shared__ int sh[SCAN_B];
    int t = threadIdx.x;
    int idx = blockIdx.x * SCAN_B + t;
    int v = (idx < NN) ? g_cursor[idx] : 0;
    sh[t] = v;
    __syncthreads();
#pragma unroll
    for (int off = 1; off < SCAN_B; off <<= 1) {
        int y = (t >= off) ? sh[t - off] : 0;
        __syncthreads();
        sh[t] += y;
        __syncthreads();
    }
    if (idx < NN) {
        int incl = sh[t] + g_blockoff[blockIdx.x];
        g_rowptr[idx + 1] = incl;
        g_cursor[idx] = incl - v;
    }
    if (idx == 0) g_rowptr[0] = 0;
}
__global__ void k_scatter_edges(const int* __restrict__ row, const int* __restrict__ col,
                                const float* __restrict__ w) {
    int e = blockIdx.x * blockDim.x + threadIdx.x;
    if (e < NE) {
        int pos = atomicAdd(&g_cursor[row[e]], 1);
        g_pcol[pos] = col[e];
        g_pw[pos]   = w[e];
    }
}

// ---------------- converters ----------------
__global__ void k_convert_x(const float* __restrict__ x) {
    int i = blockIdx.x * blockDim.x + threadIdx.x;
    if (i < NN * 128) {
        __half h, l;
        split1(x[i], h, l);
        g_ahi[i] = h;
        g_alo[i] = l;
    }
}
__global__ void k_convert_weights(const float* w0, const float* w1_, const float* w2_,
                                  const float* w3, const float* w4, const float* w5,
                                  const float* wdec) {
    int idx = blockIdx.x * blockDim.x + threadIdx.x;
    if (idx >= W_TOTAL) return;
    float v;
    if (idx < W_NODE_ELEMS) {
        int m = idx >> 14;
        int e = idx & 16383;
        int n = e >> 7, k = e & 127;
        const float* W = (m == 0) ? w0 : (m == 1) ? w1_ : (m == 2) ? w2_
                       : (m == 3) ? w3 : (m == 4) ? w4 : w5;
        v = W[k * 128 + n];
    } else {
        int e = idx - W_NODE_ELEMS;
        int n = e >> 8, k = e & 255;
        v = wdec[k * 128 + n];
    }
    __half h, l;
    split1(v, h, l);
    g_whi[idx] = h;
    g_wlo[idx] = l;
}

// ---------------- neighbor aggregation ----------------
__global__ __launch_bounds__(128) void k_aggregate(float* __restrict__ outf, int relu, int writef) {
    int node = blockIdx.x;
    int f = threadIdx.x;
    size_t idx = (size_t)node * 128 + f;
    float a0 = g_selfb[idx];
    float a1 = 0.f, a2 = 0.f, a3 = 0.f;
    int s = g_rowptr[node];
    int e = g_rowptr[node + 1];
    int i = s;
    for (; i + 3 < e; i += 4) {
        int c0 = g_pcol[i], c1 = g_pcol[i + 1], c2 = g_pcol[i + 2], c3 = g_pcol[i + 3];
        float w0 = g_pw[i], w1 = g_pw[i + 1], w2 = g_pw[i + 2], w3 = g_pw[i + 3];
        a0 += w0 * __half2float(g_suph[(size_t)c0 * 128 + f]);
        a1 += w1 * __half2float(g_suph[(size_t)c1 * 128 + f]);
        a2 += w2 * __half2float(g_suph[(size_t)c2 * 128 + f]);
        a3 += w3 * __half2float(g_suph[(size_t)c3 * 128 + f]);
    }
    for (; i < e; i++)
        a0 += g_pw[i] * __half2float(g_suph[(size_t)g_pcol[i] * 128 + f]);
    float acc = (a0 + a1) + (a2 + a3);
    if (relu) acc = fmaxf(acc, 0.f);
    if (writef) outf[idx] = acc;
    __half h, l;
    split1(acc, h, l);
    g_ahi[idx] = h;
    g_alo[idx] = l;
}

// ---------------- persistent node GEMM: 512 thr, mat-split warps, 3-stage ----------------
#define NO_BIAS  0                               // 512
#define NO_WSHI  1024
#define NO_WSLO  (NO_WSHI + 128 * PK128 * 2)     // +34816
#define NO_WNHI  (NO_WSLO + 128 * PK128 * 2)
#define NO_A0    (NO_WNHI + 128 * PK128 * 2)     // 3 stages of (hi 17408 + lo 17408)
#define NO_ASTG  (64 * PK128 * 2)                // 17408
#define NO_STAGE (2 * NO_ASTG)                   // 34816 per stage
#define NO_SMEM  (NO_A0 + 3 * NO_STAGE)          // 209920

#define NODE_TILES ((NN + 63) / 64)              // 1563

__device__ __forceinline__ void issue_node_tile(int rowBase, uint32_t smHi, uint32_t smLo, int tid) {
    int r = tid >> 3;               // 0..63
    int u0 = (tid & 7) * 2;         // units 0..15
    long long gr = (long long)rowBase + r;
    unsigned sz = (gr < NN) ? 16u : 0u;
    long long grc = gr < NN ? gr : (NN - 1);
    const char* srcH = (const char*)g_ahi + grc * 256;
    const char* srcL = (const char*)g_alo + grc * 256;
    uint32_t drow = (uint32_t)r * (PK128 * 2);
#pragma unroll
    for (int q = 0; q < 2; q++) {
        uint32_t o = (u0 + q) * 16;
        cp16(smHi + drow + o, srcH + o, sz);
        cp16(smLo + drow + o, srcL + o, sz);
    }
}

__global__ __launch_bounds__(512, 1) void k_mm_node(
    int wsel, const float* __restrict__ bias, float* __restrict__ Cself)
{
    extern __shared__ char sm[];
    uint32_t sb = smem_u32(sm);
    int tid = threadIdx.x;
    int lane = tid & 31, w = tid >> 5;
    int mat   = w & 1;            // 0 = self (3-term), 1 = support (2-term)
    int warpN = (w >> 1) & 3;     // 32-col group
    int warpM = (w >> 3) & 1;     // 32-row group

    if (tid < 128) ((float*)(sm + NO_BIAS))[tid] = bias[tid];
    {
        const uint4* whS = (const uint4*)(g_whi + (size_t)(2 * wsel) * 16384);
        const uint4* wlS = (const uint4*)(g_wlo + (size_t)(2 * wsel) * 16384);
        const uint4* whN = (const uint4*)(g_whi + (size_t)(2 * wsel + 1) * 16384);
        for (int idx = tid; idx < 2048; idx += 512) {
            int r = idx >> 4, u = idx & 15;
            uint32_t off = r * (PK128 * 2) + u * 16;
            *(uint4*)(sm + NO_WSHI + off) = whS[idx];
            *(uint4*)(sm + NO_WSLO + off) = wlS[idx];
            *(uint4*)(sm + NO_WNHI + off) = whN[idx];
        }
    }

    uint32_t stg[3] = { sb + NO_A0, sb + NO_A0 + NO_STAGE, sb + NO_A0 + 2 * NO_STAGE };
    const float* sbias = (const float*)(sm + NO_BIAS);

    uint32_t aRow = warpM * 32 + (lane & 15);
    uint32_t aColSel = (lane >> 4) * 8;
    uint32_t aOff0 = (aRow * PK128 + aColSel) * 2;
    uint32_t aOff1 = ((aRow + 16) * PK128 + aColSel) * 2;
    uint32_t bRow = warpN * 32 + (lane & 7);
    uint32_t bColSel = ((lane >> 3) & 1) * 8;
    uint32_t bOffBase = (bRow * PK128 + bColSel) * 2;
    uint32_t bHiBase = (mat ? (sb + NO_WNHI) : (sb + NO_WSHI)) + bOffBase;
    uint32_t bLoBase = (sb + NO_WSLO) + bOffBase;

    int g = gridDim.x;
    int t = blockIdx.x;
    int s = 0;
    // prologue: stages 0,1
    issue_node_tile(t * 64, stg[0], stg[0] + NO_ASTG, tid);
    CP_COMMIT();
    issue_node_tile((t + g) * 64, stg[1], stg[1] + NO_ASTG, tid);
    CP_COMMIT();
    __syncthreads();   // weights + bias visible

    while (t < NODE_TILES) {
        CP_WAIT1();        // stage s done (s+1 may still be loading)
        __syncthreads();   // data visible; previous tile's compute finished -> stage (s+2)%3 free

        int s2i = (s >= 1) ? (s - 1) : 2;   // == (s+2)%3
        issue_node_tile((t + 2 * g) * 64, stg[s2i], stg[s2i] + NO_ASTG, tid);
        CP_COMMIT();

        float acc[2][4][4];
#pragma unroll
        for (int mt = 0; mt < 2; mt++)
#pragma unroll
            for (int nt = 0; nt < 4; nt++)
#pragma unroll
                for (int q = 0; q < 4; q++) acc[mt][nt][q] = 0.f;

        uint32_t asH = stg[s], asL = stg[s] + NO_ASTG;
#pragma unroll
        for (int ks = 0; ks < 8; ks++) {
            uint32_t kadd = ks * 32;
            uint32_t aH[2][4], aL[2][4];
            ldsm_x4(aH[0][0], aH[0][1], aH[0][2], aH[0][3], asH + aOff0 + kadd);
            ldsm_x4(aH[1][0], aH[1][1], aH[1][2], aH[1][3], asH + aOff1 + kadd);
            ldsm_x4(aL[0][0], aL[0][1], aL[0][2], aL[0][3], asL + aOff0 + kadd);
            ldsm_x4(aL[1][0], aL[1][1], aL[1][2], aL[1][3], asL + aOff1 + kadd);
#pragma unroll
            for (int nt = 0; nt < 4; nt++) {
                uint32_t bo = nt * 8 * PK128 * 2 + kadd;
                uint32_t bH[2];
                ldsm_x2(bH[0], bH[1], bHiBase + bo);
                mma16816(acc[0][nt], aH[0], bH);
                mma16816(acc[1][nt], aH[1], bH);
                mma16816(acc[0][nt], aL[0], bH);
                mma16816(acc[1][nt], aL[1], bH);
                if (!mat) {
                    uint32_t bL[2];
                    ldsm_x2(bL[0], bL[1], bLoBase + bo);
                    mma16816(acc[0][nt], aH[0], bL);
                    mma16816(acc[1][nt], aH[1], bL);
                }
            }
        }

        int base = t * 64;
        if (!mat) {
#pragma unroll
            for (int mt = 0; mt < 2; mt++) {
                int r0 = base + warpM * 32 + mt * 16 + (lane >> 2);
#pragma unroll
                for (int nt = 0; nt < 4; nt++) {
                    int c = warpN * 32 + nt * 8 + (lane & 3) * 2;
                    if (r0 < NN)
                        *(float2*)(Cself + (size_t)r0 * 128 + c) =
                            make_float2(acc[mt][nt][0] + sbias[c], acc[mt][nt][1] + sbias[c + 1]);
                    if (r0 + 8 < NN)
                        *(float2*)(Cself + (size_t)(r0 + 8) * 128 + c) =
                            make_float2(acc[mt][nt][2] + sbias[c], acc[mt][nt][3] + sbias[c + 1]);
                }
            }
        } else {
#pragma unroll
            for (int mt = 0; mt < 2; mt++) {
                int r0 = base + warpM * 32 + mt * 16 + (lane >> 2);
#pragma unroll
                for (int nt = 0; nt < 4; nt++) {
                    int c = warpN * 32 + nt * 8 + (lane & 3) * 2;
                    if (r0 < NN)
                        *(__half2*)(&g_suph[(size_t)r0 * 128 + c]) =
                            __halves2half2(__float2half_rn(acc[mt][nt][0]),
                                           __float2half_rn(acc[mt][nt][1]));
                    if (r0 + 8 < NN)
                        *(__half2*)(&g_suph[(size_t)(r0 + 8) * 128 + c]) =
                            __halves2half2(__float2half_rn(acc[mt][nt][2]),
                                           __float2half_rn(acc[mt][nt][3]));
                }
            }
        }
        t += g;
        s = (s + 1 == 3) ? 0 : (s + 1);
    }
}

// ---------------- persistent fused decoder: 512 thr, 3-stage, A hi-only ----------------
#define DO_B1   0       // 512
#define DO_W2   512     // 512
#define DO_RED  1024    // 4096
#define DO_W1HI 5120
#define DO_W1LO (DO_W1HI + 128 * PK256 * 2)      // +67584
#define DO_A0   (DO_W1LO + 128 * PK256 * 2)
#define DO_ASTG (64 * PK128 * 2)                 // 17408 (hi only)
#define DO_SMEM (DO_A0 + 3 * DO_ASTG)            // 192512

#define DEC_TILES ((NP + 63) / 64)               // 7813

__device__ __forceinline__ void issue_dec_stage(int tile, int chunk,
                                                const int* __restrict__ xidx,
                                                const int* __restrict__ yidx,
                                                uint32_t smHi, int tid) {
    int r = tid >> 3;
    int u0 = (tid & 7) * 2;
    int pp = tile * 64 + r;
    if (pp >= NP) pp = NP - 1;
    const int* idx = chunk ? yidx : xidx;
    int node = idx[pp];
    const char* srcH = (const char*)g_ahi + (size_t)node * 256;
    uint32_t drow = (uint32_t)r * (PK128 * 2);
#pragma unroll
    for (int q = 0; q < 2; q++) {
        uint32_t o = (u0 + q) * 16;
        cp16(smHi + drow + o, srcH + o, 16u);
    }
}

__global__ __launch_bounds__(512, 1) void k_mm_decoder(
    const int* __restrict__ xidx, const int* __restrict__ yidx,
    const float* __restrict__ b1, const float* __restrict__ w2, const float* __restrict__ b2,
    float* __restrict__ p)
{
    extern __shared__ char sm[];
    uint32_t sb = smem_u32(sm);
    int tid = threadIdx.x;
    int lane = tid & 31, w = tid >> 5;
    int warpM = w & 3;        // 16-row group
    int warpN = w >> 2;       // 32-col group

    if (tid < 128) {
        ((float*)(sm + DO_B1))[tid] = b1[tid];
        ((float*)(sm + DO_W2))[tid] = w2[tid];
    }
    {
        const uint4* wh = (const uint4*)(g_whi + W_NODE_ELEMS);
        const uint4* wl = (const uint4*)(g_wlo + W_NODE_ELEMS);
        for (int idx = tid; idx < 4096; idx += 512) {
            int r = idx >> 5, u = idx & 31;
            uint32_t off = r * (PK256 * 2) + u * 16;
            *(uint4*)(sm + DO_W1HI + off) = wh[idx];
            *(uint4*)(sm + DO_W1LO + off) = wl[idx];
        }
    }

    uint32_t stg[3] = { sb + DO_A0, sb + DO_A0 + DO_ASTG, sb + DO_A0 + 2 * DO_ASTG };
    const float* sb1 = (const float*)(sm + DO_B1);
    const float* sw2 = (const float*)(sm + DO_W2);
    float* red = (float*)(sm + DO_RED);
    float b2v = __ldg(b2);

    uint32_t aRow = warpM * 16 + (lane & 15);
    uint32_t aColSel = (lane >> 4) * 8;
    uint32_t aOff = (aRow * PK128 + aColSel) * 2;
    uint32_t bRow = warpN * 32 + (lane & 7);
    uint32_t bColSel = ((lane >> 3) & 1) * 8;
    uint32_t bOffBase = (bRow * PK256 + bColSel) * 2;

    float acc[4][4];
#pragma unroll
    for (int nt = 0; nt < 4; nt++)
#pragma unroll
        for (int q = 0; q < 4; q++) acc[nt][q] = 0.f;

    int g = gridDim.x;
    int t = blockIdx.x;
    int c = 0;
    int s = 0;
    // prologue: stages (t,0), (t,1)
    issue_dec_stage(t, 0, xidx, yidx, stg[0], tid);
    CP_COMMIT();
    issue_dec_stage(t, 1, xidx, yidx, stg[1], tid);
    CP_COMMIT();
    __syncthreads();   // W1/b1/w2 visible

    while (t < DEC_TILES) {
        CP_WAIT1();
        __syncthreads();

        // stage+2 in the (t,c) sequence is (t+g, c)
        int s2i = (s >= 1) ? (s - 1) : 2;   // == (s+2)%3
        issue_dec_stage(t + g, c, xidx, yidx, stg[s2i], tid);
        CP_COMMIT();

        uint32_t asH = stg[s];
        uint32_t kChunk = c * 256;   // byte offset into W1 K dim
#pragma unroll
        for (int ks = 0; ks < 8; ks++) {
            uint32_t kadd = ks * 32;
            uint32_t aH[4];
            ldsm_x4(aH[0], aH[1], aH[2], aH[3], asH + aOff + kadd);
#pragma unroll
            for (int nt2 = 0; nt2 < 4; nt2++) {
                uint32_t bo = bOffBase + nt2 * 8 * PK256 * 2 + kChunk + kadd;
                uint32_t bH[2], bL[2];
                ldsm_x2(bH[0], bH[1], sb + DO_W1HI + bo);
                ldsm_x2(bL[0], bL[1], sb + DO_W1LO + bo);
                mma16816(acc[nt2], aH, bH);
                mma16816(acc[nt2], aH, bL);
            }
        }

        if (c == 1) {
            int rl = warpM * 16 + (lane >> 2);
            float p0 = 0.f, p1 = 0.f;
#pragma unroll
            for (int nt2 = 0; nt2 < 4; nt2++) {
                int cc = warpN * 32 + nt2 * 8 + (lane & 3) * 2;
                float h00 = fmaxf(acc[nt2][0] + sb1[cc], 0.f);
                float h01 = fmaxf(acc[nt2][1] + sb1[cc + 1], 0.f);
                float h10 = fmaxf(acc[nt2][2] + sb1[cc], 0.f);
                float h11 = fmaxf(acc[nt2][3] + sb1[cc + 1], 0.f);
                p0 += h00 * sw2[cc] + h01 * sw2[cc + 1];
                p1 += h10 * sw2[cc] + h11 * sw2[cc + 1];
            }
            red[rl * 16 + warpN * 4 + (lane & 3)] = p0;
            red[(rl + 8) * 16 + warpN * 4 + (lane & 3)] = p1;
            __syncthreads();
            if (tid < 64) {
                float sacc = 0.f;
#pragma unroll
                for (int j = 0; j < 16; j++) sacc += red[tid * 16 + j];
                sacc += b2v;
                float pv = 1.f / (1.f + expf(-sacc));
                int pp = t * 64 + tid;
                if (pp < NP) p[pp] = pv;
            }
#pragma unroll
            for (int nt2 = 0; nt2 < 4; nt2++)
#pragma unroll
                for (int q = 0; q < 4; q++) acc[nt2][q] = 0.f;
        }
        // advance (t,c) sequence
        c ^= 1;
        if (c == 0) t += g;
        s = (s + 1 == 3) ? 0 : (s + 1);
    }
}

// ---------------- launch ----------------
extern "C" void kernel_launch(void* const* d_in, const int* in_sizes, int n_in,
                              void* d_out, int out_size) {
    const float* x     = (const float*)d_in[0];
    const int*   erow  = (const int*)  d_in[1];
    const int*   ecol  = (const int*)  d_in[2];
    const float* ew    = (const float*)d_in[3];
    const int*   xidx  = (const int*)  d_in[4];
    const int*   yidx  = (const int*)  d_in[5];
    const float* ws[3] = { (const float*)d_in[6],  (const float*)d_in[9],  (const float*)d_in[12] };
    const float* wn[3] = { (const float*)d_in[7],  (const float*)d_in[10], (const float*)d_in[13] };
    const float* bb[3] = { (const float*)d_in[8],  (const float*)d_in[11], (const float*)d_in[14] };
    const float* dw1 = (const float*)d_in[15];
    const float* db1 = (const float*)d_in[16];
    const float* dw2 = (const float*)d_in[17];
    const float* db2 = (const float*)d_in[18];

    float* out = (float*)d_out;
    float* p_out = out;            // [NP]
    float* z_out = out + NP;       // [NN*128]

    void* ptr;
    cudaGetSymbolAddress(&ptr, g_selfb);   float* selfb_buf = (float*)ptr;

    int nsm = 148;
    cudaDeviceGetAttribute(&nsm, cudaDevAttrMultiProcessorCount, 0);

    cudaFuncSetAttribute(k_mm_node, cudaFuncAttributeMaxDynamicSharedMemorySize, NO_SMEM);
    cudaFuncSetAttribute(k_mm_decoder, cudaFuncAttributeMaxDynamicSharedMemorySize, DO_SMEM);

    // side stream for the CSR build (independent of converts + layer-1 GEMM)
    cudaStream_t s2;
    cudaStreamCreateWithFlags(&s2, cudaStreamNonBlocking);
    cudaEvent_t eFork, eJoin;
    cudaEventCreateWithFlags(&eFork, cudaEventDisableTiming);
    cudaEventCreateWithFlags(&eJoin, cudaEventDisableTiming);

    cudaEventRecord(eFork, 0);
    cudaStreamWaitEvent(s2, eFork, 0);

    // main stream: converts + layer-1 GEMM (launch #4 overall = mm_node, for ncu)
    k_convert_x<<<(NN * 128 + 255) / 256, 256>>>(x);                                        // 1
    k_convert_weights<<<(W_TOTAL + 255) / 256, 256>>>(ws[0], wn[0], ws[1], wn[1], ws[2], wn[2], dw1); // 2
    k_zero_deg<<<(NN + 255) / 256, 256, 0, s2>>>();                                         // 3 (s2)
    k_mm_node<<<nsm, 512, NO_SMEM>>>(0, bb[0], selfb_buf);                                  // 4 <- profiled
    // CSR chain on s2
    k_count_deg<<<(NE + 255) / 256, 256, 0, s2>>>(erow);                                    // 5
    k_scan_part<<<NBLK, SCAN_B, 0, s2>>>();                                                 // 6
    k_scan_mid<<<1, 128, 0, s2>>>();                                                        // 7
    k_scan_final<<<NBLK, SCAN_B, 0, s2>>>();                                                // 8
    k_scatter_edges<<<(NE + 255) / 256, 256, 0, s2>>>(erow, ecol, ew);                      // 9
    cudaEventRecord(eJoin, s2);
    cudaStreamWaitEvent(0, eJoin, 0);

    k_aggregate<<<NN, 128>>>(nullptr, 1, 0);                                                // 10
    k_mm_node<<<nsm, 512, NO_SMEM>>>(1, bb[1], selfb_buf);                                  // 11
    k_aggregate<<<NN, 128>>>(nullptr, 1, 0);                                                // 12
    k_mm_node<<<nsm, 512, NO_SMEM>>>(2, bb[2], selfb_buf);                                  // 13
    k_aggregate<<<NN, 128>>>(z_out, 0, 1);                                                  // 14
    k_mm_decoder<<<nsm, 512, DO_SMEM>>>(xidx, yidx, db1, dw2, db2, p_out);                  // 15
}

// round 10
// speedup vs baseline: 2.1734x; 1.0165x over previous
#include <cuda_runtime.h>
#include <cuda_fp16.h>
#include <math.h>
#include <stdint.h>

#define NN 100000
#define NE 1600000
#define NP 500000
#define SCAN_B 1024
#define NBLK ((NN + SCAN_B - 1) / SCAN_B)   // 98

// ---------------- static device scratch ----------------
__device__ float  g_selfb[(size_t)NN * 128];
__device__ __half g_suph[(size_t)NN * 128];   // h @ Wn in fp16 (gathered operand)
__device__ __half g_ahi[(size_t)NN * 128];    // activation hi
__device__ __half g_alo[(size_t)NN * 128];    // activation lo
__device__ int   g_rowptr[NN + 1];
__device__ int   g_cursor[NN];
__device__ int   g_partial[NBLK];
__device__ int   g_blockoff[NBLK];
__device__ int   g_pcol[NE];
__device__ float g_pw[NE];
#define W_NODE_ELEMS (6 * 16384)
#define W_TOTAL (W_NODE_ELEMS + 32768)
__device__ __half g_whi[W_TOTAL];
__device__ __half g_wlo[W_TOTAL];

#define PK128 136
#define PK256 264

// ---------------- helpers ----------------
__device__ __forceinline__ uint32_t smem_u32(const void* p) {
    uint32_t a;
    asm("{ .reg .u64 t; cvta.to.shared.u64 t, %1; cvt.u32.u64 %0, t; }" : "=r"(a) : "l"(p));
    return a;
}
__device__ __forceinline__ void ldsm_x4(uint32_t& r0, uint32_t& r1, uint32_t& r2, uint32_t& r3,
                                        uint32_t addr) {
    asm volatile("ldmatrix.sync.aligned.m8n8.x4.shared.b16 {%0,%1,%2,%3}, [%4];"
                 : "=r"(r0), "=r"(r1), "=r"(r2), "=r"(r3) : "r"(addr));
}
__device__ __forceinline__ void ldsm_x2(uint32_t& r0, uint32_t& r1, uint32_t addr) {
    asm volatile("ldmatrix.sync.aligned.m8n8.x2.shared.b16 {%0,%1}, [%2];"
                 : "=r"(r0), "=r"(r1) : "r"(addr));
}
__device__ __forceinline__ void mma16816(float* c, const uint32_t* a, const uint32_t* b) {
    asm volatile("mma.sync.aligned.m16n8k16.row.col.f32.f16.f16.f32 "
                 "{%0,%1,%2,%3}, {%4,%5,%6,%7}, {%8,%9}, {%0,%1,%2,%3};"
                 : "+f"(c[0]), "+f"(c[1]), "+f"(c[2]), "+f"(c[3])
                 : "r"(a[0]), "r"(a[1]), "r"(a[2]), "r"(a[3]), "r"(b[0]), "r"(b[1]));
}
__device__ __forceinline__ void cp16(uint32_t dst, const void* src, unsigned sz) {
    asm volatile("cp.async.cg.shared.global [%0], [%1], 16, %2;"
                 :: "r"(dst), "l"(src), "r"(sz) : "memory");
}
#define CP_COMMIT() asm volatile("cp.async.commit_group;" ::: "memory")
#define CP_WAIT1()  asm volatile("cp.async.wait_group 1;" ::: "memory")
#define CP_WAIT0()  asm volatile("cp.async.wait_group 0;" ::: "memory")

__device__ __forceinline__ void split1(float v, __half& h, __half& l) {
    h = __float2half_rn(v);
    l = __float2half_rn(v - __half2float(h));
}

// ---------------- CSR build ----------------
__global__ void k_zero_deg() {
    int i = blockIdx.x * blockDim.x + threadIdx.x;
    if (i < NN) g_cursor[i] = 0;
}
__global__ void k_count_deg(const int* __restrict__ row) {
    int e = blockIdx.x * blockDim.x + threadIdx.x;
    if (e < NE) atomicAdd(&g_cursor[row[e]], 1);
}
__global__ __launch_bounds__(SCAN_B) void k_scan_part() {
    __shared__ int sh[SCAN_B / 32];
    int t = threadIdx.x;
    int idx = blockIdx.x * SCAN_B + t;
    int v = (idx < NN) ? g_cursor[idx] : 0;
#pragma unroll
    for (int off = 16; off > 0; off >>= 1) v += __shfl_down_sync(0xffffffffu, v, off);
    if ((t & 31) == 0) sh[t >> 5] = v;
    __syncthreads();
    if (t < 32) {
        int s = (t < SCAN_B / 32) ? sh[t] : 0;
#pragma unroll
        for (int off = 16; off > 0; off >>= 1) s += __shfl_down_sync(0xffffffffu, s, off);
        if (t == 0) g_partial[blockIdx.x] = s;
    }
}
__global__ __launch_bounds__(128) void k_scan_mid() {
    __shared__ int sh[128];
    int t = threadIdx.x;
    int v = (t < NBLK) ? g_partial[t] : 0;
    sh[t] = v;
    __syncthreads();
#pragma unroll
    for (int off = 1; off < 128; off <<= 1) {
        int y = (t >= off) ? sh[t - off] : 0;
        __syncthreads();
        sh[t] += y;
        __syncthreads();
    }
    if (t < NBLK) g_blockoff[t] = sh[t] - v;
}
__global__ __launch_bounds__(SCAN_B) void k_scan_final() {
    __shared__ int sh[SCAN_B];
    int t = threadIdx.x;
    int idx = blockIdx.x * SCAN_B + t;
    int v = (idx < NN) ? g_cursor[idx] : 0;
    sh[t] = v;
    __syncthreads();
#pragma unroll
    for (int off = 1; off < SCAN_B; off <<= 1) {
        int y = (t >= off) ? sh[t - off] : 0;
        __syncthreads();
        sh[t] += y;
        __syncthreads();
    }
    if (idx < NN) {
        int incl = sh[t] + g_blockoff[blockIdx.x];
        g_rowptr[idx + 1] = incl;
        g_cursor[idx] = incl - v;
    }
    if (idx == 0) g_rowptr[0] = 0;
}
__global__ void k_scatter_edges(const int* __restrict__ row, const int* __restrict__ col,
                                const float* __restrict__ w) {
    int e = blockIdx.x * blockDim.x + threadIdx.x;
    if (e < NE) {
        int pos = atomicAdd(&g_cursor[row[e]], 1);
        g_pcol[pos] = col[e];
        g_pw[pos]   = w[e];
    }
}

// ---------------- converters ----------------
__global__ void k_convert_x(const float* __restrict__ x) {
    int i = blockIdx.x * blockDim.x + threadIdx.x;
    if (i < NN * 128) {
        __half h, l;
        split1(x[i], h, l);
        g_ahi[i] = h;
        g_alo[i] = l;
    }
}
__global__ void k_convert_weights(const float* w0, const float* w1_, const float* w2_,
                                  const float* w3, const float* w4, const float* w5,
                                  const float* wdec) {
    int idx = blockIdx.x * blockDim.x + threadIdx.x;
    if (idx >= W_TOTAL) return;
    float v;
    if (idx < W_NODE_ELEMS) {
        int m = idx >> 14;
        int e = idx & 16383;
        int n = e >> 7, k = e & 127;
        const float* W = (m == 0) ? w0 : (m == 1) ? w1_ : (m == 2) ? w2_
                       : (m == 3) ? w3 : (m == 4) ? w4 : w5;
        v = W[k * 128 + n];
    } else {
        int e = idx - W_NODE_ELEMS;
        int n = e >> 8, k = e & 255;
        v = wdec[k * 128 + n];
    }
    __half h, l;
    split1(v, h, l);
    g_whi[idx] = h;
    g_wlo[idx] = l;
}

// ---------------- neighbor aggregation ----------------
__global__ __launch_bounds__(128) void k_aggregate(float* __restrict__ outf, int relu, int writef) {
    int node = blockIdx.x;
    int f = threadIdx.x;
    size_t idx = (size_t)node * 128 + f;
    float a0 = g_selfb[idx];
    float a1 = 0.f, a2 = 0.f, a3 = 0.f;
    int s = g_rowptr[node];
    int e = g_rowptr[node + 1];
    int i = s;
    for (; i + 3 < e; i += 4) {
        int c0 = g_pcol[i], c1 = g_pcol[i + 1], c2 = g_pcol[i + 2], c3 = g_pcol[i + 3];
        float w0 = g_pw[i], w1 = g_pw[i + 1], w2 = g_pw[i + 2], w3 = g_pw[i + 3];
        a0 += w0 * __half2float(g_suph[(size_t)c0 * 128 + f]);
        a1 += w1 * __half2float(g_suph[(size_t)c1 * 128 + f]);
        a2 += w2 * __half2float(g_suph[(size_t)c2 * 128 + f]);
        a3 += w3 * __half2float(g_suph[(size_t)c3 * 128 + f]);
    }
    for (; i < e; i++)
        a0 += g_pw[i] * __half2float(g_suph[(size_t)g_pcol[i] * 128 + f]);
    float acc = (a0 + a1) + (a2 + a3);
    if (relu) acc = fmaxf(acc, 0.f);
    if (writef) outf[idx] = acc;
    __half h, l;
    split1(acc, h, l);
    g_ahi[idx] = h;
    g_alo[idx] = l;
}

// ---------------- persistent node GEMM: 512 thr, mat-split warps, 3-stage ----------------
#define NO_BIAS  0                               // 512
#define NO_WSHI  1024
#define NO_WSLO  (NO_WSHI + 128 * PK128 * 2)     // +34816
#define NO_WNHI  (NO_WSLO + 128 * PK128 * 2)
#define NO_A0    (NO_WNHI + 128 * PK128 * 2)     // 3 stages of (hi 17408 + lo 17408)
#define NO_ASTG  (64 * PK128 * 2)                // 17408
#define NO_STAGE (2 * NO_ASTG)                   // 34816 per stage
#define NO_SMEM  (NO_A0 + 3 * NO_STAGE)          // 209920

#define NODE_TILES ((NN + 63) / 64)              // 1563

__device__ __forceinline__ void issue_node_tile(int rowBase, uint32_t smHi, uint32_t smLo, int tid) {
    int r = tid >> 3;               // 0..63
    int u0 = (tid & 7) * 2;         // units 0..15
    long long gr = (long long)rowBase + r;
    unsigned sz = (gr < NN) ? 16u : 0u;
    long long grc = gr < NN ? gr : (NN - 1);
    const char* srcH = (const char*)g_ahi + grc * 256;
    const char* srcL = (const char*)g_alo + grc * 256;
    uint32_t drow = (uint32_t)r * (PK128 * 2);
#pragma unroll
    for (int q = 0; q < 2; q++) {
        uint32_t o = (u0 + q) * 16;
        cp16(smHi + drow + o, srcH + o, sz);
        cp16(smLo + drow + o, srcL + o, sz);
    }
}

__global__ __launch_bounds__(512, 1) void k_mm_node(
    int wsel, const float* __restrict__ bias, float* __restrict__ Cself)
{
    extern __shared__ char sm[];
    uint32_t sb = smem_u32(sm);
    int tid = threadIdx.x;
    int lane = tid & 31, w = tid >> 5;
    int mat   = w & 1;            // 0 = self (3-term), 1 = support (2-term)
    int warpN = (w >> 1) & 3;     // 32-col group
    int warpM = (w >> 3) & 1;     // 32-row group

    if (tid < 128) ((float*)(sm + NO_BIAS))[tid] = bias[tid];
    {
        const uint4* whS = (const uint4*)(g_whi + (size_t)(2 * wsel) * 16384);
        const uint4* wlS = (const uint4*)(g_wlo + (size_t)(2 * wsel) * 16384);
        const uint4* whN = (const uint4*)(g_whi + (size_t)(2 * wsel + 1) * 16384);
        for (int idx = tid; idx < 2048; idx += 512) {
            int r = idx >> 4, u = idx & 15;
            uint32_t off = r * (PK128 * 2) + u * 16;
            *(uint4*)(sm + NO_WSHI + off) = whS[idx];
            *(uint4*)(sm + NO_WSLO + off) = wlS[idx];
            *(uint4*)(sm + NO_WNHI + off) = whN[idx];
        }
    }

    uint32_t stg[3] = { sb + NO_A0, sb + NO_A0 + NO_STAGE, sb + NO_A0 + 2 * NO_STAGE };
    const float* sbias = (const float*)(sm + NO_BIAS);

    uint32_t aRow = warpM * 32 + (lane & 15);
    uint32_t aColSel = (lane >> 4) * 8;
    uint32_t aOff0 = (aRow * PK128 + aColSel) * 2;
    uint32_t aOff1 = ((aRow + 16) * PK128 + aColSel) * 2;
    uint32_t bRow = warpN * 32 + (lane & 7);
    uint32_t bColSel = ((lane >> 3) & 1) * 8;
    uint32_t bOffBase = (bRow * PK128 + bColSel) * 2;
    uint32_t bHiBase = (mat ? (sb + NO_WNHI) : (sb + NO_WSHI)) + bOffBase;
    uint32_t bLoBase = (sb + NO_WSLO) + bOffBase;

    int g = gridDim.x;
    int t = blockIdx.x;
    int s = 0;
    issue_node_tile(t * 64, stg[0], stg[0] + NO_ASTG, tid);
    CP_COMMIT();
    issue_node_tile((t + g) * 64, stg[1], stg[1] + NO_ASTG, tid);
    CP_COMMIT();
    __syncthreads();   // weights + bias visible

    while (t < NODE_TILES) {
        CP_WAIT1();
        __syncthreads();

        int s2i = (s >= 1) ? (s - 1) : 2;   // == (s+2)%3
        issue_node_tile((t + 2 * g) * 64, stg[s2i], stg[s2i] + NO_ASTG, tid);
        CP_COMMIT();

        float acc[2][4][4];
#pragma unroll
        for (int mt = 0; mt < 2; mt++)
#pragma unroll
            for (int nt = 0; nt < 4; nt++)
#pragma unroll
                for (int q = 0; q < 4; q++) acc[mt][nt][q] = 0.f;

        uint32_t asH = stg[s], asL = stg[s] + NO_ASTG;
#pragma unroll
        for (int ks = 0; ks < 8; ks++) {
            uint32_t kadd = ks * 32;
            uint32_t aH[2][4], aL[2][4];
            ldsm_x4(aH[0][0], aH[0][1], aH[0][2], aH[0][3], asH + aOff0 + kadd);
            ldsm_x4(aH[1][0], aH[1][1], aH[1][2], aH[1][3], asH + aOff1 + kadd);
            ldsm_x4(aL[0][0], aL[0][1], aL[0][2], aL[0][3], asL + aOff0 + kadd);
            ldsm_x4(aL[1][0], aL[1][1], aL[1][2], aL[1][3], asL + aOff1 + kadd);
#pragma unroll
            for (int nt = 0; nt < 4; nt++) {
                uint32_t bo = nt * 8 * PK128 * 2 + kadd;
                uint32_t bH[2];
                ldsm_x2(bH[0], bH[1], bHiBase + bo);
                mma16816(acc[0][nt], aH[0], bH);
                mma16816(acc[1][nt], aH[1], bH);
                mma16816(acc[0][nt], aL[0], bH);
                mma16816(acc[1][nt], aL[1], bH);
                if (!mat) {
                    uint32_t bL[2];
                    ldsm_x2(bL[0], bL[1], bLoBase + bo);
                    mma16816(acc[0][nt], aH[0], bL);
                    mma16816(acc[1][nt], aH[1], bL);
                }
            }
        }

        int base = t * 64;
        if (!mat) {
#pragma unroll
            for (int mt = 0; mt < 2; mt++) {
                int r0 = base + warpM * 32 + mt * 16 + (lane >> 2);
#pragma unroll
                for (int nt = 0; nt < 4; nt++) {
                    int c = warpN * 32 + nt * 8 + (lane & 3) * 2;
                    if (r0 < NN)
                        *(float2*)(Cself + (size_t)r0 * 128 + c) =
                            make_float2(acc[mt][nt][0] + sbias[c], acc[mt][nt][1] + sbias[c + 1]);
                    if (r0 + 8 < NN)
                        *(float2*)(Cself + (size_t)(r0 + 8) * 128 + c) =
                            make_float2(acc[mt][nt][2] + sbias[c], acc[mt][nt][3] + sbias[c + 1]);
                }
            }
        } else {
#pragma unroll
            for (int mt = 0; mt < 2; mt++) {
                int r0 = base + warpM * 32 + mt * 16 + (lane >> 2);
#pragma unroll
                for (int nt = 0; nt < 4; nt++) {
                    int c = warpN * 32 + nt * 8 + (lane & 3) * 2;
                    if (r0 < NN)
                        *(__half2*)(&g_suph[(size_t)r0 * 128 + c]) =
                            __halves2half2(__float2half_rn(acc[mt][nt][0]),
                                           __float2half_rn(acc[mt][nt][1]));
                    if (r0 + 8 < NN)
                        *(__half2*)(&g_suph[(size_t)(r0 + 8) * 128 + c]) =
                            __halves2half2(__float2half_rn(acc[mt][nt][2]),
                                           __float2half_rn(acc[mt][nt][3]));
                }
            }
        }
        t += g;
        s = (s + 1 == 3) ? 0 : (s + 1);
    }
}

// ---------------- persistent fused decoder: 512 thr, 128-pair tiles, 2-stage ----------------
#define DO_B1   0       // 512
#define DO_W2   512     // 512
#define DO_RED  1024    // 128*16*4 = 8192
#define DO_W1HI 9216
#define DO_W1LO (DO_W1HI + 128 * PK256 * 2)      // +67584
#define DO_A0   (DO_W1LO + 128 * PK256 * 2)      // 144384
#define DO_ASTG (128 * PK128 * 2)                // 34816 (hi only, 128 pairs)
#define DO_A1   (DO_A0 + DO_ASTG)
#define DO_SMEM (DO_A1 + DO_ASTG)                // 214016

#define DEC_TILES ((NP + 127) / 128)             // 3907

__device__ __forceinline__ void issue_dec_stage(int tile, int chunk,
                                                const int* __restrict__ xidx,
                                                const int* __restrict__ yidx,
                                                uint32_t smHi, int tid) {
    int r = tid >> 2;               // 0..127
    int u0 = (tid & 3) * 4;         // units 0..15
    int pp = tile * 128 + r;
    if (pp >= NP) pp = NP - 1;
    const int* idx = chunk ? yidx : xidx;
    int node = idx[pp];
    const char* srcH = (const char*)g_ahi + (size_t)node * 256;
    uint32_t drow = (uint32_t)r * (PK128 * 2);
#pragma unroll
    for (int q = 0; q < 4; q++) {
        uint32_t o = (u0 + q) * 16;
        cp16(smHi + drow + o, srcH + o, 16u);
    }
}

__global__ __launch_bounds__(512, 1) void k_mm_decoder(
    const int* __restrict__ xidx, const int* __restrict__ yidx,
    const float* __restrict__ b1, const float* __restrict__ w2, const float* __restrict__ b2,
    float* __restrict__ p)
{
    extern __shared__ char sm[];
    uint32_t sb = smem_u32(sm);
    int tid = threadIdx.x;
    int lane = tid & 31, w = tid >> 5;
    int warpM = w & 3;        // 32-row group (4 x 32 = 128 pairs)
    int warpN = w >> 2;       // 32-col group (4 x 32 = 128 hid)

    if (tid < 128) {
        ((float*)(sm + DO_B1))[tid] = b1[tid];
        ((float*)(sm + DO_W2))[tid] = w2[tid];
    }
    {
        const uint4* wh = (const uint4*)(g_whi + W_NODE_ELEMS);
        const uint4* wl = (const uint4*)(g_wlo + W_NODE_ELEMS);
        for (int idx = tid; idx < 4096; idx += 512) {
            int r = idx >> 5, u = idx & 31;
            uint32_t off = r * (PK256 * 2) + u * 16;
            *(uint4*)(sm + DO_W1HI + off) = wh[idx];
            *(uint4*)(sm + DO_W1LO + off) = wl[idx];
        }
    }

    uint32_t stg[2] = { sb + DO_A0, sb + DO_A1 };
    const float* sb1 = (const float*)(sm + DO_B1);
    const float* sw2 = (const float*)(sm + DO_W2);
    float* red = (float*)(sm + DO_RED);
    float b2v = __ldg(b2);

    uint32_t aRow = warpM * 32 + (lane & 15);
    uint32_t aColSel = (lane >> 4) * 8;
    uint32_t aOff0 = (aRow * PK128 + aColSel) * 2;
    uint32_t aOff1 = ((aRow + 16) * PK128 + aColSel) * 2;
    uint32_t bRow = warpN * 32 + (lane & 7);
    uint32_t bColSel = ((lane >> 3) & 1) * 8;
    uint32_t bOffBase = (bRow * PK256 + bColSel) * 2;

    float acc[2][4][4];
#pragma unroll
    for (int mt = 0; mt < 2; mt++)
#pragma unroll
        for (int nt = 0; nt < 4; nt++)
#pragma unroll
            for (int q = 0; q < 4; q++) acc[mt][nt][q] = 0.f;

    int g = gridDim.x;
    int t = blockIdx.x;
    int c = 0;
    int buf = 0;
    if (t < DEC_TILES) {
        issue_dec_stage(t, 0, xidx, yidx, stg[0], tid);
        CP_COMMIT();
    }
    __syncthreads();   // W1/b1/w2 visible

    while (t < DEC_TILES) {
        int nt_ = t, nc = c + 1;
        if (nc == 2) { nc = 0; nt_ = t + g; }
        if (nt_ < DEC_TILES) {
            issue_dec_stage(nt_, nc, xidx, yidx, stg[buf ^ 1], tid);
            CP_COMMIT();
            CP_WAIT1();
        } else {
            CP_WAIT0();
        }
        __syncthreads();

        uint32_t asH = stg[buf];
        uint32_t kChunk = c * 256;   // byte offset into W1 K dim
#pragma unroll
        for (int ks = 0; ks < 8; ks++) {
            uint32_t kadd = ks * 32;
            uint32_t aH[2][4];
            ldsm_x4(aH[0][0], aH[0][1], aH[0][2], aH[0][3], asH + aOff0 + kadd);
            ldsm_x4(aH[1][0], aH[1][1], aH[1][2], aH[1][3], asH + aOff1 + kadd);
#pragma unroll
            for (int nt2 = 0; nt2 < 4; nt2++) {
                uint32_t bo = bOffBase + nt2 * 8 * PK256 * 2 + kChunk + kadd;
                uint32_t bH[2], bL[2];
                ldsm_x2(bH[0], bH[1], sb + DO_W1HI + bo);
                ldsm_x2(bL[0], bL[1], sb + DO_W1LO + bo);
                mma16816(acc[0][nt2], aH[0], bH);
                mma16816(acc[1][nt2], aH[1], bH);
                mma16816(acc[0][nt2], aH[0], bL);
                mma16816(acc[1][nt2], aH[1], bL);
            }
        }

        if (c == 1) {
            // epilogue: relu + fc2 partial dot + cross-warp reduction + sigmoid
#pragma unroll
            for (int mt = 0; mt < 2; mt++) {
                int rl = warpM * 32 + mt * 16 + (lane >> 2);
                float p0 = 0.f, p1 = 0.f;
#pragma unroll
                for (int nt2 = 0; nt2 < 4; nt2++) {
                    int cc = warpN * 32 + nt2 * 8 + (lane & 3) * 2;
                    float h00 = fmaxf(acc[mt][nt2][0] + sb1[cc], 0.f);
                    float h01 = fmaxf(acc[mt][nt2][1] + sb1[cc + 1], 0.f);
                    float h10 = fmaxf(acc[mt][nt2][2] + sb1[cc], 0.f);
                    float h11 = fmaxf(acc[mt][nt2][3] + sb1[cc + 1], 0.f);
                    p0 += h00 * sw2[cc] + h01 * sw2[cc + 1];
                    p1 += h10 * sw2[cc] + h11 * sw2[cc + 1];
                }
                red[rl * 16 + warpN * 4 + (lane & 3)] = p0;
                red[(rl + 8) * 16 + warpN * 4 + (lane & 3)] = p1;
            }
            __syncthreads();
            if (tid < 128) {
                float sacc = 0.f;
#pragma unroll
                for (int j = 0; j < 16; j++) sacc += red[tid * 16 + j];
                sacc += b2v;
                float pv = 1.f / (1.f + expf(-sacc));
                int pp = t * 128 + tid;
                if (pp < NP) p[pp] = pv;
            }
#pragma unroll
            for (int mt = 0; mt < 2; mt++)
#pragma unroll
                for (int nt2 = 0; nt2 < 4; nt2++)
#pragma unroll
                    for (int q = 0; q < 4; q++) acc[mt][nt2][q] = 0.f;
        }
        __syncthreads();
        buf ^= 1;
        c = nc;
        t = nt_;
    }
}

// ---------------- launch ----------------
extern "C" void kernel_launch(void* const* d_in, const int* in_sizes, int n_in,
                              void* d_out, int out_size) {
    const float* x     = (const float*)d_in[0];
    const int*   erow  = (const int*)  d_in[1];
    const int*   ecol  = (const int*)  d_in[2];
    const float* ew    = (const float*)d_in[3];
    const int*   xidx  = (const int*)  d_in[4];
    const int*   yidx  = (const int*)  d_in[5];
    const float* ws[3] = { (const float*)d_in[6],  (const float*)d_in[9],  (const float*)d_in[12] };
    const float* wn[3] = { (const float*)d_in[7],  (const float*)d_in[10], (const float*)d_in[13] };
    const float* bb[3] = { (const float*)d_in[8],  (const float*)d_in[11], (const float*)d_in[14] };
    const float* dw1 = (const float*)d_in[15];
    const float* db1 = (const float*)d_in[16];
    const float* dw2 = (const float*)d_in[17];
    const float* db2 = (const float*)d_in[18];

    float* out = (float*)d_out;
    float* p_out = out;            // [NP]
    float* z_out = out + NP;       // [NN*128]

    void* ptr;
    cudaGetSymbolAddress(&ptr, g_selfb);   float* selfb_buf = (float*)ptr;

    int nsm = 148;
    cudaDeviceGetAttribute(&nsm, cudaDevAttrMultiProcessorCount, 0);

    cudaFuncSetAttribute(k_mm_node, cudaFuncAttributeMaxDynamicSharedMemorySize, NO_SMEM);
    cudaFuncSetAttribute(k_mm_decoder, cudaFuncAttributeMaxDynamicSharedMemorySize, DO_SMEM);

    // side stream for the CSR build (independent of converts + layer-1 GEMM)
    cudaStream_t s2;
    cudaStreamCreateWithFlags(&s2, cudaStreamNonBlocking);
    cudaEvent_t eFork, eJoin;
    cudaEventCreateWithFlags(&eFork, cudaEventDisableTiming);
    cudaEventCreateWithFlags(&eJoin, cudaEventDisableTiming);

    cudaEventRecord(eFork, 0);
    cudaStreamWaitEvent(s2, eFork, 0);

    // main stream: converts + layer-1 GEMM (launch #4 overall = mm_node, for ncu)
    k_convert_x<<<(NN * 128 + 255) / 256, 256>>>(x);                                        // 1
    k_convert_weights<<<(W_TOTAL + 255) / 256, 256>>>(ws[0], wn[0], ws[1], wn[1], ws[2], wn[2], dw1); // 2
    k_zero_deg<<<(NN + 255) / 256, 256, 0, s2>>>();                                         // 3 (s2)
    k_mm_node<<<nsm, 512, NO_SMEM>>>(0, bb[0], selfb_buf);                                  // 4 <- profiled
    // CSR chain on s2
    k_count_deg<<<(NE + 255) / 256, 256, 0, s2>>>(erow);                                    // 5
    k_scan_part<<<NBLK, SCAN_B, 0, s2>>>();                                                 // 6
    k_scan_mid<<<1, 128, 0, s2>>>();                                                        // 7
    k_scan_final<<<NBLK, SCAN_B, 0, s2>>>();                                                // 8
    k_scatter_edges<<<(NE + 255) / 256, 256, 0, s2>>>(erow, ecol, ew);                      // 9
    cudaEventRecord(eJoin, s2);
    cudaStreamWaitEvent(0, eJoin, 0);

    k_aggregate<<<NN, 128>>>(nullptr, 1, 0);                                                // 10
    k_mm_node<<<nsm, 512, NO_SMEM>>>(1, bb[1], selfb_buf);                                  // 11
    k_aggregate<<<NN, 128>>>(nullptr, 1, 0);                                                // 12
    k_mm_node<<<nsm, 512, NO_SMEM>>>(2, bb[2], selfb_buf);                                  // 13
    k_aggregate<<<NN, 128>>>(z_out, 0, 1);                                                  // 14
    k_mm_decoder<<<nsm, 512, DO_SMEM>>>(xidx, yidx, db1, dw2, db2, p_out);                  // 15
}

// round 11
// speedup vs baseline: 2.9940x; 1.3776x over previous
#include <cuda_runtime.h>
#include <cuda_fp16.h>
#include <math.h>
#include <stdint.h>

#define NN 100000
#define NE 1600000
#define NP 500000
#define SCAN_B 1024
#define NBLK ((NN + SCAN_B - 1) / SCAN_B)   // 98

// ---------------- static device scratch ----------------
__device__ float  g_selfb[(size_t)NN * 128];
__device__ __half g_suph[(size_t)NN * 128];   // h @ Wn in fp16 (gathered operand)
__device__ __half g_ahi[(size_t)NN * 128];    // activation hi
__device__ __half g_alo[(size_t)NN * 128];    // activation lo
__device__ int   g_rowptr[NN + 1];
__device__ int   g_cursor[NN];
__device__ int   g_partial[NBLK];
__device__ int   g_blockoff[NBLK];
__device__ int   g_pcol[NE];
__device__ float g_pw[NE];
#define W_NODE_ELEMS (6 * 16384)
#define W_TOTAL (W_NODE_ELEMS + 32768)
__device__ __half g_whi[W_TOTAL];
__device__ __half g_wlo[W_TOTAL];

#define PK128 136
#define PK256 264

// ---------------- helpers ----------------
__device__ __forceinline__ uint32_t smem_u32(const void* p) {
    uint32_t a;
    asm("{ .reg .u64 t; cvta.to.shared.u64 t, %1; cvt.u32.u64 %0, t; }" : "=r"(a) : "l"(p));
    return a;
}
__device__ __forceinline__ void ldsm_x4(uint32_t& r0, uint32_t& r1, uint32_t& r2, uint32_t& r3,
                                        uint32_t addr) {
    asm volatile("ldmatrix.sync.aligned.m8n8.x4.shared.b16 {%0,%1,%2,%3}, [%4];"
                 : "=r"(r0), "=r"(r1), "=r"(r2), "=r"(r3) : "r"(addr));
}
__device__ __forceinline__ void ldsm_x2(uint32_t& r0, uint32_t& r1, uint32_t addr) {
    asm volatile("ldmatrix.sync.aligned.m8n8.x2.shared.b16 {%0,%1}, [%2];"
                 : "=r"(r0), "=r"(r1) : "r"(addr));
}
__device__ __forceinline__ void mma16816(float* c, const uint32_t* a, const uint32_t* b) {
    asm volatile("mma.sync.aligned.m16n8k16.row.col.f32.f16.f16.f32 "
                 "{%0,%1,%2,%3}, {%4,%5,%6,%7}, {%8,%9}, {%0,%1,%2,%3};"
                 : "+f"(c[0]), "+f"(c[1]), "+f"(c[2]), "+f"(c[3])
                 : "r"(a[0]), "r"(a[1]), "r"(a[2]), "r"(a[3]), "r"(b[0]), "r"(b[1]));
}
__device__ __forceinline__ void cp16(uint32_t dst, const void* src, unsigned sz) {
    asm volatile("cp.async.cg.shared.global [%0], [%1], 16, %2;"
                 :: "r"(dst), "l"(src), "r"(sz) : "memory");
}
#define CP_COMMIT() asm volatile("cp.async.commit_group;" ::: "memory")
#define CP_WAIT1()  asm volatile("cp.async.wait_group 1;" ::: "memory")
#define CP_WAIT0()  asm volatile("cp.async.wait_group 0;" ::: "memory")

__device__ __forceinline__ void split1(float v, __half& h, __half& l) {
    h = __float2half_rn(v);
    l = __float2half_rn(v - __half2float(h));
}

// ---------------- CSR build ----------------
__global__ void k_zero_deg() {
    int i = blockIdx.x * blockDim.x + threadIdx.x;
    if (i < NN) g_cursor[i] = 0;
}
__global__ void k_count_deg(const int* __restrict__ row) {
    int e = blockIdx.x * blockDim.x + threadIdx.x;
    if (e < NE) atomicAdd(&g_cursor[row[e]], 1);
}
__global__ __launch_bounds__(SCAN_B) void k_scan_part() {
    __shared__ int sh[SCAN_B / 32];
    int t = threadIdx.x;
    int idx = blockIdx.x * SCAN_B + t;
    int v = (idx < NN) ? g_cursor[idx] : 0;
#pragma unroll
    for (int off = 16; off > 0; off >>= 1) v += __shfl_down_sync(0xffffffffu, v, off);
    if ((t & 31) == 0) sh[t >> 5] = v;
    __syncthreads();
    if (t < 32) {
        int s = (t < SCAN_B / 32) ? sh[t] : 0;
#pragma unroll
        for (int off = 16; off > 0; off >>= 1) s += __shfl_down_sync(0xffffffffu, s, off);
        if (t == 0) g_partial[blockIdx.x] = s;
    }
}
__global__ __launch_bounds__(128) void k_scan_mid() {
    __shared__ int sh[128];
    int t = threadIdx.x;
    int v = (t < NBLK) ? g_partial[t] : 0;
    sh[t] = v;
    __syncthreads();
#pragma unroll
    for (int off = 1; off < 128; off <<= 1) {
        int y = (t >= off) ? sh[t - off] : 0;
        __syncthreads();
        sh[t] += y;
        __syncthreads();
    }
    if (t < NBLK) g_blockoff[t] = sh[t] - v;
}
__global__ __launch_bounds__(SCAN_B) void k_scan_final() {
    __shared__ int sh[SCAN_B];
    int t = threadIdx.x;
    int idx = blockIdx.x * SCAN_B + t;
    int v = (idx < NN) ? g_cursor[idx] : 0;
    sh[t] = v;
    __syncthreads();
#pragma unroll
    for (int off = 1; off < SCAN_B; off <<= 1) {
        int y = (t >= off) ? sh[t - off] : 0;
        __syncthreads();
        sh[t] += y;
        __syncthreads();
    }
    if (idx < NN) {
        int incl = sh[t] + g_blockoff[blockIdx.x];
        g_rowptr[idx + 1] = incl;
        g_cursor[idx] = incl - v;
    }
    if (idx == 0) g_rowptr[0] = 0;
}
__global__ void k_scatter_edges(const int* __restrict__ row, const int* __restrict__ col,
                                const float* __restrict__ w) {
    int e = blockIdx.x * blockDim.x + threadIdx.x;
    if (e < NE) {
        int pos = atomicAdd(&g_cursor[row[e]], 1);
        g_pcol[pos] = col[e];
        g_pw[pos]   = w[e];
    }
}

// ---------------- converters ----------------
__global__ void k_convert_x(const float* __restrict__ x) {
    int i = blockIdx.x * blockDim.x + threadIdx.x;   // handles 4 floats
    if (i < NN * 32) {
        float4 v = *(const float4*)(x + (size_t)i * 4);
        __half h0, h1, h2, h3, l0, l1, l2, l3;
        split1(v.x, h0, l0); split1(v.y, h1, l1);
        split1(v.z, h2, l2); split1(v.w, h3, l3);
        __half2 H01 = __halves2half2(h0, h1), H23 = __halves2half2(h2, h3);
        __half2 L01 = __halves2half2(l0, l1), L23 = __halves2half2(l2, l3);
        uint2 uh, ul;
        uh.x = *reinterpret_cast<unsigned*>(&H01); uh.y = *reinterpret_cast<unsigned*>(&H23);
        ul.x = *reinterpret_cast<unsigned*>(&L01); ul.y = *reinterpret_cast<unsigned*>(&L23);
        *(uint2*)(g_ahi + (size_t)i * 4) = uh;
        *(uint2*)(g_alo + (size_t)i * 4) = ul;
    }
}
__global__ void k_convert_weights(const float* w0, const float* w1_, const float* w2_,
                                  const float* w3, const float* w4, const float* w5,
                                  const float* wdec) {
    int idx = blockIdx.x * blockDim.x + threadIdx.x;
    if (idx >= W_TOTAL) return;
    float v;
    if (idx < W_NODE_ELEMS) {
        int m = idx >> 14;
        int e = idx & 16383;
        int n = e >> 7, k = e & 127;
        const float* W = (m == 0) ? w0 : (m == 1) ? w1_ : (m == 2) ? w2_
                       : (m == 3) ? w3 : (m == 4) ? w4 : w5;
        v = W[k * 128 + n];
    } else {
        int e = idx - W_NODE_ELEMS;
        int n = e >> 8, k = e & 255;
        v = wdec[k * 128 + n];
    }
    __half h, l;
    split1(v, h, l);
    g_whi[idx] = h;
    g_wlo[idx] = l;
}

// ---------------- neighbor aggregation: warp-per-node, 8B vector gathers ----------------
__global__ __launch_bounds__(128) void k_aggregate(float* __restrict__ outf, int relu, int writef) {
    int warp = threadIdx.x >> 5;
    int lane = threadIdx.x & 31;
    int node = blockIdx.x * 4 + warp;
    if (node >= NN) return;
    size_t base = (size_t)node * 128 + lane * 4;

    float4 sv = *(const float4*)(g_selfb + base);
    float a0 = sv.x, a1 = sv.y, a2 = sv.z, a3 = sv.w;

    int s = g_rowptr[node];
    int e = g_rowptr[node + 1];
    for (int i0 = s; i0 < e; i0 += 32) {
        int n = e - i0;
        if (n > 32) n = 32;
        int   c  = 0;
        float wv = 0.f;
        if (lane < n) { c = g_pcol[i0 + lane]; wv = g_pw[i0 + lane]; }
        for (int j = 0; j < n; j++) {
            int   cj = __shfl_sync(0xffffffffu, c, j);
            float wj = __shfl_sync(0xffffffffu, wv, j);
            uint2 hv = *(const uint2*)(g_suph + (size_t)cj * 128 + lane * 4);
            __half2 h01 = *reinterpret_cast<__half2*>(&hv.x);
            __half2 h23 = *reinterpret_cast<__half2*>(&hv.y);
            float2 f01 = __half22float2(h01);
            float2 f23 = __half22float2(h23);
            a0 += wj * f01.x; a1 += wj * f01.y;
            a2 += wj * f23.x; a3 += wj * f23.y;
        }
    }
    if (relu) {
        a0 = fmaxf(a0, 0.f); a1 = fmaxf(a1, 0.f);
        a2 = fmaxf(a2, 0.f); a3 = fmaxf(a3, 0.f);
    }
    if (writef) *(float4*)(outf + base) = make_float4(a0, a1, a2, a3);
    __half h0, h1, h2, h3, l0, l1, l2, l3;
    split1(a0, h0, l0); split1(a1, h1, l1);
    split1(a2, h2, l2); split1(a3, h3, l3);
    __half2 H01 = __halves2half2(h0, h1), H23 = __halves2half2(h2, h3);
    __half2 L01 = __halves2half2(l0, l1), L23 = __halves2half2(l2, l3);
    uint2 uh, ul;
    uh.x = *reinterpret_cast<unsigned*>(&H01); uh.y = *reinterpret_cast<unsigned*>(&H23);
    ul.x = *reinterpret_cast<unsigned*>(&L01); ul.y = *reinterpret_cast<unsigned*>(&L23);
    *(uint2*)(g_ahi + base) = uh;
    *(uint2*)(g_alo + base) = ul;
}

// ---------------- persistent node GEMM: 512 thr, mat-split warps, 3-stage ----------------
#define NO_BIAS  0                               // 512
#define NO_WSHI  1024
#define NO_WSLO  (NO_WSHI + 128 * PK128 * 2)     // +34816
#define NO_WNHI  (NO_WSLO + 128 * PK128 * 2)
#define NO_A0    (NO_WNHI + 128 * PK128 * 2)     // 3 stages of (hi 17408 + lo 17408)
#define NO_ASTG  (64 * PK128 * 2)                // 17408
#define NO_STAGE (2 * NO_ASTG)                   // 34816 per stage
#define NO_SMEM  (NO_A0 + 3 * NO_STAGE)          // 209920

#define NODE_TILES ((NN + 63) / 64)              // 1563

__device__ __forceinline__ void issue_node_tile(int rowBase, uint32_t smHi, uint32_t smLo, int tid) {
    int r = tid >> 3;               // 0..63
    int u0 = (tid & 7) * 2;         // units 0..15
    long long gr = (long long)rowBase + r;
    unsigned sz = (gr < NN) ? 16u : 0u;
    long long grc = gr < NN ? gr : (NN - 1);
    const char* srcH = (const char*)g_ahi + grc * 256;
    const char* srcL = (const char*)g_alo + grc * 256;
    uint32_t drow = (uint32_t)r * (PK128 * 2);
#pragma unroll
    for (int q = 0; q < 2; q++) {
        uint32_t o = (u0 + q) * 16;
        cp16(smHi + drow + o, srcH + o, sz);
        cp16(smLo + drow + o, srcL + o, sz);
    }
}

__global__ __launch_bounds__(512, 1) void k_mm_node(
    int wsel, const float* __restrict__ bias, float* __restrict__ Cself)
{
    extern __shared__ char sm[];
    uint32_t sb = smem_u32(sm);
    int tid = threadIdx.x;
    int lane = tid & 31, w = tid >> 5;
    int mat   = w & 1;            // 0 = self (3-term), 1 = support (2-term)
    int warpN = (w >> 1) & 3;     // 32-col group
    int warpM = (w >> 3) & 1;     // 32-row group

    if (tid < 128) ((float*)(sm + NO_BIAS))[tid] = bias[tid];
    {
        const uint4* whS = (const uint4*)(g_whi + (size_t)(2 * wsel) * 16384);
        const uint4* wlS = (const uint4*)(g_wlo + (size_t)(2 * wsel) * 16384);
        const uint4* whN = (const uint4*)(g_whi + (size_t)(2 * wsel + 1) * 16384);
        for (int idx = tid; idx < 2048; idx += 512) {
            int r = idx >> 4, u = idx & 15;
            uint32_t off = r * (PK128 * 2) + u * 16;
            *(uint4*)(sm + NO_WSHI + off) = whS[idx];
            *(uint4*)(sm + NO_WSLO + off) = wlS[idx];
            *(uint4*)(sm + NO_WNHI + off) = whN[idx];
        }
    }

    uint32_t stg[3] = { sb + NO_A0, sb + NO_A0 + NO_STAGE, sb + NO_A0 + 2 * NO_STAGE };
    const float* sbias = (const float*)(sm + NO_BIAS);

    uint32_t aRow = warpM * 32 + (lane & 15);
    uint32_t aColSel = (lane >> 4) * 8;
    uint32_t aOff0 = (aRow * PK128 + aColSel) * 2;
    uint32_t aOff1 = ((aRow + 16) * PK128 + aColSel) * 2;
    uint32_t bRow = warpN * 32 + (lane & 7);
    uint32_t bColSel = ((lane >> 3) & 1) * 8;
    uint32_t bOffBase = (bRow * PK128 + bColSel) * 2;
    uint32_t bHiBase = (mat ? (sb + NO_WNHI) : (sb + NO_WSHI)) + bOffBase;
    uint32_t bLoBase = (sb + NO_WSLO) + bOffBase;

    int g = gridDim.x;
    int t = blockIdx.x;
    int s = 0;
    issue_node_tile(t * 64, stg[0], stg[0] + NO_ASTG, tid);
    CP_COMMIT();
    issue_node_tile((t + g) * 64, stg[1], stg[1] + NO_ASTG, tid);
    CP_COMMIT();
    __syncthreads();   // weights + bias visible

    while (t < NODE_TILES) {
        CP_WAIT1();
        __syncthreads();

        int s2i = (s >= 1) ? (s - 1) : 2;   // == (s+2)%3
        issue_node_tile((t + 2 * g) * 64, stg[s2i], stg[s2i] + NO_ASTG, tid);
        CP_COMMIT();

        float acc[2][4][4];
#pragma unroll
        for (int mt = 0; mt < 2; mt++)
#pragma unroll
            for (int nt = 0; nt < 4; nt++)
#pragma unroll
                for (int q = 0; q < 4; q++) acc[mt][nt][q] = 0.f;

        uint32_t asH = stg[s], asL = stg[s] + NO_ASTG;
#pragma unroll
        for (int ks = 0; ks < 8; ks++) {
            uint32_t kadd = ks * 32;
            uint32_t aH[2][4], aL[2][4];
            ldsm_x4(aH[0][0], aH[0][1], aH[0][2], aH[0][3], asH + aOff0 + kadd);
            ldsm_x4(aH[1][0], aH[1][1], aH[1][2], aH[1][3], asH + aOff1 + kadd);
            ldsm_x4(aL[0][0], aL[0][1], aL[0][2], aL[0][3], asL + aOff0 + kadd);
            ldsm_x4(aL[1][0], aL[1][1], aL[1][2], aL[1][3], asL + aOff1 + kadd);
#pragma unroll
            for (int nt = 0; nt < 4; nt++) {
                uint32_t bo = nt * 8 * PK128 * 2 + kadd;
                uint32_t bH[2];
                ldsm_x2(bH[0], bH[1], bHiBase + bo);
                mma16816(acc[0][nt], aH[0], bH);
                mma16816(acc[1][nt], aH[1], bH);
                mma16816(acc[0][nt], aL[0], bH);
                mma16816(acc[1][nt], aL[1], bH);
                if (!mat) {
                    uint32_t bL[2];
                    ldsm_x2(bL[0], bL[1], bLoBase + bo);
                    mma16816(acc[0][nt], aH[0], bL);
                    mma16816(acc[1][nt], aH[1], bL);
                }
            }
        }

        int base = t * 64;
        if (!mat) {
#pragma unroll
            for (int mt = 0; mt < 2; mt++) {
                int r0 = base + warpM * 32 + mt * 16 + (lane >> 2);
#pragma unroll
                for (int nt = 0; nt < 4; nt++) {
                    int c = warpN * 32 + nt * 8 + (lane & 3) * 2;
                    if (r0 < NN)
                        *(float2*)(Cself + (size_t)r0 * 128 + c) =
                            make_float2(acc[mt][nt][0] + sbias[c], acc[mt][nt][1] + sbias[c + 1]);
                    if (r0 + 8 < NN)
                        *(float2*)(Cself + (size_t)(r0 + 8) * 128 + c) =
                            make_float2(acc[mt][nt][2] + sbias[c], acc[mt][nt][3] + sbias[c + 1]);
                }
            }
        } else {
#pragma unroll
            for (int mt = 0; mt < 2; mt++) {
                int r0 = base + warpM * 32 + mt * 16 + (lane >> 2);
#pragma unroll
                for (int nt = 0; nt < 4; nt++) {
                    int c = warpN * 32 + nt * 8 + (lane & 3) * 2;
                    if (r0 < NN)
                        *(__half2*)(&g_suph[(size_t)r0 * 128 + c]) =
                            __halves2half2(__float2half_rn(acc[mt][nt][0]),
                                           __float2half_rn(acc[mt][nt][1]));
                    if (r0 + 8 < NN)
                        *(__half2*)(&g_suph[(size_t)(r0 + 8) * 128 + c]) =
                            __halves2half2(__float2half_rn(acc[mt][nt][2]),
                                           __float2half_rn(acc[mt][nt][3]));
                }
            }
        }
        t += g;
        s = (s + 1 == 3) ? 0 : (s + 1);
    }
}

// ---------------- persistent fused decoder: 512 thr, 128-pair tiles, 2-stage ----------------
#define DO_B1   0       // 512
#define DO_W2   512     // 512
#define DO_RED  1024    // 128*16*4 = 8192
#define DO_W1HI 9216
#define DO_W1LO (DO_W1HI + 128 * PK256 * 2)      // +67584
#define DO_A0   (DO_W1LO + 128 * PK256 * 2)      // 144384
#define DO_ASTG (128 * PK128 * 2)                // 34816 (hi only, 128 pairs)
#define DO_A1   (DO_A0 + DO_ASTG)
#define DO_SMEM (DO_A1 + DO_ASTG)                // 214016

#define DEC_TILES ((NP + 127) / 128)             // 3907

__device__ __forceinline__ void issue_dec_stage(int tile, int chunk,
                                                const int* __restrict__ xidx,
                                                const int* __restrict__ yidx,
                                                uint32_t smHi, int tid) {
    int r = tid >> 2;               // 0..127
    int u0 = (tid & 3) * 4;         // units 0..15
    int pp = tile * 128 + r;
    if (pp >= NP) pp = NP - 1;
    const int* idx = chunk ? yidx : xidx;
    int node = idx[pp];
    const char* srcH = (const char*)g_ahi + (size_t)node * 256;
    uint32_t drow = (uint32_t)r * (PK128 * 2);
#pragma unroll
    for (int q = 0; q < 4; q++) {
        uint32_t o = (u0 + q) * 16;
        cp16(smHi + drow + o, srcH + o, 16u);
    }
}

__global__ __launch_bounds__(512, 1) void k_mm_decoder(
    const int* __restrict__ xidx, const int* __restrict__ yidx,
    const float* __restrict__ b1, const float* __restrict__ w2, const float* __restrict__ b2,
    float* __restrict__ p)
{
    extern __shared__ char sm[];
    uint32_t sb = smem_u32(sm);
    int tid = threadIdx.x;
    int lane = tid & 31, w = tid >> 5;
    int warpM = w & 3;        // 32-row group (4 x 32 = 128 pairs)
    int warpN = w >> 2;       // 32-col group (4 x 32 = 128 hid)

    if (tid < 128) {
        ((float*)(sm + DO_B1))[tid] = b1[tid];
        ((float*)(sm + DO_W2))[tid] = w2[tid];
    }
    {
        const uint4* wh = (const uint4*)(g_whi + W_NODE_ELEMS);
        const uint4* wl = (const uint4*)(g_wlo + W_NODE_ELEMS);
        for (int idx = tid; idx < 4096; idx += 512) {
            int r = idx >> 5, u = idx & 31;
            uint32_t off = r * (PK256 * 2) + u * 16;
            *(uint4*)(sm + DO_W1HI + off) = wh[idx];
            *(uint4*)(sm + DO_W1LO + off) = wl[idx];
        }
    }

    uint32_t stg[2] = { sb + DO_A0, sb + DO_A1 };
    const float* sb1 = (const float*)(sm + DO_B1);
    const float* sw2 = (const float*)(sm + DO_W2);
    float* red = (float*)(sm + DO_RED);
    float b2v = __ldg(b2);

    uint32_t aRow = warpM * 32 + (lane & 15);
    uint32_t aColSel = (lane >> 4) * 8;
    uint32_t aOff0 = (aRow * PK128 + aColSel) * 2;
    uint32_t aOff1 = ((aRow + 16) * PK128 + aColSel) * 2;
    uint32_t bRow = warpN * 32 + (lane & 7);
    uint32_t bColSel = ((lane >> 3) & 1) * 8;
    uint32_t bOffBase = (bRow * PK256 + bColSel) * 2;

    float acc[2][4][4];
#pragma unroll
    for (int mt = 0; mt < 2; mt++)
#pragma unroll
        for (int nt = 0; nt < 4; nt++)
#pragma unroll
            for (int q = 0; q < 4; q++) acc[mt][nt][q] = 0.f;

    int g = gridDim.x;
    int t = blockIdx.x;
    int c = 0;
    int buf = 0;
    if (t < DEC_TILES) {
        issue_dec_stage(t, 0, xidx, yidx, stg[0], tid);
        CP_COMMIT();
    }
    __syncthreads();   // W1/b1/w2 visible

    while (t < DEC_TILES) {
        int nt_ = t, nc = c + 1;
        if (nc == 2) { nc = 0; nt_ = t + g; }
        if (nt_ < DEC_TILES) {
            issue_dec_stage(nt_, nc, xidx, yidx, stg[buf ^ 1], tid);
            CP_COMMIT();
            CP_WAIT1();
        } else {
            CP_WAIT0();
        }
        __syncthreads();

        uint32_t asH = stg[buf];
        uint32_t kChunk = c * 256;   // byte offset into W1 K dim
#pragma unroll
        for (int ks = 0; ks < 8; ks++) {
            uint32_t kadd = ks * 32;
            uint32_t aH[2][4];
            ldsm_x4(aH[0][0], aH[0][1], aH[0][2], aH[0][3], asH + aOff0 + kadd);
            ldsm_x4(aH[1][0], aH[1][1], aH[1][2], aH[1][3], asH + aOff1 + kadd);
#pragma unroll
            for (int nt2 = 0; nt2 < 4; nt2++) {
                uint32_t bo = bOffBase + nt2 * 8 * PK256 * 2 + kChunk + kadd;
                uint32_t bH[2], bL[2];
                ldsm_x2(bH[0], bH[1], sb + DO_W1HI + bo);
                ldsm_x2(bL[0], bL[1], sb + DO_W1LO + bo);
                mma16816(acc[0][nt2], aH[0], bH);
                mma16816(acc[1][nt2], aH[1], bH);
                mma16816(acc[0][nt2], aH[0], bL);
                mma16816(acc[1][nt2], aH[1], bL);
            }
        }

        if (c == 1) {
            // epilogue: relu + fc2 partial dot + cross-warp reduction + sigmoid
#pragma unroll
            for (int mt = 0; mt < 2; mt++) {
                int rl = warpM * 32 + mt * 16 + (lane >> 2);
                float p0 = 0.f, p1 = 0.f;
#pragma unroll
                for (int nt2 = 0; nt2 < 4; nt2++) {
                    int cc = warpN * 32 + nt2 * 8 + (lane & 3) * 2;
                    float h00 = fmaxf(acc[mt][nt2][0] + sb1[cc], 0.f);
                    float h01 = fmaxf(acc[mt][nt2][1] + sb1[cc + 1], 0.f);
                    float h10 = fmaxf(acc[mt][nt2][2] + sb1[cc], 0.f);
                    float h11 = fmaxf(acc[mt][nt2][3] + sb1[cc + 1], 0.f);
                    p0 += h00 * sw2[cc] + h01 * sw2[cc + 1];
                    p1 += h10 * sw2[cc] + h11 * sw2[cc + 1];
                }
                red[rl * 16 + warpN * 4 + (lane & 3)] = p0;
                red[(rl + 8) * 16 + warpN * 4 + (lane & 3)] = p1;
            }
            __syncthreads();
            if (tid < 128) {
                float sacc = 0.f;
#pragma unroll
                for (int j = 0; j < 16; j++) sacc += red[tid * 16 + j];
                sacc += b2v;
                float pv = 1.f / (1.f + expf(-sacc));
                int pp = t * 128 + tid;
                if (pp < NP) p[pp] = pv;
            }
#pragma unroll
            for (int mt = 0; mt < 2; mt++)
#pragma unroll
                for (int nt2 = 0; nt2 < 4; nt2++)
#pragma unroll
                    for (int q = 0; q < 4; q++) acc[mt][nt2][q] = 0.f;
        }
        __syncthreads();
        buf ^= 1;
        c = nc;
        t = nt_;
    }
}

// ---------------- launch ----------------
extern "C" void kernel_launch(void* const* d_in, const int* in_sizes, int n_in,
                              void* d_out, int out_size) {
    const float* x     = (const float*)d_in[0];
    const int*   erow  = (const int*)  d_in[1];
    const int*   ecol  = (const int*)  d_in[2];
    const float* ew    = (const float*)d_in[3];
    const int*   xidx  = (const int*)  d_in[4];
    const int*   yidx  = (const int*)  d_in[5];
    const float* ws[3] = { (const float*)d_in[6],  (const float*)d_in[9],  (const float*)d_in[12] };
    const float* wn[3] = { (const float*)d_in[7],  (const float*)d_in[10], (const float*)d_in[13] };
    const float* bb[3] = { (const float*)d_in[8],  (const float*)d_in[11], (const float*)d_in[14] };
    const float* dw1 = (const float*)d_in[15];
    const float* db1 = (const float*)d_in[16];
    const float* dw2 = (const float*)d_in[17];
    const float* db2 = (const float*)d_in[18];

    float* out = (float*)d_out;
    float* p_out = out;            // [NP]
    float* z_out = out + NP;       // [NN*128]

    void* ptr;
    cudaGetSymbolAddress(&ptr, g_selfb);   float* selfb_buf = (float*)ptr;

    int nsm = 148;
    cudaDeviceGetAttribute(&nsm, cudaDevAttrMultiProcessorCount, 0);

    cudaFuncSetAttribute(k_mm_node, cudaFuncAttributeMaxDynamicSharedMemorySize, NO_SMEM);
    cudaFuncSetAttribute(k_mm_decoder, cudaFuncAttributeMaxDynamicSharedMemorySize, DO_SMEM);

    // side stream for the CSR build (independent of converts + layer-1 GEMM)
    cudaStream_t s2;
    cudaStreamCreateWithFlags(&s2, cudaStreamNonBlocking);
    cudaEvent_t eFork, eJoin;
    cudaEventCreateWithFlags(&eFork, cudaEventDisableTiming);
    cudaEventCreateWithFlags(&eJoin, cudaEventDisableTiming);

    cudaEventRecord(eFork, 0);
    cudaStreamWaitEvent(s2, eFork, 0);

    const int aggGrid = (NN + 3) / 4;   // warp-per-node

    // main stream: converts + layer-1 GEMM (launch #4 overall = mm_node, for ncu)
    k_convert_x<<<(NN * 32 + 255) / 256, 256>>>(x);                                         // 1
    k_convert_weights<<<(W_TOTAL + 255) / 256, 256>>>(ws[0], wn[0], ws[1], wn[1], ws[2], wn[2], dw1); // 2
    k_zero_deg<<<(NN + 255) / 256, 256, 0, s2>>>();                                         // 3 (s2)
    k_mm_node<<<nsm, 512, NO_SMEM>>>(0, bb[0], selfb_buf);                                  // 4 <- profiled
    // CSR chain on s2
    k_count_deg<<<(NE + 255) / 256, 256, 0, s2>>>(erow);                                    // 5
    k_scan_part<<<NBLK, SCAN_B, 0, s2>>>();                                                 // 6
    k_scan_mid<<<1, 128, 0, s2>>>();                                                        // 7
    k_scan_final<<<NBLK, SCAN_B, 0, s2>>>();                                                // 8
    k_scatter_edges<<<(NE + 255) / 256, 256, 0, s2>>>(erow, ecol, ew);                      // 9
    cudaEventRecord(eJoin, s2);
    cudaStreamWaitEvent(0, eJoin, 0);

    k_aggregate<<<aggGrid, 128>>>(nullptr, 1, 0);                                           // 10
    k_mm_node<<<nsm, 512, NO_SMEM>>>(1, bb[1], selfb_buf);                                  // 11
    k_aggregate<<<aggGrid, 128>>>(nullptr, 1, 0);                                           // 12
    k_mm_node<<<nsm, 512, NO_SMEM>>>(2, bb[2], selfb_buf);                                  // 13
    k_aggregate<<<aggGrid, 128>>>(z_out, 0, 1);                                             // 14
    k_mm_decoder<<<nsm, 512, DO_SMEM>>>(xidx, yidx, db1, dw2, db2, p_out);                  // 15
}

// round 12
// speedup vs baseline: 3.4761x; 1.1610x over previous
#include <cuda_runtime.h>
#include <cuda_fp16.h>
#include <math.h>
#include <stdint.h>

#define NN 100000
#define NE 1600000
#define NP 500000
#define SCAN_B 1024
#define NBLK ((NN + SCAN_B - 1) / SCAN_B)   // 98

// ---------------- static device scratch ----------------
__device__ float  g_selfb[(size_t)NN * 128];  // selfb; reused as U after layer 3
__device__ float  g_v[(size_t)NN * 128];      // V = Z @ W1_bot
__device__ __half g_suph[(size_t)NN * 128];   // h @ Wn in fp16 (gathered operand)
__device__ __half g_ahi[(size_t)NN * 128];    // activation hi
__device__ __half g_alo[(size_t)NN * 128];    // activation lo
__device__ int   g_rowptr[NN + 1];
__device__ int   g_cursor[NN];
__device__ int   g_partial[NBLK];
__device__ int   g_blockoff[NBLK];
__device__ int   g_pcol[NE];
__device__ float g_pw[NE];
// converted weights (all [n][k128] node layout): mats 0..5 = layer ws/wn pairs,
// mats 6,7 = W1_top / W1_bot
#define W_TOTAL (8 * 16384)
__device__ __half g_whi[W_TOTAL];
__device__ __half g_wlo[W_TOTAL];

#define PK128 136

// ---------------- helpers ----------------
__device__ __forceinline__ uint32_t smem_u32(const void* p) {
    uint32_t a;
    asm("{ .reg .u64 t; cvta.to.shared.u64 t, %1; cvt.u32.u64 %0, t; }" : "=r"(a) : "l"(p));
    return a;
}
__device__ __forceinline__ void ldsm_x4(uint32_t& r0, uint32_t& r1, uint32_t& r2, uint32_t& r3,
                                        uint32_t addr) {
    asm volatile("ldmatrix.sync.aligned.m8n8.x4.shared.b16 {%0,%1,%2,%3}, [%4];"
                 : "=r"(r0), "=r"(r1), "=r"(r2), "=r"(r3) : "r"(addr));
}
__device__ __forceinline__ void ldsm_x2(uint32_t& r0, uint32_t& r1, uint32_t addr) {
    asm volatile("ldmatrix.sync.aligned.m8n8.x2.shared.b16 {%0,%1}, [%2];"
                 : "=r"(r0), "=r"(r1) : "r"(addr));
}
__device__ __forceinline__ void mma16816(float* c, const uint32_t* a, const uint32_t* b) {
    asm volatile("mma.sync.aligned.m16n8k16.row.col.f32.f16.f16.f32 "
                 "{%0,%1,%2,%3}, {%4,%5,%6,%7}, {%8,%9}, {%0,%1,%2,%3};"
                 : "+f"(c[0]), "+f"(c[1]), "+f"(c[2]), "+f"(c[3])
                 : "r"(a[0]), "r"(a[1]), "r"(a[2]), "r"(a[3]), "r"(b[0]), "r"(b[1]));
}
__device__ __forceinline__ void cp16(uint32_t dst, const void* src, unsigned sz) {
    asm volatile("cp.async.cg.shared.global [%0], [%1], 16, %2;"
                 :: "r"(dst), "l"(src), "r"(sz) : "memory");
}
#define CP_COMMIT() asm volatile("cp.async.commit_group;" ::: "memory")
#define CP_WAIT1()  asm volatile("cp.async.wait_group 1;" ::: "memory")

__device__ __forceinline__ void split1(float v, __half& h, __half& l) {
    h = __float2half_rn(v);
    l = __float2half_rn(v - __half2float(h));
}

// ---------------- CSR build ----------------
__global__ void k_zero_deg() {
    int i = blockIdx.x * blockDim.x + threadIdx.x;
    if (i < NN) g_cursor[i] = 0;
}
__global__ void k_count_deg(const int* __restrict__ row) {
    int e = blockIdx.x * blockDim.x + threadIdx.x;
    if (e < NE) atomicAdd(&g_cursor[row[e]], 1);
}
__global__ __launch_bounds__(SCAN_B) void k_scan_part() {
    __shared__ int sh[SCAN_B / 32];
    int t = threadIdx.x;
    int idx = blockIdx.x * SCAN_B + t;
    int v = (idx < NN) ? g_cursor[idx] : 0;
#pragma unroll
    for (int off = 16; off > 0; off >>= 1) v += __shfl_down_sync(0xffffffffu, v, off);
    if ((t & 31) == 0) sh[t >> 5] = v;
    __syncthreads();
    if (t < 32) {
        int s = (t < SCAN_B / 32) ? sh[t] : 0;
#pragma unroll
        for (int off = 16; off > 0; off >>= 1) s += __shfl_down_sync(0xffffffffu, s, off);
        if (t == 0) g_partial[blockIdx.x] = s;
    }
}
__global__ __launch_bounds__(128) void k_scan_mid() {
    __shared__ int sh[128];
    int t = threadIdx.x;
    int v = (t < NBLK) ? g_partial[t] : 0;
    sh[t] = v;
    __syncthreads();
#pragma unroll
    for (int off = 1; off < 128; off <<= 1) {
        int y = (t >= off) ? sh[t - off] : 0;
        __syncthreads();
        sh[t] += y;
        __syncthreads();
    }
    if (t < NBLK) g_blockoff[t] = sh[t] - v;
}
__global__ __launch_bounds__(SCAN_B) void k_scan_final() {
    __shared__ int sh[SCAN_B];
    int t = threadIdx.x;
    int idx = blockIdx.x * SCAN_B + t;
    int v = (idx < NN) ? g_cursor[idx] : 0;
    sh[t] = v;
    __syncthreads();
#pragma unroll
    for (int off = 1; off < SCAN_B; off <<= 1) {
        int y = (t >= off) ? sh[t - off] : 0;
        __syncthreads();
        sh[t] += y;
        __syncthreads();
    }
    if (idx < NN) {
        int incl = sh[t] + g_blockoff[blockIdx.x];
        g_rowptr[idx + 1] = incl;
        g_cursor[idx] = incl - v;
    }
    if (idx == 0) g_rowptr[0] = 0;
}
__global__ void k_scatter_edges(const int* __restrict__ row, const int* __restrict__ col,
                                const float* __restrict__ w) {
    int e = blockIdx.x * blockDim.x + threadIdx.x;
    if (e < NE) {
        int pos = atomicAdd(&g_cursor[row[e]], 1);
        g_pcol[pos] = col[e];
        g_pw[pos]   = w[e];
    }
}

// ---------------- converters ----------------
__global__ void k_convert_x(const float* __restrict__ x) {
    int i = blockIdx.x * blockDim.x + threadIdx.x;   // handles 4 floats
    if (i < NN * 32) {
        float4 v = *(const float4*)(x + (size_t)i * 4);
        __half h0, h1, h2, h3, l0, l1, l2, l3;
        split1(v.x, h0, l0); split1(v.y, h1, l1);
        split1(v.z, h2, l2); split1(v.w, h3, l3);
        __half2 H01 = __halves2half2(h0, h1), H23 = __halves2half2(h2, h3);
        __half2 L01 = __halves2half2(l0, l1), L23 = __halves2half2(l2, l3);
        uint2 uh, ul;
        uh.x = *reinterpret_cast<unsigned*>(&H01); uh.y = *reinterpret_cast<unsigned*>(&H23);
        ul.x = *reinterpret_cast<unsigned*>(&L01); ul.y = *reinterpret_cast<unsigned*>(&L23);
        *(uint2*)(g_ahi + (size_t)i * 4) = uh;
        *(uint2*)(g_alo + (size_t)i * 4) = ul;
    }
}
// all mats in [n][k128] layout. mats 0..5: node weights (W[k*128+n]).
// mats 6,7: W1_top/bot: v = wdec[(m6*128 + k)*128 + n]
__global__ void k_convert_weights(const float* w0, const float* w1_, const float* w2_,
                                  const float* w3, const float* w4, const float* w5,
                                  const float* wdec) {
    int idx = blockIdx.x * blockDim.x + threadIdx.x;
    if (idx >= W_TOTAL) return;
    int m = idx >> 14;
    int e = idx & 16383;
    int n = e >> 7, k = e & 127;
    float v;
    if (m < 6) {
        const float* W = (m == 0) ? w0 : (m == 1) ? w1_ : (m == 2) ? w2_
                       : (m == 3) ? w3 : (m == 4) ? w4 : w5;
        v = W[k * 128 + n];
    } else {
        v = wdec[((m - 6) * 128 + k) * 128 + n];
    }
    __half h, l;
    split1(v, h, l);
    g_whi[idx] = h;
    g_wlo[idx] = l;
}

// ---------------- neighbor aggregation: warp-per-node, 8B vector gathers ----------------
__global__ __launch_bounds__(128) void k_aggregate(float* __restrict__ outf, int relu, int writef) {
    int warp = threadIdx.x >> 5;
    int lane = threadIdx.x & 31;
    int node = blockIdx.x * 4 + warp;
    if (node >= NN) return;
    size_t base = (size_t)node * 128 + lane * 4;

    float4 sv = *(const float4*)(g_selfb + base);
    float a0 = sv.x, a1 = sv.y, a2 = sv.z, a3 = sv.w;

    int s = g_rowptr[node];
    int e = g_rowptr[node + 1];
    for (int i0 = s; i0 < e; i0 += 32) {
        int n = e - i0;
        if (n > 32) n = 32;
        int   c  = 0;
        float wv = 0.f;
        if (lane < n) { c = g_pcol[i0 + lane]; wv = g_pw[i0 + lane]; }
        for (int j = 0; j < n; j++) {
            int   cj = __shfl_sync(0xffffffffu, c, j);
            float wj = __shfl_sync(0xffffffffu, wv, j);
            uint2 hv = *(const uint2*)(g_suph + (size_t)cj * 128 + lane * 4);
            __half2 h01 = *reinterpret_cast<__half2*>(&hv.x);
            __half2 h23 = *reinterpret_cast<__half2*>(&hv.y);
            float2 f01 = __half22float2(h01);
            float2 f23 = __half22float2(h23);
            a0 += wj * f01.x; a1 += wj * f01.y;
            a2 += wj * f23.x; a3 += wj * f23.y;
        }
    }
    if (relu) {
        a0 = fmaxf(a0, 0.f); a1 = fmaxf(a1, 0.f);
        a2 = fmaxf(a2, 0.f); a3 = fmaxf(a3, 0.f);
    }
    if (writef) *(float4*)(outf + base) = make_float4(a0, a1, a2, a3);
    __half h0, h1, h2, h3, l0, l1, l2, l3;
    split1(a0, h0, l0); split1(a1, h1, l1);
    split1(a2, h2, l2); split1(a3, h3, l3);
    __half2 H01 = __halves2half2(h0, h1), H23 = __halves2half2(h2, h3);
    __half2 L01 = __halves2half2(l0, l1), L23 = __halves2half2(l2, l3);
    uint2 uh, ul;
    uh.x = *reinterpret_cast<unsigned*>(&H01); uh.y = *reinterpret_cast<unsigned*>(&H23);
    ul.x = *reinterpret_cast<unsigned*>(&L01); ul.y = *reinterpret_cast<unsigned*>(&L23);
    *(uint2*)(g_ahi + base) = uh;
    *(uint2*)(g_alo + base) = ul;
}

// ---------------- shared GEMM plumbing ----------------
#define NODE_TILES ((NN + 63) / 64)              // 1563
#define NO_ASTG  (64 * PK128 * 2)                // 17408
#define NO_STAGE (2 * NO_ASTG)                   // 34816 per stage (hi+lo)

__device__ __forceinline__ void issue_node_tile(int rowBase, uint32_t smHi, uint32_t smLo, int tid) {
    int r = tid >> 3;               // 0..63
    int u0 = (tid & 7) * 2;         // units 0..15
    long long gr = (long long)rowBase + r;
    unsigned sz = (gr < NN) ? 16u : 0u;
    long long grc = gr < NN ? gr : (NN - 1);
    const char* srcH = (const char*)g_ahi + grc * 256;
    const char* srcL = (const char*)g_alo + grc * 256;
    uint32_t drow = (uint32_t)r * (PK128 * 2);
#pragma unroll
    for (int q = 0; q < 2; q++) {
        uint32_t o = (u0 + q) * 16;
        cp16(smHi + drow + o, srcH + o, sz);
        cp16(smLo + drow + o, srcL + o, sz);
    }
}

// ---------------- persistent node GEMM: 512 thr, mat-split warps, 3-stage ----------------
#define NO_BIAS  0                               // 512
#define NO_WSHI  1024
#define NO_WSLO  (NO_WSHI + 128 * PK128 * 2)     // +34816
#define NO_WNHI  (NO_WSLO + 128 * PK128 * 2)
#define NO_A0    (NO_WNHI + 128 * PK128 * 2)
#define NO_SMEM  (NO_A0 + 3 * NO_STAGE)          // 209920

__global__ __launch_bounds__(512, 1) void k_mm_node(
    int wsel, const float* __restrict__ bias, float* __restrict__ Cself)
{
    extern __shared__ char sm[];
    uint32_t sb = smem_u32(sm);
    int tid = threadIdx.x;
    int lane = tid & 31, w = tid >> 5;
    int mat   = w & 1;            // 0 = self (3-term), 1 = support (2-term)
    int warpN = (w >> 1) & 3;
    int warpM = (w >> 3) & 1;

    if (tid < 128) ((float*)(sm + NO_BIAS))[tid] = bias[tid];
    {
        const uint4* whS = (const uint4*)(g_whi + (size_t)(2 * wsel) * 16384);
        const uint4* wlS = (const uint4*)(g_wlo + (size_t)(2 * wsel) * 16384);
        const uint4* whN = (const uint4*)(g_whi + (size_t)(2 * wsel + 1) * 16384);
        for (int idx = tid; idx < 2048; idx += 512) {
            int r = idx >> 4, u = idx & 15;
            uint32_t off = r * (PK128 * 2) + u * 16;
            *(uint4*)(sm + NO_WSHI + off) = whS[idx];
            *(uint4*)(sm + NO_WSLO + off) = wlS[idx];
            *(uint4*)(sm + NO_WNHI + off) = whN[idx];
        }
    }

    uint32_t stg[3] = { sb + NO_A0, sb + NO_A0 + NO_STAGE, sb + NO_A0 + 2 * NO_STAGE };
    const float* sbias = (const float*)(sm + NO_BIAS);

    uint32_t aRow = warpM * 32 + (lane & 15);
    uint32_t aColSel = (lane >> 4) * 8;
    uint32_t aOff0 = (aRow * PK128 + aColSel) * 2;
    uint32_t aOff1 = ((aRow + 16) * PK128 + aColSel) * 2;
    uint32_t bRow = warpN * 32 + (lane & 7);
    uint32_t bColSel = ((lane >> 3) & 1) * 8;
    uint32_t bOffBase = (bRow * PK128 + bColSel) * 2;
    uint32_t bHiBase = (mat ? (sb + NO_WNHI) : (sb + NO_WSHI)) + bOffBase;
    uint32_t bLoBase = (sb + NO_WSLO) + bOffBase;

    int g = gridDim.x;
    int t = blockIdx.x;
    int s = 0;
    issue_node_tile(t * 64, stg[0], stg[0] + NO_ASTG, tid);
    CP_COMMIT();
    issue_node_tile((t + g) * 64, stg[1], stg[1] + NO_ASTG, tid);
    CP_COMMIT();
    __syncthreads();

    while (t < NODE_TILES) {
        CP_WAIT1();
        __syncthreads();

        int s2i = (s >= 1) ? (s - 1) : 2;   // == (s+2)%3
        issue_node_tile((t + 2 * g) * 64, stg[s2i], stg[s2i] + NO_ASTG, tid);
        CP_COMMIT();

        float acc[2][4][4];
#pragma unroll
        for (int mt = 0; mt < 2; mt++)
#pragma unroll
            for (int nt = 0; nt < 4; nt++)
#pragma unroll
                for (int q = 0; q < 4; q++) acc[mt][nt][q] = 0.f;

        uint32_t asH = stg[s], asL = stg[s] + NO_ASTG;
#pragma unroll
        for (int ks = 0; ks < 8; ks++) {
            uint32_t kadd = ks * 32;
            uint32_t aH[2][4], aL[2][4];
            ldsm_x4(aH[0][0], aH[0][1], aH[0][2], aH[0][3], asH + aOff0 + kadd);
            ldsm_x4(aH[1][0], aH[1][1], aH[1][2], aH[1][3], asH + aOff1 + kadd);
            ldsm_x4(aL[0][0], aL[0][1], aL[0][2], aL[0][3], asL + aOff0 + kadd);
            ldsm_x4(aL[1][0], aL[1][1], aL[1][2], aL[1][3], asL + aOff1 + kadd);
#pragma unroll
            for (int nt = 0; nt < 4; nt++) {
                uint32_t bo = nt * 8 * PK128 * 2 + kadd;
                uint32_t bH[2];
                ldsm_x2(bH[0], bH[1], bHiBase + bo);
                mma16816(acc[0][nt], aH[0], bH);
                mma16816(acc[1][nt], aH[1], bH);
                mma16816(acc[0][nt], aL[0], bH);
                mma16816(acc[1][nt], aL[1], bH);
                if (!mat) {
                    uint32_t bL[2];
                    ldsm_x2(bL[0], bL[1], bLoBase + bo);
                    mma16816(acc[0][nt], aH[0], bL);
                    mma16816(acc[1][nt], aH[1], bL);
                }
            }
        }

        int base = t * 64;
        if (!mat) {
#pragma unroll
            for (int mt = 0; mt < 2; mt++) {
                int r0 = base + warpM * 32 + mt * 16 + (lane >> 2);
#pragma unroll
                for (int nt = 0; nt < 4; nt++) {
                    int c = warpN * 32 + nt * 8 + (lane & 3) * 2;
                    if (r0 < NN)
                        *(float2*)(Cself + (size_t)r0 * 128 + c) =
                            make_float2(acc[mt][nt][0] + sbias[c], acc[mt][nt][1] + sbias[c + 1]);
                    if (r0 + 8 < NN)
                        *(float2*)(Cself + (size_t)(r0 + 8) * 128 + c) =
                            make_float2(acc[mt][nt][2] + sbias[c], acc[mt][nt][3] + sbias[c + 1]);
                }
            }
        } else {
#pragma unroll
            for (int mt = 0; mt < 2; mt++) {
                int r0 = base + warpM * 32 + mt * 16 + (lane >> 2);
#pragma unroll
                for (int nt = 0; nt < 4; nt++) {
                    int c = warpN * 32 + nt * 8 + (lane & 3) * 2;
                    if (r0 < NN)
                        *(__half2*)(&g_suph[(size_t)r0 * 128 + c]) =
                            __halves2half2(__float2half_rn(acc[mt][nt][0]),
                                           __float2half_rn(acc[mt][nt][1]));
                    if (r0 + 8 < NN)
                        *(__half2*)(&g_suph[(size_t)(r0 + 8) * 128 + c]) =
                            __halves2half2(__float2half_rn(acc[mt][nt][2]),
                                           __float2half_rn(acc[mt][nt][3]));
                }
            }
        }
        t += g;
        s = (s + 1 == 3) ? 0 : (s + 1);
    }
}

// ---------------- persistent UV GEMM: U = Z@W1_top, V = Z@W1_bot (2-term, fp32 out) ----------------
#define NU_WTHI  0
#define NU_WBHI  (NU_WTHI + 128 * PK128 * 2)     // +34816
#define NU_A0    (NU_WBHI + 128 * PK128 * 2)
#define NU_SMEM  (NU_A0 + 3 * NO_STAGE)          // 174080

__global__ __launch_bounds__(512, 1) void k_mm_uv(float* __restrict__ U, float* __restrict__ V)
{
    extern __shared__ char sm[];
    uint32_t sb = smem_u32(sm);
    int tid = threadIdx.x;
    int lane = tid & 31, w = tid >> 5;
    int mat   = w & 1;            // 0 = U, 1 = V
    int warpN = (w >> 1) & 3;
    int warpM = (w >> 3) & 1;

    {
        const uint4* whT = (const uint4*)(g_whi + (size_t)6 * 16384);
        const uint4* whB = (const uint4*)(g_whi + (size_t)7 * 16384);
        for (int idx = tid; idx < 1024; idx += 512) {
            int r = idx >> 3, u = idx & 7;       // wait: 1024 uint4 = 16KB... need 2048
            (void)r; (void)u;
        }
        for (int idx = tid; idx < 2048; idx += 512) {
            int r = idx >> 4, u = idx & 15;
            uint32_t off = r * (PK128 * 2) + u * 16;
            *(uint4*)(sm + NU_WTHI + off) = whT[idx];
            *(uint4*)(sm + NU_WBHI + off) = whB[idx];
        }
    }

    uint32_t stg[3] = { sb + NU_A0, sb + NU_A0 + NO_STAGE, sb + NU_A0 + 2 * NO_STAGE };

    uint32_t aRow = warpM * 32 + (lane & 15);
    uint32_t aColSel = (lane >> 4) * 8;
    uint32_t aOff0 = (aRow * PK128 + aColSel) * 2;
    uint32_t aOff1 = ((aRow + 16) * PK128 + aColSel) * 2;
    uint32_t bRow = warpN * 32 + (lane & 7);
    uint32_t bColSel = ((lane >> 3) & 1) * 8;
    uint32_t bOffBase = (bRow * PK128 + bColSel) * 2;
    uint32_t bHiBase = (mat ? (sb + NU_WBHI) : (sb + NU_WTHI)) + bOffBase;
    float* Cout = mat ? V : U;

    int g = gridDim.x;
    int t = blockIdx.x;
    int s = 0;
    issue_node_tile(t * 64, stg[0], stg[0] + NO_ASTG, tid);
    CP_COMMIT();
    issue_node_tile((t + g) * 64, stg[1], stg[1] + NO_ASTG, tid);
    CP_COMMIT();
    __syncthreads();

    while (t < NODE_TILES) {
        CP_WAIT1();
        __syncthreads();

        int s2i = (s >= 1) ? (s - 1) : 2;
        issue_node_tile((t + 2 * g) * 64, stg[s2i], stg[s2i] + NO_ASTG, tid);
        CP_COMMIT();

        float acc[2][4][4];
#pragma unroll
        for (int mt = 0; mt < 2; mt++)
#pragma unroll
            for (int nt = 0; nt < 4; nt++)
#pragma unroll
                for (int q = 0; q < 4; q++) acc[mt][nt][q] = 0.f;

        uint32_t asH = stg[s], asL = stg[s] + NO_ASTG;
#pragma unroll
        for (int ks = 0; ks < 8; ks++) {
            uint32_t kadd = ks * 32;
            uint32_t aH[2][4], aL[2][4];
            ldsm_x4(aH[0][0], aH[0][1], aH[0][2], aH[0][3], asH + aOff0 + kadd);
            ldsm_x4(aH[1][0], aH[1][1], aH[1][2], aH[1][3], asH + aOff1 + kadd);
            ldsm_x4(aL[0][0], aL[0][1], aL[0][2], aL[0][3], asL + aOff0 + kadd);
            ldsm_x4(aL[1][0], aL[1][1], aL[1][2], aL[1][3], asL + aOff1 + kadd);
#pragma unroll
            for (int nt = 0; nt < 4; nt++) {
                uint32_t bo = nt * 8 * PK128 * 2 + kadd;
                uint32_t bH[2];
                ldsm_x2(bH[0], bH[1], bHiBase + bo);
                mma16816(acc[0][nt], aH[0], bH);
                mma16816(acc[1][nt], aH[1], bH);
                mma16816(acc[0][nt], aL[0], bH);
                mma16816(acc[1][nt], aL[1], bH);
            }
        }

        int base = t * 64;
#pragma unroll
        for (int mt = 0; mt < 2; mt++) {
            int r0 = base + warpM * 32 + mt * 16 + (lane >> 2);
#pragma unroll
            for (int nt = 0; nt < 4; nt++) {
                int c = warpN * 32 + nt * 8 + (lane & 3) * 2;
                if (r0 < NN)
                    *(float2*)(Cout + (size_t)r0 * 128 + c) =
                        make_float2(acc[mt][nt][0], acc[mt][nt][1]);
                if (r0 + 8 < NN)
                    *(float2*)(Cout + (size_t)(r0 + 8) * 128 + c) =
                        make_float2(acc[mt][nt][2], acc[mt][nt][3]);
            }
        }
        t += g;
        s = (s + 1 == 3) ? 0 : (s + 1);
    }
}

// ---------------- decoder gather: p = sigmoid(relu(U[x]+V[y]+b1) . w2 + b2) ----------------
__global__ __launch_bounds__(128) void k_dec_gather(
    const float* __restrict__ U, const float* __restrict__ V,
    const int* __restrict__ xidx, const int* __restrict__ yidx,
    const float* __restrict__ b1, const float* __restrict__ w2, const float* __restrict__ b2,
    float* __restrict__ p)
{
    int warp = threadIdx.x >> 5;
    int lane = threadIdx.x & 31;
    int pp = blockIdx.x * 4 + warp;
    if (pp >= NP) return;
    int xn = xidx[pp], yn = yidx[pp];
    float4 u4 = *(const float4*)(U + (size_t)xn * 128 + lane * 4);
    float4 v4 = *(const float4*)(V + (size_t)yn * 128 + lane * 4);
    float4 b4 = *(const float4*)(b1 + lane * 4);
    float4 w4 = *(const float4*)(w2 + lane * 4);
    float s = fmaxf(u4.x + v4.x + b4.x, 0.f) * w4.x
            + fmaxf(u4.y + v4.y + b4.y, 0.f) * w4.y
            + fmaxf(u4.z + v4.z + b4.z, 0.f) * w4.z
            + fmaxf(u4.w + v4.w + b4.w, 0.f) * w4.w;
#pragma unroll
    for (int off = 16; off > 0; off >>= 1) s += __shfl_down_sync(0xffffffffu, s, off);
    if (lane == 0) {
        s += b2[0];
        p[pp] = 1.f / (1.f + expf(-s));
    }
}

// ---------------- launch ----------------
extern "C" void kernel_launch(void* const* d_in, const int* in_sizes, int n_in,
                              void* d_out, int out_size) {
    const float* x     = (const float*)d_in[0];
    const int*   erow  = (const int*)  d_in[1];
    const int*   ecol  = (const int*)  d_in[2];
    const float* ew    = (const float*)d_in[3];
    const int*   xidx  = (const int*)  d_in[4];
    const int*   yidx  = (const int*)  d_in[5];
    const float* ws[3] = { (const float*)d_in[6],  (const float*)d_in[9],  (const float*)d_in[12] };
    const float* wn[3] = { (const float*)d_in[7],  (const float*)d_in[10], (const float*)d_in[13] };
    const float* bb[3] = { (const float*)d_in[8],  (const float*)d_in[11], (const float*)d_in[14] };
    const float* dw1 = (const float*)d_in[15];
    const float* db1 = (const float*)d_in[16];
    const float* dw2 = (const float*)d_in[17];
    const float* db2 = (const float*)d_in[18];

    float* out = (float*)d_out;
    float* p_out = out;            // [NP]
    float* z_out = out + NP;       // [NN*128]

    void* ptr;
    cudaGetSymbolAddress(&ptr, g_selfb);   float* selfb_buf = (float*)ptr;  // doubles as U
    cudaGetSymbolAddress(&ptr, g_v);       float* v_buf     = (float*)ptr;

    int nsm = 148;
    cudaDeviceGetAttribute(&nsm, cudaDevAttrMultiProcessorCount, 0);

    cudaFuncSetAttribute(k_mm_node, cudaFuncAttributeMaxDynamicSharedMemorySize, NO_SMEM);
    cudaFuncSetAttribute(k_mm_uv,   cudaFuncAttributeMaxDynamicSharedMemorySize, NU_SMEM);

    // side stream for the CSR build (independent of converts + layer-1 GEMM)
    cudaStream_t s2;
    cudaStreamCreateWithFlags(&s2, cudaStreamNonBlocking);
    cudaEvent_t eFork, eJoin;
    cudaEventCreateWithFlags(&eFork, cudaEventDisableTiming);
    cudaEventCreateWithFlags(&eJoin, cudaEventDisableTiming);

    cudaEventRecord(eFork, 0);
    cudaStreamWaitEvent(s2, eFork, 0);

    const int aggGrid = (NN + 3) / 4;   // warp-per-node

    // main stream: converts + layer-1 GEMM (launch #4 overall = mm_node, for ncu)
    k_convert_x<<<(NN * 32 + 255) / 256, 256>>>(x);                                         // 1
    k_convert_weights<<<(W_TOTAL + 255) / 256, 256>>>(ws[0], wn[0], ws[1], wn[1], ws[2], wn[2], dw1); // 2
    k_zero_deg<<<(NN + 255) / 256, 256, 0, s2>>>();                                         // 3 (s2)
    k_mm_node<<<nsm, 512, NO_SMEM>>>(0, bb[0], selfb_buf);                                  // 4 <- profiled
    // CSR chain on s2
    k_count_deg<<<(NE + 255) / 256, 256, 0, s2>>>(erow);                                    // 5
    k_scan_part<<<NBLK, SCAN_B, 0, s2>>>();                                                 // 6
    k_scan_mid<<<1, 128, 0, s2>>>();                                                        // 7
    k_scan_final<<<NBLK, SCAN_B, 0, s2>>>();                                                // 8
    k_scatter_edges<<<(NE + 255) / 256, 256, 0, s2>>>(erow, ecol, ew);                      // 9
    cudaEventRecord(eJoin, s2);
    cudaStreamWaitEvent(0, eJoin, 0);

    k_aggregate<<<aggGrid, 128>>>(nullptr, 1, 0);                                           // 10
    k_mm_node<<<nsm, 512, NO_SMEM>>>(1, bb[1], selfb_buf);                                  // 11
    k_aggregate<<<aggGrid, 128>>>(nullptr, 1, 0);                                           // 12
    k_mm_node<<<nsm, 512, NO_SMEM>>>(2, bb[2], selfb_buf);                                  // 13
    k_aggregate<<<aggGrid, 128>>>(z_out, 0, 1);                                             // 14 (z + ahi/alo)
    // decoder: factored through W1
    k_mm_uv<<<nsm, 512, NU_SMEM>>>(selfb_buf, v_buf);                                       // 15 (U reuses selfb)
    k_dec_gather<<<(NP + 3) / 4, 128>>>(selfb_buf, v_buf, xidx, yidx, db1, dw2, db2, p_out);// 16
}